// round 1
// baseline (speedup 1.0000x reference)
#include <cuda_runtime.h>
#include <cuda_bf16.h>
#include <math.h>

// ---------------------------------------------------------------------------
// Problem constants
//   B=4, S=SM=1024, D=1024, H=16, HD=64, DFF=4096
//   Outputs concatenated in d_out: x[B,S,D], sa_k[B,H,S,HD], sa_v[B,H,S,HD]
// ---------------------------------------------------------------------------

#define TOK  4096          // B*S = B*SM
#define DMODEL 1024
#define DFF_  4096
#define NELEM 4194304      // TOK * DMODEL

// Scratch (static device globals - allowed; no runtime allocation)
__device__ float g_ln[NELEM];
__device__ float g_q [NELEM];
__device__ float g_k2[NELEM];
__device__ float g_v2[NELEM];
__device__ float g_o [NELEM];
__device__ float g_ob[NELEM];
__device__ float g_x1[NELEM];
__device__ float g_x2[NELEM];
__device__ float g_h1[16777216];   // 4096 x 4096

// ---------------------------------------------------------------------------
// LayerNorm: one block per row, D=1024, 256 threads x float4
// ---------------------------------------------------------------------------
__global__ __launch_bounds__(256) void ln_kernel(
    const float* __restrict__ x, const float* __restrict__ g,
    const float* __restrict__ be, float* __restrict__ y)
{
    int row = blockIdx.x;
    const float* xr = x + (size_t)row * DMODEL;
    int c = threadIdx.x * 4;
    float4 v = *(const float4*)(xr + c);
    float s  = v.x + v.y + v.z + v.w;
    float ss = v.x*v.x + v.y*v.y + v.z*v.z + v.w*v.w;
    #pragma unroll
    for (int o = 16; o > 0; o >>= 1) {
        s  += __shfl_xor_sync(0xffffffffu, s,  o);
        ss += __shfl_xor_sync(0xffffffffu, ss, o);
    }
    __shared__ float sm[8], sm2[8];
    int w = threadIdx.x >> 5, lane = threadIdx.x & 31;
    if (lane == 0) { sm[w] = s; sm2[w] = ss; }
    __syncthreads();
    s = 0.f; ss = 0.f;
    #pragma unroll
    for (int i = 0; i < 8; i++) { s += sm[i]; ss += sm2[i]; }
    float mu   = s  * (1.0f / DMODEL);
    float var  = ss * (1.0f / DMODEL) - mu * mu;
    float rstd = rsqrtf(var + 1e-5f);
    float4 gv = *(const float4*)(g + c);
    float4 bv = *(const float4*)(be + c);
    float4 o;
    o.x = (v.x - mu) * rstd * gv.x + bv.x;
    o.y = (v.y - mu) * rstd * gv.y + bv.y;
    o.z = (v.z - mu) * rstd * gv.z + bv.z;
    o.w = (v.w - mu) * rstd * gv.w + bv.w;
    *(float4*)(y + (size_t)row * DMODEL + c) = o;
}

// ---------------------------------------------------------------------------
// GEMM (NT): C[M,N] = A[M,K] @ B[N,K]^T  (+bias) (+relu) (+residual)
// Optional scatter: row m = b*1024+s, col n = h*64+hd ->
//                   out[((b*16+h)*1024+s)*64+hd]  ([B,H,S,HD] layout)
// 128x128 block tile, BK=8, 256 threads, 8x8 per thread.
// All M,N,K here are multiples of 128/128/8 -> no bounds checks.
// ---------------------------------------------------------------------------
#define BKG 8
__global__ __launch_bounds__(256) void gemm_nt_kernel(
    const float* __restrict__ A, const float* __restrict__ B,
    const float* __restrict__ bias, const float* __restrict__ res,
    float* __restrict__ C, int M, int N, int K, int relu, int scatter)
{
    __shared__ float As[BKG][128];
    __shared__ float Bs[BKG][128];
    int tid = threadIdx.x;
    int tx = tid & 15, ty = tid >> 4;
    int m0 = blockIdx.y * 128, n0 = blockIdx.x * 128;

    float acc[8][8];
    #pragma unroll
    for (int i = 0; i < 8; i++)
        #pragma unroll
        for (int j = 0; j < 8; j++) acc[i][j] = 0.f;

    int lrow = tid >> 1;    // 0..127
    int lseg = tid & 1;     // 0..1
    const float* Aptr = A + (size_t)(m0 + lrow) * K + lseg * 4;
    const float* Bptr = B + (size_t)(n0 + lrow) * K + lseg * 4;

    for (int kk = 0; kk < K; kk += BKG) {
        float4 av = *(const float4*)(Aptr + kk);
        float4 bv = *(const float4*)(Bptr + kk);
        As[lseg*4+0][lrow] = av.x; As[lseg*4+1][lrow] = av.y;
        As[lseg*4+2][lrow] = av.z; As[lseg*4+3][lrow] = av.w;
        Bs[lseg*4+0][lrow] = bv.x; Bs[lseg*4+1][lrow] = bv.y;
        Bs[lseg*4+2][lrow] = bv.z; Bs[lseg*4+3][lrow] = bv.w;
        __syncthreads();
        #pragma unroll
        for (int k = 0; k < BKG; k++) {
            float a[8], b[8];
            *(float4*)&a[0] = *(const float4*)&As[k][ty*8];
            *(float4*)&a[4] = *(const float4*)&As[k][ty*8+4];
            *(float4*)&b[0] = *(const float4*)&Bs[k][tx*8];
            *(float4*)&b[4] = *(const float4*)&Bs[k][tx*8+4];
            #pragma unroll
            for (int i = 0; i < 8; i++)
                #pragma unroll
                for (int j = 0; j < 8; j++)
                    acc[i][j] = fmaf(a[i], b[j], acc[i][j]);
        }
        __syncthreads();
    }

    #pragma unroll
    for (int i = 0; i < 8; i++) {
        int m = m0 + ty*8 + i;
        #pragma unroll
        for (int j = 0; j < 8; j++) {
            int n = n0 + tx*8 + j;
            float v = acc[i][j];
            if (bias) v += bias[n];
            if (relu) v = fmaxf(v, 0.f);
            if (res)  v += res[(size_t)m * N + n];
            if (scatter) {
                int b_ = m >> 10, s_ = m & 1023, h_ = n >> 6, d_ = n & 63;
                C[(((size_t)(b_*16 + h_) << 10) + s_) * 64 + d_] = v;
            } else {
                C[(size_t)m * N + n] = v;
            }
        }
    }
}

// ---------------------------------------------------------------------------
// Fused flash attention (fp32), HD=64, Skv=1024.
// Q,K,V,O in [B,H,S,64] layout. Block: 64 query rows, iterate 64-col K tiles.
// 256 threads as 16x16; thread owns 4 rows x 4 dims (or 4x4 score tile).
// Online softmax. Causal mask optional (diag offset 0 within [S,S]).
// Dynamic smem: Qt/Kt/Pt padded-65, Vs stride-64.
// ---------------------------------------------------------------------------
#define ATTN_SMEM ((3*64*65 + 64*64) * 4)

__global__ __launch_bounds__(256) void attn_kernel(
    const float* __restrict__ Q, const float* __restrict__ K,
    const float* __restrict__ V, float* __restrict__ O, int causal)
{
    extern __shared__ float smem[];
    float* Qt = smem;             // [64][65] transposed: Qt[d*65+r]
    float* Kt = Qt + 64*65;       // [64][65] transposed: Kt[d*65+c]
    float* Pt = Kt + 64*65;       // [64][65] transposed: Pt[c*65+r]
    float* Vs = Pt + 64*65;       // [64][64]           : Vs[c*64+d]

    int tid = threadIdx.x;
    int tx = tid & 15, ty = tid >> 4;
    int q0 = blockIdx.x * 64;
    int bh = blockIdx.y;

    const float* Qb = Q + ((size_t)bh * 1024 + q0) * 64;
    const float* Kb = K + (size_t)bh * 1024 * 64;
    const float* Vb = V + (size_t)bh * 1024 * 64;

    // Load Q tile transposed
    #pragma unroll
    for (int t = 0; t < 4; t++) {
        int lin = tid + t * 256;     // float4 index, 0..1023
        int r = lin >> 4;
        int d0 = (lin & 15) << 2;
        float4 v = *(const float4*)(Qb + r*64 + d0);
        Qt[(d0+0)*65 + r] = v.x;
        Qt[(d0+1)*65 + r] = v.y;
        Qt[(d0+2)*65 + r] = v.z;
        Qt[(d0+3)*65 + r] = v.w;
    }

    float o[4][4];
    float m[4], l[4];
    #pragma unroll
    for (int i = 0; i < 4; i++) {
        m[i] = -1e30f; l[i] = 0.f;
        #pragma unroll
        for (int j = 0; j < 4; j++) o[i][j] = 0.f;
    }

    int ntiles = causal ? (blockIdx.x + 1) : 16;

    for (int t = 0; t < ntiles; t++) {
        int k0 = t * 64;
        __syncthreads();    // protect Kt/Vs (prev PV) and Qt (first iter)
        #pragma unroll
        for (int u = 0; u < 4; u++) {
            int lin = tid + u * 256;
            int r = lin >> 4;
            int d0 = (lin & 15) << 2;
            float4 kv = *(const float4*)(Kb + (size_t)(k0 + r)*64 + d0);
            Kt[(d0+0)*65 + r] = kv.x;
            Kt[(d0+1)*65 + r] = kv.y;
            Kt[(d0+2)*65 + r] = kv.z;
            Kt[(d0+3)*65 + r] = kv.w;
            float4 vv = *(const float4*)(Vb + (size_t)(k0 + r)*64 + d0);
            *(float4*)&Vs[r*64 + d0] = vv;
        }
        __syncthreads();

        // Scores: s[i][j] = q[ty*4+i] . k[tx*4+j]
        float s[4][4];
        #pragma unroll
        for (int i = 0; i < 4; i++)
            #pragma unroll
            for (int j = 0; j < 4; j++) s[i][j] = 0.f;

        #pragma unroll 8
        for (int d = 0; d < 64; d++) {
            float a[4], b[4];
            #pragma unroll
            for (int i = 0; i < 4; i++) a[i] = Qt[d*65 + ty*4 + i];
            #pragma unroll
            for (int j = 0; j < 4; j++) b[j] = Kt[d*65 + tx*4 + j];
            #pragma unroll
            for (int i = 0; i < 4; i++)
                #pragma unroll
                for (int j = 0; j < 4; j++)
                    s[i][j] = fmaf(a[i], b[j], s[i][j]);
        }

        // scale + causal mask
        #pragma unroll
        for (int i = 0; i < 4; i++) {
            int rg = q0 + ty*4 + i;
            #pragma unroll
            for (int j = 0; j < 4; j++) {
                int cg = k0 + tx*4 + j;
                s[i][j] *= 0.125f;                // 1/sqrt(64)
                if (causal && cg > rg) s[i][j] = -1e30f;
            }
        }

        // online softmax update (row state replicated across the 16 tx lanes)
        #pragma unroll
        for (int i = 0; i < 4; i++) {
            float mloc = fmaxf(fmaxf(s[i][0], s[i][1]), fmaxf(s[i][2], s[i][3]));
            #pragma unroll
            for (int off = 8; off > 0; off >>= 1)
                mloc = fmaxf(mloc, __shfl_xor_sync(0xffffffffu, mloc, off));
            float mnew = fmaxf(m[i], mloc);
            float sc = __expf(m[i] - mnew);
            float ls = 0.f;
            #pragma unroll
            for (int j = 0; j < 4; j++) {
                float p = __expf(s[i][j] - mnew);
                s[i][j] = p;
                ls += p;
            }
            #pragma unroll
            for (int off = 8; off > 0; off >>= 1)
                ls += __shfl_xor_sync(0xffffffffu, ls, off);
            l[i] = l[i] * sc + ls;
            m[i] = mnew;
            #pragma unroll
            for (int j = 0; j < 4; j++) o[i][j] *= sc;
            // store P transposed for the PV pass
            #pragma unroll
            for (int j = 0; j < 4; j++)
                Pt[(tx*4 + j)*65 + ty*4 + i] = s[i][j];
        }
        __syncthreads();

        // O += P @ V : thread owns rows ty*4..+3, dims tx*4..+3
        #pragma unroll 8
        for (int c = 0; c < 64; c++) {
            float a[4];
            #pragma unroll
            for (int i = 0; i < 4; i++) a[i] = Pt[c*65 + ty*4 + i];
            float4 bv = *(const float4*)&Vs[c*64 + tx*4];
            #pragma unroll
            for (int i = 0; i < 4; i++) {
                o[i][0] = fmaf(a[i], bv.x, o[i][0]);
                o[i][1] = fmaf(a[i], bv.y, o[i][1]);
                o[i][2] = fmaf(a[i], bv.z, o[i][2]);
                o[i][3] = fmaf(a[i], bv.w, o[i][3]);
            }
        }
    }

    #pragma unroll
    for (int i = 0; i < 4; i++) {
        float inv = 1.0f / l[i];
        float4 ov = make_float4(o[i][0]*inv, o[i][1]*inv, o[i][2]*inv, o[i][3]*inv);
        *(float4*)(O + ((size_t)bh * 1024 + q0 + ty*4 + i) * 64 + tx*4) = ov;
    }
}

// ---------------------------------------------------------------------------
// [B,H,S,HD] -> [B,S,H*HD]
// ---------------------------------------------------------------------------
__global__ __launch_bounds__(256) void bhsd_to_bsd_kernel(
    const float* __restrict__ in, float* __restrict__ out)
{
    int idx = blockIdx.x * 256 + threadIdx.x;   // 0 .. 4M-1
    int d = idx & 63;
    int s = (idx >> 6) & 1023;
    int h = (idx >> 16) & 15;
    int b = idx >> 20;
    out[(((size_t)(b << 10) + s) << 10) + h*64 + d] = in[idx];
}

// ---------------------------------------------------------------------------
// Host launch
// ---------------------------------------------------------------------------
extern "C" void kernel_launch(void* const* d_in, const int* in_sizes, int n_in,
                              void* d_out, int out_size)
{
    (void)in_sizes; (void)n_in; (void)out_size;
    const float* tgt       = (const float*)d_in[0];
    const float* memory    = (const float*)d_in[1];
    const float* Wq        = (const float*)d_in[2];
    const float* Wk        = (const float*)d_in[3];
    const float* Wv        = (const float*)d_in[4];
    const float* Wo        = (const float*)d_in[5];
    const float* mha_in_w  = (const float*)d_in[6];
    const float* mha_in_b  = (const float*)d_in[7];
    const float* mha_out_w = (const float*)d_in[8];
    const float* mha_out_b = (const float*)d_in[9];
    const float* W1        = (const float*)d_in[10];
    const float* b1        = (const float*)d_in[11];
    const float* W2        = (const float*)d_in[12];
    const float* b2        = (const float*)d_in[13];
    const float* g1        = (const float*)d_in[14];
    const float* be1       = (const float*)d_in[15];
    const float* g2        = (const float*)d_in[16];
    const float* be2       = (const float*)d_in[17];
    const float* g3        = (const float*)d_in[18];
    const float* be3       = (const float*)d_in[19];

    float* xout = (float*)d_out;
    float* kout = xout + (size_t)NELEM;   // sa_k [B,H,S,HD]
    float* vout = kout + (size_t)NELEM;   // sa_v [B,H,S,HD]

    float *ln, *q, *k2, *v2, *o, *ob, *x1, *x2, *h1;
    cudaGetSymbolAddress((void**)&ln, g_ln);
    cudaGetSymbolAddress((void**)&q,  g_q);
    cudaGetSymbolAddress((void**)&k2, g_k2);
    cudaGetSymbolAddress((void**)&v2, g_v2);
    cudaGetSymbolAddress((void**)&o,  g_o);
    cudaGetSymbolAddress((void**)&ob, g_ob);
    cudaGetSymbolAddress((void**)&x1, g_x1);
    cudaGetSymbolAddress((void**)&x2, g_x2);
    cudaGetSymbolAddress((void**)&h1, g_h1);

    cudaFuncSetAttribute(attn_kernel,
        cudaFuncAttributeMaxDynamicSharedMemorySize, ATTN_SMEM);

    dim3 gProj(DMODEL/128, TOK/128);      // (8, 32)
    dim3 gFF1 (DFF_/128,  TOK/128);       // (32, 32)
    dim3 gAttn(16, 64);                   // (S/64, B*H)

    // ---- self-attention block ----
    ln_kernel<<<TOK, 256>>>(tgt, g1, be1, ln);
    gemm_nt_kernel<<<gProj, 256>>>(ln, Wq, nullptr, nullptr, q,    TOK, DMODEL, DMODEL, 0, 1);
    gemm_nt_kernel<<<gProj, 256>>>(ln, Wk, nullptr, nullptr, kout, TOK, DMODEL, DMODEL, 0, 1);
    gemm_nt_kernel<<<gProj, 256>>>(ln, Wv, nullptr, nullptr, vout, TOK, DMODEL, DMODEL, 0, 1);
    attn_kernel<<<gAttn, 256, ATTN_SMEM>>>(q, kout, vout, o, 1);
    bhsd_to_bsd_kernel<<<NELEM/256, 256>>>(o, ob);
    gemm_nt_kernel<<<gProj, 256>>>(ob, Wo, nullptr, tgt, x1, TOK, DMODEL, DMODEL, 0, 0);

    // ---- cross-attention block ----
    ln_kernel<<<TOK, 256>>>(x1, g2, be2, ln);
    gemm_nt_kernel<<<gProj, 256>>>(ln,     mha_in_w,             mha_in_b,        nullptr, q,  TOK, DMODEL, DMODEL, 0, 1);
    gemm_nt_kernel<<<gProj, 256>>>(memory, mha_in_w + 1048576,   mha_in_b + 1024, nullptr, k2, TOK, DMODEL, DMODEL, 0, 1);
    gemm_nt_kernel<<<gProj, 256>>>(memory, mha_in_w + 2097152,   mha_in_b + 2048, nullptr, v2, TOK, DMODEL, DMODEL, 0, 1);
    attn_kernel<<<gAttn, 256, ATTN_SMEM>>>(q, k2, v2, o, 0);
    bhsd_to_bsd_kernel<<<NELEM/256, 256>>>(o, ob);
    gemm_nt_kernel<<<gProj, 256>>>(ob, mha_out_w, mha_out_b, x1, x2, TOK, DMODEL, DMODEL, 0, 0);

    // ---- FFN block ----
    ln_kernel<<<TOK, 256>>>(x2, g3, be3, ln);
    gemm_nt_kernel<<<gFF1,  256>>>(ln, W1, b1, nullptr, h1,   TOK, DFF_,   DMODEL, 1, 0);
    gemm_nt_kernel<<<gProj, 256>>>(h1, W2, b2, x2,      xout, TOK, DMODEL, DFF_,   0, 0);
}

// round 2
// speedup vs baseline: 2.2378x; 2.2378x over previous
#include <cuda_runtime.h>
#include <cuda_bf16.h>
#include <math.h>
#include <stdint.h>

// ---------------------------------------------------------------------------
// B=4, S=SM=1024, D=1024, H=16, HD=64, DFF=4096
// Outputs: x[B,S,D], sa_k[B,H,S,HD], sa_v[B,H,S,HD] concatenated in d_out.
// ---------------------------------------------------------------------------

#define TOK    4096
#define DMODEL 1024
#define DFF_   4096
#define NELEM  4194304

// Scratch (static device globals)
__device__ float g_ln[NELEM];
__device__ float g_q [NELEM];
__device__ float g_k2[NELEM];
__device__ float g_v2[NELEM];
__device__ float g_o [NELEM];
__device__ float g_x1[NELEM];
__device__ float g_x2[NELEM];
__device__ float g_h1[16777216];   // 4096 x 4096

// ---------------------------------------------------------------------------
// LayerNorm: one block per row, D=1024, 256 threads x float4
// ---------------------------------------------------------------------------
__global__ __launch_bounds__(256) void ln_kernel(
    const float* __restrict__ x, const float* __restrict__ g,
    const float* __restrict__ be, float* __restrict__ y)
{
    int row = blockIdx.x;
    const float* xr = x + (size_t)row * DMODEL;
    int c = threadIdx.x * 4;
    float4 v = *(const float4*)(xr + c);
    float s  = v.x + v.y + v.z + v.w;
    float ss = v.x*v.x + v.y*v.y + v.z*v.z + v.w*v.w;
    #pragma unroll
    for (int o = 16; o > 0; o >>= 1) {
        s  += __shfl_xor_sync(0xffffffffu, s,  o);
        ss += __shfl_xor_sync(0xffffffffu, ss, o);
    }
    __shared__ float sm[8], sm2[8];
    int w = threadIdx.x >> 5, lane = threadIdx.x & 31;
    if (lane == 0) { sm[w] = s; sm2[w] = ss; }
    __syncthreads();
    s = 0.f; ss = 0.f;
    #pragma unroll
    for (int i = 0; i < 8; i++) { s += sm[i]; ss += sm2[i]; }
    float mu   = s  * (1.0f / DMODEL);
    float var  = ss * (1.0f / DMODEL) - mu * mu;
    float rstd = rsqrtf(var + 1e-5f);
    float4 gv = *(const float4*)(g + c);
    float4 bv = *(const float4*)(be + c);
    float4 o;
    o.x = (v.x - mu) * rstd * gv.x + bv.x;
    o.y = (v.y - mu) * rstd * gv.y + bv.y;
    o.z = (v.z - mu) * rstd * gv.z + bv.z;
    o.w = (v.w - mu) * rstd * gv.w + bv.w;
    *(float4*)(y + (size_t)row * DMODEL + c) = o;
}

// ---------------------------------------------------------------------------
// tf32 tensor-core GEMM (NT): C[M,N] = A[M,K] @ B[N,K]^T (+bias)(+relu)(+res)
// Optional scatter to [B,H,S,HD].
// CTA tile 128x128x32, 8 warps (2x4), warp tile 64x32, mma.m16n8k8.tf32.
// Smem [m][k] stride-36 layout: conflict-free fragment loads + STS.128 stage.
// cvt.rna.tf32 applied at staging (unbiased rounding).
// ---------------------------------------------------------------------------
#define GBUF (128*36)          // floats per matrix buffer
#define GEMM_SMEM (4*GBUF*4)   // 2 buffers x (A+B) x 4B = 73728

__device__ __forceinline__ float cvt_tf32(float x) {
    uint32_t u;
    asm("cvt.rna.tf32.f32 %0, %1;" : "=r"(u) : "f"(x));
    return __uint_as_float(u);
}

__device__ __forceinline__ void mma_tf32(
    float& c0, float& c1, float& c2, float& c3,
    uint32_t a0, uint32_t a1, uint32_t a2, uint32_t a3,
    uint32_t b0, uint32_t b1)
{
    asm volatile(
        "mma.sync.aligned.m16n8k8.row.col.f32.tf32.tf32.f32 "
        "{%0,%1,%2,%3}, {%4,%5,%6,%7}, {%8,%9}, {%0,%1,%2,%3};"
        : "+f"(c0), "+f"(c1), "+f"(c2), "+f"(c3)
        : "r"(a0), "r"(a1), "r"(a2), "r"(a3), "r"(b0), "r"(b1));
}

__global__ __launch_bounds__(256) void gemm_tf32_kernel(
    const float* __restrict__ A, const float* __restrict__ B,
    const float* __restrict__ bias, const float* __restrict__ res,
    float* __restrict__ C, int M, int N, int K, int relu, int scatter)
{
    extern __shared__ float smem[];
    int tid  = threadIdx.x;
    int lane = tid & 31;
    int warp = tid >> 5;
    int g    = lane >> 2;      // groupID 0..7
    int tig  = lane & 3;       // threadInGroup 0..3
    int wm   = warp >> 2;      // 0..1
    int wn   = warp & 3;       // 0..3
    int m0 = blockIdx.y * 128, n0 = blockIdx.x * 128;

    float c[4][4][4];
    #pragma unroll
    for (int i = 0; i < 4; i++)
        #pragma unroll
        for (int j = 0; j < 4; j++)
            #pragma unroll
            for (int f = 0; f < 4; f++) c[i][j][f] = 0.f;

    int srow  = tid >> 3;            // 0..31 (+32*t)
    int kseg  = (tid & 7) * 4;       // 0..28

    const float* Ab = A + (size_t)m0 * K;
    const float* Bb = B + (size_t)n0 * K;

    float4 ra[4], rb[4];
    int NIT = K >> 5;

    // prologue: load tile 0
    #pragma unroll
    for (int t = 0; t < 4; t++) {
        int row = srow + t * 32;
        ra[t] = *(const float4*)(Ab + (size_t)row * K + kseg);
        rb[t] = *(const float4*)(Bb + (size_t)row * K + kseg);
    }
    {
        float* Ad = smem;
        float* Bd = smem + GBUF;
        #pragma unroll
        for (int t = 0; t < 4; t++) {
            int row = srow + t * 32;
            float4 ca = make_float4(cvt_tf32(ra[t].x), cvt_tf32(ra[t].y),
                                    cvt_tf32(ra[t].z), cvt_tf32(ra[t].w));
            float4 cb = make_float4(cvt_tf32(rb[t].x), cvt_tf32(rb[t].y),
                                    cvt_tf32(rb[t].z), cvt_tf32(rb[t].w));
            *(float4*)(Ad + row * 36 + kseg) = ca;
            *(float4*)(Bd + row * 36 + kseg) = cb;
        }
    }
    __syncthreads();

    for (int kk = 0; kk < NIT; kk++) {
        // prefetch next tile into registers
        if (kk + 1 < NIT) {
            int koff = (kk + 1) << 5;
            #pragma unroll
            for (int t = 0; t < 4; t++) {
                int row = srow + t * 32;
                ra[t] = *(const float4*)(Ab + (size_t)row * K + koff + kseg);
                rb[t] = *(const float4*)(Bb + (size_t)row * K + koff + kseg);
            }
        }

        const float* Ac = smem + (kk & 1) * 2 * GBUF;
        const float* Bc = Ac + GBUF;
        const float* Awp = Ac + (wm * 64 + g) * 36 + tig;
        const float* Bwp = Bc + (wn * 32 + g) * 36 + tig;

        #pragma unroll
        for (int ks = 0; ks < 4; ks++) {
            int k0 = ks * 8;
            uint32_t af[4][4], bf[4][2];
            #pragma unroll
            for (int mt = 0; mt < 4; mt++) {
                const float* p = Awp + mt * (16 * 36) + k0;
                af[mt][0] = __float_as_uint(p[0]);
                af[mt][2] = __float_as_uint(p[4]);
                af[mt][1] = __float_as_uint(p[8 * 36]);
                af[mt][3] = __float_as_uint(p[8 * 36 + 4]);
            }
            #pragma unroll
            for (int nt = 0; nt < 4; nt++) {
                const float* p = Bwp + nt * (8 * 36) + k0;
                bf[nt][0] = __float_as_uint(p[0]);
                bf[nt][1] = __float_as_uint(p[4]);
            }
            #pragma unroll
            for (int mt = 0; mt < 4; mt++)
                #pragma unroll
                for (int nt = 0; nt < 4; nt++)
                    mma_tf32(c[mt][nt][0], c[mt][nt][1], c[mt][nt][2], c[mt][nt][3],
                             af[mt][0], af[mt][1], af[mt][2], af[mt][3],
                             bf[nt][0], bf[nt][1]);
        }

        // stage next tile into the other buffer
        if (kk + 1 < NIT) {
            float* Ad = smem + ((kk + 1) & 1) * 2 * GBUF;
            float* Bd = Ad + GBUF;
            #pragma unroll
            for (int t = 0; t < 4; t++) {
                int row = srow + t * 32;
                float4 ca = make_float4(cvt_tf32(ra[t].x), cvt_tf32(ra[t].y),
                                        cvt_tf32(ra[t].z), cvt_tf32(ra[t].w));
                float4 cb = make_float4(cvt_tf32(rb[t].x), cvt_tf32(rb[t].y),
                                        cvt_tf32(rb[t].z), cvt_tf32(rb[t].w));
                *(float4*)(Ad + row * 36 + kseg) = ca;
                *(float4*)(Bd + row * 36 + kseg) = cb;
            }
        }
        __syncthreads();
    }

    // epilogue
    #pragma unroll
    for (int mt = 0; mt < 4; mt++) {
        int row0 = m0 + wm * 64 + mt * 16 + g;
        int row1 = row0 + 8;
        #pragma unroll
        for (int nt = 0; nt < 4; nt++) {
            int col = n0 + wn * 32 + nt * 8 + tig * 2;
            float v00 = c[mt][nt][0], v01 = c[mt][nt][1];
            float v10 = c[mt][nt][2], v11 = c[mt][nt][3];
            if (bias) {
                float b0v = bias[col], b1v = bias[col + 1];
                v00 += b0v; v01 += b1v; v10 += b0v; v11 += b1v;
            }
            if (relu) {
                v00 = fmaxf(v00, 0.f); v01 = fmaxf(v01, 0.f);
                v10 = fmaxf(v10, 0.f); v11 = fmaxf(v11, 0.f);
            }
            if (res) {
                v00 += res[(size_t)row0 * N + col];
                v01 += res[(size_t)row0 * N + col + 1];
                v10 += res[(size_t)row1 * N + col];
                v11 += res[(size_t)row1 * N + col + 1];
            }
            if (scatter) {
                int h_ = col >> 6, d_ = col & 63;
                {
                    int b_ = row0 >> 10, s_ = row0 & 1023;
                    float* p = C + (((size_t)(b_ * 16 + h_) << 10) + s_) * 64 + d_;
                    p[0] = v00; p[1] = v01;
                }
                {
                    int b_ = row1 >> 10, s_ = row1 & 1023;
                    float* p = C + (((size_t)(b_ * 16 + h_) << 10) + s_) * 64 + d_;
                    p[0] = v10; p[1] = v11;
                }
            } else {
                *(float2*)(C + (size_t)row0 * N + col) = make_float2(v00, v01);
                *(float2*)(C + (size_t)row1 * N + col) = make_float2(v10, v11);
            }
        }
    }
}

// ---------------------------------------------------------------------------
// Fused flash attention (fp32), HD=64, Skv=1024. Q,K,V in [B,H,S,64].
// Output written directly in [B,S,H*HD] layout (transpose fused).
// ---------------------------------------------------------------------------
#define ATTN_SMEM ((3*64*65 + 64*64) * 4)

__global__ __launch_bounds__(256) void attn_kernel(
    const float* __restrict__ Q, const float* __restrict__ K,
    const float* __restrict__ V, float* __restrict__ O, int causal)
{
    extern __shared__ float smem[];
    float* Qt = smem;
    float* Kt = Qt + 64*65;
    float* Pt = Kt + 64*65;
    float* Vs = Pt + 64*65;

    int tid = threadIdx.x;
    int tx = tid & 15, ty = tid >> 4;
    int q0 = blockIdx.x * 64;
    int bh = blockIdx.y;

    const float* Qb = Q + ((size_t)bh * 1024 + q0) * 64;
    const float* Kb = K + (size_t)bh * 1024 * 64;
    const float* Vb = V + (size_t)bh * 1024 * 64;

    #pragma unroll
    for (int t = 0; t < 4; t++) {
        int lin = tid + t * 256;
        int r = lin >> 4;
        int d0 = (lin & 15) << 2;
        float4 v = *(const float4*)(Qb + r*64 + d0);
        Qt[(d0+0)*65 + r] = v.x;
        Qt[(d0+1)*65 + r] = v.y;
        Qt[(d0+2)*65 + r] = v.z;
        Qt[(d0+3)*65 + r] = v.w;
    }

    float o[4][4];
    float m[4], l[4];
    #pragma unroll
    for (int i = 0; i < 4; i++) {
        m[i] = -1e30f; l[i] = 0.f;
        #pragma unroll
        for (int j = 0; j < 4; j++) o[i][j] = 0.f;
    }

    int ntiles = causal ? (blockIdx.x + 1) : 16;

    for (int t = 0; t < ntiles; t++) {
        int k0 = t * 64;
        __syncthreads();
        #pragma unroll
        for (int u = 0; u < 4; u++) {
            int lin = tid + u * 256;
            int r = lin >> 4;
            int d0 = (lin & 15) << 2;
            float4 kv = *(const float4*)(Kb + (size_t)(k0 + r)*64 + d0);
            Kt[(d0+0)*65 + r] = kv.x;
            Kt[(d0+1)*65 + r] = kv.y;
            Kt[(d0+2)*65 + r] = kv.z;
            Kt[(d0+3)*65 + r] = kv.w;
            float4 vv = *(const float4*)(Vb + (size_t)(k0 + r)*64 + d0);
            *(float4*)&Vs[r*64 + d0] = vv;
        }
        __syncthreads();

        float s[4][4];
        #pragma unroll
        for (int i = 0; i < 4; i++)
            #pragma unroll
            for (int j = 0; j < 4; j++) s[i][j] = 0.f;

        #pragma unroll 8
        for (int d = 0; d < 64; d++) {
            float a[4], b[4];
            #pragma unroll
            for (int i = 0; i < 4; i++) a[i] = Qt[d*65 + ty*4 + i];
            #pragma unroll
            for (int j = 0; j < 4; j++) b[j] = Kt[d*65 + tx*4 + j];
            #pragma unroll
            for (int i = 0; i < 4; i++)
                #pragma unroll
                for (int j = 0; j < 4; j++)
                    s[i][j] = fmaf(a[i], b[j], s[i][j]);
        }

        #pragma unroll
        for (int i = 0; i < 4; i++) {
            int rg = q0 + ty*4 + i;
            #pragma unroll
            for (int j = 0; j < 4; j++) {
                int cg = k0 + tx*4 + j;
                s[i][j] *= 0.125f;
                if (causal && cg > rg) s[i][j] = -1e30f;
            }
        }

        #pragma unroll
        for (int i = 0; i < 4; i++) {
            float mloc = fmaxf(fmaxf(s[i][0], s[i][1]), fmaxf(s[i][2], s[i][3]));
            #pragma unroll
            for (int off = 8; off > 0; off >>= 1)
                mloc = fmaxf(mloc, __shfl_xor_sync(0xffffffffu, mloc, off));
            float mnew = fmaxf(m[i], mloc);
            float sc = __expf(m[i] - mnew);
            float ls = 0.f;
            #pragma unroll
            for (int j = 0; j < 4; j++) {
                float p = __expf(s[i][j] - mnew);
                s[i][j] = p;
                ls += p;
            }
            #pragma unroll
            for (int off = 8; off > 0; off >>= 1)
                ls += __shfl_xor_sync(0xffffffffu, ls, off);
            l[i] = l[i] * sc + ls;
            m[i] = mnew;
            #pragma unroll
            for (int j = 0; j < 4; j++) o[i][j] *= sc;
            #pragma unroll
            for (int j = 0; j < 4; j++)
                Pt[(tx*4 + j)*65 + ty*4 + i] = s[i][j];
        }
        __syncthreads();

        #pragma unroll 8
        for (int cidx = 0; cidx < 64; cidx++) {
            float a[4];
            #pragma unroll
            for (int i = 0; i < 4; i++) a[i] = Pt[cidx*65 + ty*4 + i];
            float4 bv = *(const float4*)&Vs[cidx*64 + tx*4];
            #pragma unroll
            for (int i = 0; i < 4; i++) {
                o[i][0] = fmaf(a[i], bv.x, o[i][0]);
                o[i][1] = fmaf(a[i], bv.y, o[i][1]);
                o[i][2] = fmaf(a[i], bv.z, o[i][2]);
                o[i][3] = fmaf(a[i], bv.w, o[i][3]);
            }
        }
    }

    // write in [B, S, H*HD] layout (transpose fused)
    int b_ = bh >> 4, h_ = bh & 15;
    float* Ob = O + ((size_t)b_ * 1024) * 1024 + h_ * 64;
    #pragma unroll
    for (int i = 0; i < 4; i++) {
        float inv = 1.0f / l[i];
        float4 ov = make_float4(o[i][0]*inv, o[i][1]*inv, o[i][2]*inv, o[i][3]*inv);
        *(float4*)(Ob + (size_t)(q0 + ty*4 + i) * 1024 + tx*4) = ov;
    }
}

// ---------------------------------------------------------------------------
// Host launch
// ---------------------------------------------------------------------------
extern "C" void kernel_launch(void* const* d_in, const int* in_sizes, int n_in,
                              void* d_out, int out_size)
{
    (void)in_sizes; (void)n_in; (void)out_size;
    const float* tgt       = (const float*)d_in[0];
    const float* memory    = (const float*)d_in[1];
    const float* Wq        = (const float*)d_in[2];
    const float* Wk        = (const float*)d_in[3];
    const float* Wv        = (const float*)d_in[4];
    const float* Wo        = (const float*)d_in[5];
    const float* mha_in_w  = (const float*)d_in[6];
    const float* mha_in_b  = (const float*)d_in[7];
    const float* mha_out_w = (const float*)d_in[8];
    const float* mha_out_b = (const float*)d_in[9];
    const float* W1        = (const float*)d_in[10];
    const float* b1        = (const float*)d_in[11];
    const float* W2        = (const float*)d_in[12];
    const float* b2        = (const float*)d_in[13];
    const float* g1        = (const float*)d_in[14];
    const float* be1       = (const float*)d_in[15];
    const float* g2        = (const float*)d_in[16];
    const float* be2       = (const float*)d_in[17];
    const float* g3        = (const float*)d_in[18];
    const float* be3       = (const float*)d_in[19];

    float* xout = (float*)d_out;
    float* kout = xout + (size_t)NELEM;
    float* vout = kout + (size_t)NELEM;

    float *ln, *q, *k2, *v2, *o, *x1, *x2, *h1;
    cudaGetSymbolAddress((void**)&ln, g_ln);
    cudaGetSymbolAddress((void**)&q,  g_q);
    cudaGetSymbolAddress((void**)&k2, g_k2);
    cudaGetSymbolAddress((void**)&v2, g_v2);
    cudaGetSymbolAddress((void**)&o,  g_o);
    cudaGetSymbolAddress((void**)&x1, g_x1);
    cudaGetSymbolAddress((void**)&x2, g_x2);
    cudaGetSymbolAddress((void**)&h1, g_h1);

    cudaFuncSetAttribute(attn_kernel,
        cudaFuncAttributeMaxDynamicSharedMemorySize, ATTN_SMEM);
    cudaFuncSetAttribute(gemm_tf32_kernel,
        cudaFuncAttributeMaxDynamicSharedMemorySize, GEMM_SMEM);

    dim3 gProj(DMODEL/128, TOK/128);      // (8, 32)
    dim3 gFF1 (DFF_/128,  TOK/128);       // (32, 32)
    dim3 gAttn(16, 64);

    // ---- self-attention ----
    ln_kernel<<<TOK, 256>>>(tgt, g1, be1, ln);
    gemm_tf32_kernel<<<gProj, 256, GEMM_SMEM>>>(ln, Wq, nullptr, nullptr, q,    TOK, DMODEL, DMODEL, 0, 1);
    gemm_tf32_kernel<<<gProj, 256, GEMM_SMEM>>>(ln, Wk, nullptr, nullptr, kout, TOK, DMODEL, DMODEL, 0, 1);
    gemm_tf32_kernel<<<gProj, 256, GEMM_SMEM>>>(ln, Wv, nullptr, nullptr, vout, TOK, DMODEL, DMODEL, 0, 1);
    attn_kernel<<<gAttn, 256, ATTN_SMEM>>>(q, kout, vout, o, 1);
    gemm_tf32_kernel<<<gProj, 256, GEMM_SMEM>>>(o, Wo, nullptr, tgt, x1, TOK, DMODEL, DMODEL, 0, 0);

    // ---- cross-attention ----
    ln_kernel<<<TOK, 256>>>(x1, g2, be2, ln);
    gemm_tf32_kernel<<<gProj, 256, GEMM_SMEM>>>(ln,     mha_in_w,           mha_in_b,        nullptr, q,  TOK, DMODEL, DMODEL, 0, 1);
    gemm_tf32_kernel<<<gProj, 256, GEMM_SMEM>>>(memory, mha_in_w + 1048576, mha_in_b + 1024, nullptr, k2, TOK, DMODEL, DMODEL, 0, 1);
    gemm_tf32_kernel<<<gProj, 256, GEMM_SMEM>>>(memory, mha_in_w + 2097152, mha_in_b + 2048, nullptr, v2, TOK, DMODEL, DMODEL, 0, 1);
    attn_kernel<<<gAttn, 256, ATTN_SMEM>>>(q, k2, v2, o, 0);
    gemm_tf32_kernel<<<gProj, 256, GEMM_SMEM>>>(o, mha_out_w, mha_out_b, x1, x2, TOK, DMODEL, DMODEL, 0, 0);

    // ---- FFN ----
    ln_kernel<<<TOK, 256>>>(x2, g3, be3, ln);
    gemm_tf32_kernel<<<gFF1,  256, GEMM_SMEM>>>(ln, W1, b1, nullptr, h1,   TOK, DFF_,   DMODEL, 1, 0);
    gemm_tf32_kernel<<<gProj, 256, GEMM_SMEM>>>(h1, W2, b2, x2,      xout, TOK, DMODEL, DFF_,   0, 0);
}

// round 3
// speedup vs baseline: 2.3351x; 1.0435x over previous
#include <cuda_runtime.h>
#include <cuda_bf16.h>
#include <math.h>
#include <stdint.h>

// ---------------------------------------------------------------------------
// B=4, S=SM=1024, D=1024, H=16, HD=64, DFF=4096
// Outputs: x[B,S,D], sa_k[B,H,S,HD], sa_v[B,H,S,HD] concatenated in d_out.
// ---------------------------------------------------------------------------

#define TOK    4096
#define DMODEL 1024
#define DFF_   4096
#define NELEM  4194304

// Scratch (static device globals)
__device__ float g_ln[NELEM];
__device__ float g_q [NELEM];
__device__ float g_k2[NELEM];
__device__ float g_v2[NELEM];
__device__ float g_o [NELEM];
__device__ float g_x1[NELEM];
__device__ float g_x2[NELEM];
__device__ float g_h1[16777216];    // 4096 x 4096
__device__ float g_rw[20971520];    // tf32-rounded weights + memory (20M floats)

// rounded-region offsets (floats)
#define RW_WQ   0
#define RW_WK   1048576
#define RW_WV   2097152
#define RW_WO   3145728
#define RW_INW  4194304
#define RW_OUTW 7340032
#define RW_W1   8388608
#define RW_W2   12582912
#define RW_MEM  16777216

__device__ __forceinline__ float cvt_tf32(float x) {
    uint32_t u;
    asm("cvt.rna.tf32.f32 %0, %1;" : "=r"(u) : "f"(x));
    return __uint_as_float(u);
}

// ---------------------------------------------------------------------------
// Round weights + memory to tf32 (rna) into g_rw. 5242880 float4s.
// ---------------------------------------------------------------------------
__global__ __launch_bounds__(256) void round_all_kernel(
    const float* __restrict__ wq, const float* __restrict__ wk,
    const float* __restrict__ wv, const float* __restrict__ wo,
    const float* __restrict__ inw, const float* __restrict__ outw,
    const float* __restrict__ w1, const float* __restrict__ w2,
    const float* __restrict__ mem, float* __restrict__ dst)
{
    int i = blockIdx.x * 256 + threadIdx.x;   // float4 index, 0..5242879
    const float* src;
    int base;
    if      (i < 262144)  { src = wq;   base = 0; }
    else if (i < 524288)  { src = wk;   base = 262144; }
    else if (i < 786432)  { src = wv;   base = 524288; }
    else if (i < 1048576) { src = wo;   base = 786432; }
    else if (i < 1835008) { src = inw;  base = 1048576; }
    else if (i < 2097152) { src = outw; base = 1835008; }
    else if (i < 3145728) { src = w1;   base = 2097152; }
    else if (i < 4194304) { src = w2;   base = 3145728; }
    else                  { src = mem;  base = 4194304; }
    float4 v = ((const float4*)src)[i - base];
    v.x = cvt_tf32(v.x); v.y = cvt_tf32(v.y);
    v.z = cvt_tf32(v.z); v.w = cvt_tf32(v.w);
    ((float4*)dst)[i] = v;
}

// ---------------------------------------------------------------------------
// LayerNorm: one block per row, D=1024. Output pre-rounded to tf32.
// ---------------------------------------------------------------------------
__global__ __launch_bounds__(256) void ln_kernel(
    const float* __restrict__ x, const float* __restrict__ g,
    const float* __restrict__ be, float* __restrict__ y)
{
    int row = blockIdx.x;
    const float* xr = x + (size_t)row * DMODEL;
    int c = threadIdx.x * 4;
    float4 v = *(const float4*)(xr + c);
    float s  = v.x + v.y + v.z + v.w;
    float ss = v.x*v.x + v.y*v.y + v.z*v.z + v.w*v.w;
    #pragma unroll
    for (int o = 16; o > 0; o >>= 1) {
        s  += __shfl_xor_sync(0xffffffffu, s,  o);
        ss += __shfl_xor_sync(0xffffffffu, ss, o);
    }
    __shared__ float sm[8], sm2[8];
    int w = threadIdx.x >> 5, lane = threadIdx.x & 31;
    if (lane == 0) { sm[w] = s; sm2[w] = ss; }
    __syncthreads();
    s = 0.f; ss = 0.f;
    #pragma unroll
    for (int i = 0; i < 8; i++) { s += sm[i]; ss += sm2[i]; }
    float mu   = s  * (1.0f / DMODEL);
    float var  = ss * (1.0f / DMODEL) - mu * mu;
    float rstd = rsqrtf(var + 1e-5f);
    float4 gv = *(const float4*)(g + c);
    float4 bv = *(const float4*)(be + c);
    float4 o;
    o.x = cvt_tf32((v.x - mu) * rstd * gv.x + bv.x);
    o.y = cvt_tf32((v.y - mu) * rstd * gv.y + bv.y);
    o.z = cvt_tf32((v.z - mu) * rstd * gv.z + bv.z);
    o.w = cvt_tf32((v.w - mu) * rstd * gv.w + bv.w);
    *(float4*)(y + (size_t)row * DMODEL + c) = o;
}

// ---------------------------------------------------------------------------
// tf32 tensor-core GEMM (NT), cp.async 3-stage pipeline.
// C[M,N] = A[M,K] @ B[N,K]^T (+bias)(+relu)(+res)(+round)(+scatter)
// CTA 128x128x32, 8 warps (2x4), warp tile 64x32, mma.m16n8k8.tf32.
// Inputs must already be tf32-rounded.
// Smem [m][k] stride-36: conflict-free fragment LDS; 144B row pitch is
// 16B-aligned so cp.async.cg 16B staging works directly.
// ---------------------------------------------------------------------------
#define GBUF 4608                    // 128*36 floats per matrix per stage
#define STAGEB (2*GBUF)              // A+B floats per stage
#define GEMM_SMEM (3*STAGEB*4)       // 110592 bytes

__device__ __forceinline__ void mma_tf32(
    float& c0, float& c1, float& c2, float& c3,
    uint32_t a0, uint32_t a1, uint32_t a2, uint32_t a3,
    uint32_t b0, uint32_t b1)
{
    asm volatile(
        "mma.sync.aligned.m16n8k8.row.col.f32.tf32.tf32.f32 "
        "{%0,%1,%2,%3}, {%4,%5,%6,%7}, {%8,%9}, {%0,%1,%2,%3};"
        : "+f"(c0), "+f"(c1), "+f"(c2), "+f"(c3)
        : "r"(a0), "r"(a1), "r"(a2), "r"(a3), "r"(b0), "r"(b1));
}

__device__ __forceinline__ void cp16(uint32_t dst, const float* src) {
    asm volatile("cp.async.cg.shared.global [%0], [%1], 16;"
                 :: "r"(dst), "l"(src));
}

__global__ __launch_bounds__(256) void gemm_tf32_kernel(
    const float* __restrict__ A, const float* __restrict__ B,
    const float* __restrict__ bias, const float* __restrict__ res,
    float* __restrict__ C, int M, int N, int K,
    int relu, int scatter, int roundC)
{
    extern __shared__ float smem[];
    uint32_t sbase = (uint32_t)__cvta_generic_to_shared(smem);

    int tid  = threadIdx.x;
    int lane = tid & 31;
    int warp = tid >> 5;
    int g    = lane >> 2;
    int tig  = lane & 3;
    int wm   = warp >> 2;
    int wn   = warp & 3;
    int m0 = blockIdx.y * 128, n0 = blockIdx.x * 128;

    float c[4][4][4];
    #pragma unroll
    for (int i = 0; i < 4; i++)
        #pragma unroll
        for (int j = 0; j < 4; j++)
            #pragma unroll
            for (int f = 0; f < 4; f++) c[i][j][f] = 0.f;

    int srow = tid >> 3;          // 0..31
    int kseg = (tid & 7) * 4;     // 0..28

    const float* Ab = A + (size_t)m0 * K;
    const float* Bb = B + (size_t)n0 * K;
    int NIT = K >> 5;

    // per-thread smem staging offsets (bytes), stage-relative
    uint32_t stA[4], stB[4];
    #pragma unroll
    for (int t = 0; t < 4; t++) {
        int row = srow + t * 32;
        stA[t] = sbase + (uint32_t)(row * 36 + kseg) * 4;
        stB[t] = stA[t] + GBUF * 4;
    }

    // prologue: stage 0 and 1
    #pragma unroll
    for (int s = 0; s < 2; s++) {
        if (s < NIT) {
            int koff = s << 5;
            uint32_t so = (uint32_t)(s * STAGEB) * 4;
            #pragma unroll
            for (int t = 0; t < 4; t++) {
                int row = srow + t * 32;
                cp16(stA[t] + so, Ab + (size_t)row * K + koff + kseg);
                cp16(stB[t] + so, Bb + (size_t)row * K + koff + kseg);
            }
        }
        asm volatile("cp.async.commit_group;");
    }

    int bufc = 0, bufn = 2;
    for (int kk = 0; kk < NIT; kk++) {
        asm volatile("cp.async.wait_group 1;");
        __syncthreads();

        if (kk + 2 < NIT) {
            int koff = (kk + 2) << 5;
            uint32_t so = (uint32_t)(bufn * STAGEB) * 4;
            #pragma unroll
            for (int t = 0; t < 4; t++) {
                int row = srow + t * 32;
                cp16(stA[t] + so, Ab + (size_t)row * K + koff + kseg);
                cp16(stB[t] + so, Bb + (size_t)row * K + koff + kseg);
            }
        }
        asm volatile("cp.async.commit_group;");

        const float* Ac = smem + bufc * STAGEB;
        const float* Bc = Ac + GBUF;
        const float* Awp = Ac + (wm * 64 + g) * 36 + tig;
        const float* Bwp = Bc + (wn * 32 + g) * 36 + tig;

        #pragma unroll
        for (int ks = 0; ks < 4; ks++) {
            int k0 = ks * 8;
            uint32_t af[4][4], bf[4][2];
            #pragma unroll
            for (int mt = 0; mt < 4; mt++) {
                const float* p = Awp + mt * (16 * 36) + k0;
                af[mt][0] = __float_as_uint(p[0]);
                af[mt][2] = __float_as_uint(p[4]);
                af[mt][1] = __float_as_uint(p[8 * 36]);
                af[mt][3] = __float_as_uint(p[8 * 36 + 4]);
            }
            #pragma unroll
            for (int nt = 0; nt < 4; nt++) {
                const float* p = Bwp + nt * (8 * 36) + k0;
                bf[nt][0] = __float_as_uint(p[0]);
                bf[nt][1] = __float_as_uint(p[4]);
            }
            #pragma unroll
            for (int mt = 0; mt < 4; mt++)
                #pragma unroll
                for (int nt = 0; nt < 4; nt++)
                    mma_tf32(c[mt][nt][0], c[mt][nt][1], c[mt][nt][2], c[mt][nt][3],
                             af[mt][0], af[mt][1], af[mt][2], af[mt][3],
                             bf[nt][0], bf[nt][1]);
        }
        __syncthreads();
        bufc = (bufc == 2) ? 0 : bufc + 1;
        bufn = (bufn == 2) ? 0 : bufn + 1;
    }

    // epilogue
    #pragma unroll
    for (int mt = 0; mt < 4; mt++) {
        int row0 = m0 + wm * 64 + mt * 16 + g;
        int row1 = row0 + 8;
        #pragma unroll
        for (int nt = 0; nt < 4; nt++) {
            int col = n0 + wn * 32 + nt * 8 + tig * 2;
            float v00 = c[mt][nt][0], v01 = c[mt][nt][1];
            float v10 = c[mt][nt][2], v11 = c[mt][nt][3];
            if (bias) {
                float b0v = bias[col], b1v = bias[col + 1];
                v00 += b0v; v01 += b1v; v10 += b0v; v11 += b1v;
            }
            if (relu) {
                v00 = fmaxf(v00, 0.f); v01 = fmaxf(v01, 0.f);
                v10 = fmaxf(v10, 0.f); v11 = fmaxf(v11, 0.f);
            }
            if (res) {
                v00 += res[(size_t)row0 * N + col];
                v01 += res[(size_t)row0 * N + col + 1];
                v10 += res[(size_t)row1 * N + col];
                v11 += res[(size_t)row1 * N + col + 1];
            }
            if (roundC) {
                v00 = cvt_tf32(v00); v01 = cvt_tf32(v01);
                v10 = cvt_tf32(v10); v11 = cvt_tf32(v11);
            }
            if (scatter) {
                int h_ = col >> 6, d_ = col & 63;
                {
                    int b_ = row0 >> 10, s_ = row0 & 1023;
                    float* p = C + (((size_t)(b_ * 16 + h_) << 10) + s_) * 64 + d_;
                    p[0] = v00; p[1] = v01;
                }
                {
                    int b_ = row1 >> 10, s_ = row1 & 1023;
                    float* p = C + (((size_t)(b_ * 16 + h_) << 10) + s_) * 64 + d_;
                    p[0] = v10; p[1] = v11;
                }
            } else {
                *(float2*)(C + (size_t)row0 * N + col) = make_float2(v00, v01);
                *(float2*)(C + (size_t)row1 * N + col) = make_float2(v10, v11);
            }
        }
    }
}

// ---------------------------------------------------------------------------
// Fused flash attention (fp32), HD=64, Skv=1024. Q,K,V in [B,H,S,64].
// Output written in [B,S,H*HD] layout, pre-rounded to tf32 (feeds a GEMM).
// ---------------------------------------------------------------------------
#define ATTN_SMEM ((3*64*65 + 64*64) * 4)

__global__ __launch_bounds__(256) void attn_kernel(
    const float* __restrict__ Q, const float* __restrict__ K,
    const float* __restrict__ V, float* __restrict__ O, int causal)
{
    extern __shared__ float smem[];
    float* Qt = smem;
    float* Kt = Qt + 64*65;
    float* Pt = Kt + 64*65;
    float* Vs = Pt + 64*65;

    int tid = threadIdx.x;
    int tx = tid & 15, ty = tid >> 4;
    int q0 = blockIdx.x * 64;
    int bh = blockIdx.y;

    const float* Qb = Q + ((size_t)bh * 1024 + q0) * 64;
    const float* Kb = K + (size_t)bh * 1024 * 64;
    const float* Vb = V + (size_t)bh * 1024 * 64;

    #pragma unroll
    for (int t = 0; t < 4; t++) {
        int lin = tid + t * 256;
        int r = lin >> 4;
        int d0 = (lin & 15) << 2;
        float4 v = *(const float4*)(Qb + r*64 + d0);
        Qt[(d0+0)*65 + r] = v.x;
        Qt[(d0+1)*65 + r] = v.y;
        Qt[(d0+2)*65 + r] = v.z;
        Qt[(d0+3)*65 + r] = v.w;
    }

    float o[4][4];
    float m[4], l[4];
    #pragma unroll
    for (int i = 0; i < 4; i++) {
        m[i] = -1e30f; l[i] = 0.f;
        #pragma unroll
        for (int j = 0; j < 4; j++) o[i][j] = 0.f;
    }

    int ntiles = causal ? (blockIdx.x + 1) : 16;

    for (int t = 0; t < ntiles; t++) {
        int k0 = t * 64;
        __syncthreads();
        #pragma unroll
        for (int u = 0; u < 4; u++) {
            int lin = tid + u * 256;
            int r = lin >> 4;
            int d0 = (lin & 15) << 2;
            float4 kv = *(const float4*)(Kb + (size_t)(k0 + r)*64 + d0);
            Kt[(d0+0)*65 + r] = kv.x;
            Kt[(d0+1)*65 + r] = kv.y;
            Kt[(d0+2)*65 + r] = kv.z;
            Kt[(d0+3)*65 + r] = kv.w;
            float4 vv = *(const float4*)(Vb + (size_t)(k0 + r)*64 + d0);
            *(float4*)&Vs[r*64 + d0] = vv;
        }
        __syncthreads();

        float s[4][4];
        #pragma unroll
        for (int i = 0; i < 4; i++)
            #pragma unroll
            for (int j = 0; j < 4; j++) s[i][j] = 0.f;

        #pragma unroll 8
        for (int d = 0; d < 64; d++) {
            float a[4], b[4];
            #pragma unroll
            for (int i = 0; i < 4; i++) a[i] = Qt[d*65 + ty*4 + i];
            #pragma unroll
            for (int j = 0; j < 4; j++) b[j] = Kt[d*65 + tx*4 + j];
            #pragma unroll
            for (int i = 0; i < 4; i++)
                #pragma unroll
                for (int j = 0; j < 4; j++)
                    s[i][j] = fmaf(a[i], b[j], s[i][j]);
        }

        #pragma unroll
        for (int i = 0; i < 4; i++) {
            int rg = q0 + ty*4 + i;
            #pragma unroll
            for (int j = 0; j < 4; j++) {
                int cg = k0 + tx*4 + j;
                s[i][j] *= 0.125f;
                if (causal && cg > rg) s[i][j] = -1e30f;
            }
        }

        #pragma unroll
        for (int i = 0; i < 4; i++) {
            float mloc = fmaxf(fmaxf(s[i][0], s[i][1]), fmaxf(s[i][2], s[i][3]));
            #pragma unroll
            for (int off = 8; off > 0; off >>= 1)
                mloc = fmaxf(mloc, __shfl_xor_sync(0xffffffffu, mloc, off));
            float mnew = fmaxf(m[i], mloc);
            float sc = __expf(m[i] - mnew);
            float ls = 0.f;
            #pragma unroll
            for (int j = 0; j < 4; j++) {
                float p = __expf(s[i][j] - mnew);
                s[i][j] = p;
                ls += p;
            }
            #pragma unroll
            for (int off = 8; off > 0; off >>= 1)
                ls += __shfl_xor_sync(0xffffffffu, ls, off);
            l[i] = l[i] * sc + ls;
            m[i] = mnew;
            #pragma unroll
            for (int j = 0; j < 4; j++) o[i][j] *= sc;
            #pragma unroll
            for (int j = 0; j < 4; j++)
                Pt[(tx*4 + j)*65 + ty*4 + i] = s[i][j];
        }
        __syncthreads();

        #pragma unroll 8
        for (int cidx = 0; cidx < 64; cidx++) {
            float a[4];
            #pragma unroll
            for (int i = 0; i < 4; i++) a[i] = Pt[cidx*65 + ty*4 + i];
            float4 bv = *(const float4*)&Vs[cidx*64 + tx*4];
            #pragma unroll
            for (int i = 0; i < 4; i++) {
                o[i][0] = fmaf(a[i], bv.x, o[i][0]);
                o[i][1] = fmaf(a[i], bv.y, o[i][1]);
                o[i][2] = fmaf(a[i], bv.z, o[i][2]);
                o[i][3] = fmaf(a[i], bv.w, o[i][3]);
            }
        }
    }

    int b_ = bh >> 4, h_ = bh & 15;
    float* Ob = O + ((size_t)b_ * 1024) * 1024 + h_ * 64;
    #pragma unroll
    for (int i = 0; i < 4; i++) {
        float inv = 1.0f / l[i];
        float4 ov = make_float4(cvt_tf32(o[i][0]*inv), cvt_tf32(o[i][1]*inv),
                                cvt_tf32(o[i][2]*inv), cvt_tf32(o[i][3]*inv));
        *(float4*)(Ob + (size_t)(q0 + ty*4 + i) * 1024 + tx*4) = ov;
    }
}

// ---------------------------------------------------------------------------
// Host launch
// ---------------------------------------------------------------------------
extern "C" void kernel_launch(void* const* d_in, const int* in_sizes, int n_in,
                              void* d_out, int out_size)
{
    (void)in_sizes; (void)n_in; (void)out_size;
    const float* tgt       = (const float*)d_in[0];
    const float* memory    = (const float*)d_in[1];
    const float* Wq        = (const float*)d_in[2];
    const float* Wk        = (const float*)d_in[3];
    const float* Wv        = (const float*)d_in[4];
    const float* Wo        = (const float*)d_in[5];
    const float* mha_in_w  = (const float*)d_in[6];
    const float* mha_in_b  = (const float*)d_in[7];
    const float* mha_out_w = (const float*)d_in[8];
    const float* mha_out_b = (const float*)d_in[9];
    const float* W1        = (const float*)d_in[10];
    const float* b1        = (const float*)d_in[11];
    const float* W2        = (const float*)d_in[12];
    const float* b2        = (const float*)d_in[13];
    const float* g1        = (const float*)d_in[14];
    const float* be1       = (const float*)d_in[15];
    const float* g2        = (const float*)d_in[16];
    const float* be2       = (const float*)d_in[17];
    const float* g3        = (const float*)d_in[18];
    const float* be3       = (const float*)d_in[19];

    float* xout = (float*)d_out;
    float* kout = xout + (size_t)NELEM;
    float* vout = kout + (size_t)NELEM;

    float *ln, *q, *k2, *v2, *o, *x1, *x2, *h1, *rw;
    cudaGetSymbolAddress((void**)&ln, g_ln);
    cudaGetSymbolAddress((void**)&q,  g_q);
    cudaGetSymbolAddress((void**)&k2, g_k2);
    cudaGetSymbolAddress((void**)&v2, g_v2);
    cudaGetSymbolAddress((void**)&o,  g_o);
    cudaGetSymbolAddress((void**)&x1, g_x1);
    cudaGetSymbolAddress((void**)&x2, g_x2);
    cudaGetSymbolAddress((void**)&h1, g_h1);
    cudaGetSymbolAddress((void**)&rw, g_rw);

    cudaFuncSetAttribute(attn_kernel,
        cudaFuncAttributeMaxDynamicSharedMemorySize, ATTN_SMEM);
    cudaFuncSetAttribute(gemm_tf32_kernel,
        cudaFuncAttributeMaxDynamicSharedMemorySize, GEMM_SMEM);

    dim3 gProj(DMODEL/128, TOK/128);      // (8, 32)
    dim3 gFF1 (DFF_/128,  TOK/128);       // (32, 32)
    dim3 gAttn(16, 64);

    // pre-round weights + memory to tf32
    round_all_kernel<<<20480, 256>>>(Wq, Wk, Wv, Wo, mha_in_w, mha_out_w,
                                     W1, W2, memory, rw);

    // ---- self-attention ----
    ln_kernel<<<TOK, 256>>>(tgt, g1, be1, ln);
    gemm_tf32_kernel<<<gProj, 256, GEMM_SMEM>>>(ln, rw+RW_WQ, nullptr, nullptr, q,    TOK, DMODEL, DMODEL, 0, 1, 0);
    gemm_tf32_kernel<<<gProj, 256, GEMM_SMEM>>>(ln, rw+RW_WK, nullptr, nullptr, kout, TOK, DMODEL, DMODEL, 0, 1, 0);
    gemm_tf32_kernel<<<gProj, 256, GEMM_SMEM>>>(ln, rw+RW_WV, nullptr, nullptr, vout, TOK, DMODEL, DMODEL, 0, 1, 0);
    attn_kernel<<<gAttn, 256, ATTN_SMEM>>>(q, kout, vout, o, 1);
    gemm_tf32_kernel<<<gProj, 256, GEMM_SMEM>>>(o, rw+RW_WO, nullptr, tgt, x1, TOK, DMODEL, DMODEL, 0, 0, 0);

    // ---- cross-attention ----
    ln_kernel<<<TOK, 256>>>(x1, g2, be2, ln);
    gemm_tf32_kernel<<<gProj, 256, GEMM_SMEM>>>(ln,         rw+RW_INW,           mha_in_b,        nullptr, q,  TOK, DMODEL, DMODEL, 0, 1, 0);
    gemm_tf32_kernel<<<gProj, 256, GEMM_SMEM>>>(rw+RW_MEM,  rw+RW_INW+1048576,   mha_in_b + 1024, nullptr, k2, TOK, DMODEL, DMODEL, 0, 1, 0);
    gemm_tf32_kernel<<<gProj, 256, GEMM_SMEM>>>(rw+RW_MEM,  rw+RW_INW+2097152,   mha_in_b + 2048, nullptr, v2, TOK, DMODEL, DMODEL, 0, 1, 0);
    attn_kernel<<<gAttn, 256, ATTN_SMEM>>>(q, k2, v2, o, 0);
    gemm_tf32_kernel<<<gProj, 256, GEMM_SMEM>>>(o, rw+RW_OUTW, mha_out_b, x1, x2, TOK, DMODEL, DMODEL, 0, 0, 0);

    // ---- FFN ----
    ln_kernel<<<TOK, 256>>>(x2, g3, be3, ln);
    gemm_tf32_kernel<<<gFF1,  256, GEMM_SMEM>>>(ln, rw+RW_W1, b1, nullptr, h1,   TOK, DFF_,   DMODEL, 1, 0, 1);
    gemm_tf32_kernel<<<gProj, 256, GEMM_SMEM>>>(h1, rw+RW_W2, b2, x2,      xout, TOK, DMODEL, DFF_,   0, 0, 0);
}

// round 6
// speedup vs baseline: 3.1415x; 1.3454x over previous
#include <cuda_runtime.h>
#include <cuda_bf16.h>
#include <math.h>
#include <stdint.h>

// ---------------------------------------------------------------------------
// B=4, S=SM=1024, D=1024, H=16, HD=64, DFF=4096
// Outputs: x[B,S,D], sa_k[B,H,S,HD], sa_v[B,H,S,HD] concatenated in d_out.
// ---------------------------------------------------------------------------

#define TOK    4096
#define DMODEL 1024
#define DFF_   4096
#define NELEM  4194304

__device__ float g_ln[NELEM];
__device__ float g_q [NELEM];
__device__ float g_k2[NELEM];
__device__ float g_v2[NELEM];
__device__ float g_o [NELEM];
__device__ float g_x1[NELEM];
__device__ float g_x2[NELEM];
__device__ float g_h1[16777216];    // 4096 x 4096
__device__ float g_rw[20971520];    // tf32-rounded weights + memory

#define RW_WQ   0
#define RW_WK   1048576
#define RW_WV   2097152
#define RW_WO   3145728
#define RW_INW  4194304
#define RW_OUTW 7340032
#define RW_W1   8388608
#define RW_W2   12582912
#define RW_MEM  16777216

// single dynamic-smem declaration for the whole TU
extern __shared__ char dyn_smem[];

__device__ __forceinline__ float cvt_tf32(float x) {
    uint32_t u;
    asm("cvt.rna.tf32.f32 %0, %1;" : "=r"(u) : "f"(x));
    return __uint_as_float(u);
}

__device__ __forceinline__ void mma_tf32(
    float& c0, float& c1, float& c2, float& c3,
    uint32_t a0, uint32_t a1, uint32_t a2, uint32_t a3,
    uint32_t b0, uint32_t b1)
{
    asm volatile(
        "mma.sync.aligned.m16n8k8.row.col.f32.tf32.tf32.f32 "
        "{%0,%1,%2,%3}, {%4,%5,%6,%7}, {%8,%9}, {%0,%1,%2,%3};"
        : "+f"(c0), "+f"(c1), "+f"(c2), "+f"(c3)
        : "r"(a0), "r"(a1), "r"(a2), "r"(a3), "r"(b0), "r"(b1));
}

__device__ __forceinline__ void cp16(uint32_t dst, const float* src) {
    asm volatile("cp.async.cg.shared.global [%0], [%1], 16;"
                 :: "r"(dst), "l"(src));
}

// ---------------------------------------------------------------------------
// Round weights + memory to tf32 (rna) into g_rw.
// ---------------------------------------------------------------------------
__global__ __launch_bounds__(256) void round_all_kernel(
    const float* __restrict__ wq, const float* __restrict__ wk,
    const float* __restrict__ wv, const float* __restrict__ wo,
    const float* __restrict__ inw, const float* __restrict__ outw,
    const float* __restrict__ w1, const float* __restrict__ w2,
    const float* __restrict__ mem, float* __restrict__ dst)
{
    int i = blockIdx.x * 256 + threadIdx.x;
    const float* src;
    int base;
    if      (i < 262144)  { src = wq;   base = 0; }
    else if (i < 524288)  { src = wk;   base = 262144; }
    else if (i < 786432)  { src = wv;   base = 524288; }
    else if (i < 1048576) { src = wo;   base = 786432; }
    else if (i < 1835008) { src = inw;  base = 1048576; }
    else if (i < 2097152) { src = outw; base = 1835008; }
    else if (i < 3145728) { src = w1;   base = 2097152; }
    else if (i < 4194304) { src = w2;   base = 3145728; }
    else                  { src = mem;  base = 4194304; }
    float4 v = ((const float4*)src)[i - base];
    v.x = cvt_tf32(v.x); v.y = cvt_tf32(v.y);
    v.z = cvt_tf32(v.z); v.w = cvt_tf32(v.w);
    ((float4*)dst)[i] = v;
}

// ---------------------------------------------------------------------------
// LayerNorm (tf32-rounded output)
// ---------------------------------------------------------------------------
__global__ __launch_bounds__(256) void ln_kernel(
    const float* __restrict__ x, const float* __restrict__ g,
    const float* __restrict__ be, float* __restrict__ y)
{
    int row = blockIdx.x;
    const float* xr = x + (size_t)row * DMODEL;
    int c = threadIdx.x * 4;
    float4 v = *(const float4*)(xr + c);
    float s  = v.x + v.y + v.z + v.w;
    float ss = v.x*v.x + v.y*v.y + v.z*v.z + v.w*v.w;
    #pragma unroll
    for (int o = 16; o > 0; o >>= 1) {
        s  += __shfl_xor_sync(0xffffffffu, s,  o);
        ss += __shfl_xor_sync(0xffffffffu, ss, o);
    }
    __shared__ float sm[8], sm2[8];
    int w = threadIdx.x >> 5, lane = threadIdx.x & 31;
    if (lane == 0) { sm[w] = s; sm2[w] = ss; }
    __syncthreads();
    s = 0.f; ss = 0.f;
    #pragma unroll
    for (int i = 0; i < 8; i++) { s += sm[i]; ss += sm2[i]; }
    float mu   = s  * (1.0f / DMODEL);
    float var  = ss * (1.0f / DMODEL) - mu * mu;
    float rstd = rsqrtf(var + 1e-5f);
    float4 gv = *(const float4*)(g + c);
    float4 bv = *(const float4*)(be + c);
    float4 o;
    o.x = cvt_tf32((v.x - mu) * rstd * gv.x + bv.x);
    o.y = cvt_tf32((v.y - mu) * rstd * gv.y + bv.y);
    o.z = cvt_tf32((v.z - mu) * rstd * gv.z + bv.z);
    o.w = cvt_tf32((v.w - mu) * rstd * gv.w + bv.w);
    *(float4*)(y + (size_t)row * DMODEL + c) = o;
}

// ---------------------------------------------------------------------------
// tf32 mma.sync GEMM (NT): C[M,N] = A[M,K] @ B[N,K]^T
// (+bias)(+relu)(+res)(+roundC)(+scatter to [B,H,S,HD])
// CTA 128x128x32, 512 threads = 16 warps (4x4), warp tile 32x32.
// 3-stage cp.async pipeline, smem stride-36 conflict-free layout.
// Inputs must be pre-rounded tf32.
// ---------------------------------------------------------------------------
#define GBUF 4608                    // 128*36 floats per matrix per stage
#define STAGEB (2*GBUF)
#define GEMM_SMEM (3*STAGEB*4)       // 110592 bytes

__global__ __launch_bounds__(512, 1) void gemm_tf32_kernel(
    const float* __restrict__ A, const float* __restrict__ B,
    const float* __restrict__ bias, const float* __restrict__ res,
    float* __restrict__ C, int M, int N, int K,
    int relu, int scatter, int roundC)
{
    float* smem = (float*)dyn_smem;
    uint32_t sbase;
    asm("{ .reg .u64 t; cvta.to.shared.u64 t, %1; cvt.u32.u64 %0, t; }"
        : "=r"(sbase) : "l"((char*)dyn_smem));

    int tid  = threadIdx.x;
    int lane = tid & 31;
    int warp = tid >> 5;            // 0..15
    int g    = lane >> 2;
    int tig  = lane & 3;
    int wm   = warp >> 2;           // 0..3
    int wn   = warp & 3;            // 0..3
    int m0 = blockIdx.y * 128, n0 = blockIdx.x * 128;

    float c[2][4][4];
    #pragma unroll
    for (int i = 0; i < 2; i++)
        #pragma unroll
        for (int j = 0; j < 4; j++)
            #pragma unroll
            for (int f = 0; f < 4; f++) c[i][j][f] = 0.f;

    int srow = tid >> 3;            // 0..63
    int kseg = (tid & 7) * 4;       // 0..28

    const float* Ab = A + (size_t)m0 * K;
    const float* Bb = B + (size_t)n0 * K;
    int NIT = K >> 5;

    uint32_t stA[2], stB[2];
    #pragma unroll
    for (int t = 0; t < 2; t++) {
        int row = srow + t * 64;
        stA[t] = sbase + (uint32_t)(row * 36 + kseg) * 4;
        stB[t] = stA[t] + GBUF * 4;
    }

    // prologue: stages 0 and 1
    #pragma unroll
    for (int s = 0; s < 2; s++) {
        int k0 = s << 5;
        uint32_t so = (uint32_t)(s * STAGEB) * 4;
        #pragma unroll
        for (int t = 0; t < 2; t++) {
            int row = srow + t * 64;
            cp16(stA[t] + so, Ab + (size_t)row * K + k0 + kseg);
            cp16(stB[t] + so, Bb + (size_t)row * K + k0 + kseg);
        }
        asm volatile("cp.async.commit_group;");
    }

    int bufc = 0, bufn = 2;
    for (int kk = 0; kk < NIT; kk++) {
        asm volatile("cp.async.wait_group 1;");
        __syncthreads();

        if (kk + 2 < NIT) {
            int k0 = (kk + 2) << 5;
            uint32_t so = (uint32_t)(bufn * STAGEB) * 4;
            #pragma unroll
            for (int t = 0; t < 2; t++) {
                int row = srow + t * 64;
                cp16(stA[t] + so, Ab + (size_t)row * K + k0 + kseg);
                cp16(stB[t] + so, Bb + (size_t)row * K + k0 + kseg);
            }
        }
        asm volatile("cp.async.commit_group;");

        const float* Ac = smem + bufc * STAGEB;
        const float* Bc = Ac + GBUF;
        const float* Awp = Ac + (wm * 32 + g) * 36 + tig;
        const float* Bwp = Bc + (wn * 32 + g) * 36 + tig;

        #pragma unroll
        for (int ks = 0; ks < 4; ks++) {
            int k0 = ks * 8;
            uint32_t af[2][4], bf[4][2];
            #pragma unroll
            for (int mt = 0; mt < 2; mt++) {
                const float* p = Awp + mt * (16 * 36) + k0;
                af[mt][0] = __float_as_uint(p[0]);
                af[mt][1] = __float_as_uint(p[8 * 36]);
                af[mt][2] = __float_as_uint(p[4]);
                af[mt][3] = __float_as_uint(p[8 * 36 + 4]);
            }
            #pragma unroll
            for (int nt = 0; nt < 4; nt++) {
                const float* p = Bwp + nt * (8 * 36) + k0;
                bf[nt][0] = __float_as_uint(p[0]);
                bf[nt][1] = __float_as_uint(p[4]);
            }
            #pragma unroll
            for (int mt = 0; mt < 2; mt++)
                #pragma unroll
                for (int nt = 0; nt < 4; nt++)
                    mma_tf32(c[mt][nt][0], c[mt][nt][1], c[mt][nt][2], c[mt][nt][3],
                             af[mt][0], af[mt][1], af[mt][2], af[mt][3],
                             bf[nt][0], bf[nt][1]);
        }
        bufc = (bufc == 2) ? 0 : bufc + 1;
        bufn = (bufn == 2) ? 0 : bufn + 1;
    }

    // epilogue
    #pragma unroll
    for (int mt = 0; mt < 2; mt++) {
        int row0 = m0 + wm * 32 + mt * 16 + g;
        int row1 = row0 + 8;
        #pragma unroll
        for (int nt = 0; nt < 4; nt++) {
            int col = n0 + wn * 32 + nt * 8 + tig * 2;
            float v00 = c[mt][nt][0], v01 = c[mt][nt][1];
            float v10 = c[mt][nt][2], v11 = c[mt][nt][3];
            if (bias) {
                float b0v = bias[col], b1v = bias[col + 1];
                v00 += b0v; v01 += b1v; v10 += b0v; v11 += b1v;
            }
            if (relu) {
                v00 = fmaxf(v00, 0.f); v01 = fmaxf(v01, 0.f);
                v10 = fmaxf(v10, 0.f); v11 = fmaxf(v11, 0.f);
            }
            if (res) {
                v00 += res[(size_t)row0 * N + col];
                v01 += res[(size_t)row0 * N + col + 1];
                v10 += res[(size_t)row1 * N + col];
                v11 += res[(size_t)row1 * N + col + 1];
            }
            if (roundC) {
                v00 = cvt_tf32(v00); v01 = cvt_tf32(v01);
                v10 = cvt_tf32(v10); v11 = cvt_tf32(v11);
            }
            if (scatter) {
                int h_ = col >> 6, d_ = col & 63;
                {
                    int b_ = row0 >> 10, s_ = row0 & 1023;
                    float* p = C + (((size_t)(b_ * 16 + h_) << 10) + s_) * 64 + d_;
                    p[0] = v00; p[1] = v01;
                }
                {
                    int b_ = row1 >> 10, s_ = row1 & 1023;
                    float* p = C + (((size_t)(b_ * 16 + h_) << 10) + s_) * 64 + d_;
                    p[0] = v10; p[1] = v11;
                }
            } else {
                *(float2*)(C + (size_t)row0 * N + col) = make_float2(v00, v01);
                *(float2*)(C + (size_t)row1 * N + col) = make_float2(v10, v11);
            }
        }
    }
}

// ---------------------------------------------------------------------------
// Tensor-core flash attention (tf32 mma.sync), HD=64, Skv=1024.
// Q,K,V in [B,H,S,64] (pre-rounded tf32). 128 threads = 4 warps; each warp
// owns 16 q-rows of a 64-row q block. QK^T and PV via m16n8k8; P routed
// through per-warp smem (syncwarp only). Output [B,S,H*HD], tf32-rounded.
// ---------------------------------------------------------------------------
#define APITCH 68
#define ATTN_SMEM (4*64*APITCH*4)   // Qs,Ks,Vs,Ps = 69632 B

__global__ __launch_bounds__(128, 3) void attn_kernel(
    const float* __restrict__ Q, const float* __restrict__ K,
    const float* __restrict__ V, float* __restrict__ O, int causal)
{
    float* Qs = (float*)dyn_smem;          // [64][68] q rows
    float* Ks = Qs + 64*APITCH;            // [64][68] k rows
    float* Vs = Ks + 64*APITCH;            // [64][68] v rows
    float* Ps = Vs + 64*APITCH;            // [64][68] p rows (warp w: rows w*16..)

    int tid  = threadIdx.x;
    int lane = tid & 31;
    int w    = tid >> 5;        // 0..3
    int g    = lane >> 2;       // 0..7
    int tig  = lane & 3;        // 0..3
    int q0 = blockIdx.x * 64;
    int bh = blockIdx.y;

    const float* Qb = Q + ((size_t)bh * 1024 + q0) * 64;
    const float* Kb = K + (size_t)bh * 1024 * 64;
    const float* Vb = V + (size_t)bh * 1024 * 64;

    // load Q tile (64x64), row-major
    #pragma unroll
    for (int t = 0; t < 8; t++) {
        int lin = tid + t * 128;
        int r = lin >> 4, d0 = (lin & 15) << 2;
        *(float4*)&Qs[r*APITCH + d0] = *(const float4*)(Qb + r*64 + d0);
    }

    float o[8][4];
    float m[2], l[2];
    #pragma unroll
    for (int nt = 0; nt < 8; nt++)
        #pragma unroll
        for (int f = 0; f < 4; f++) o[nt][f] = 0.f;
    m[0] = m[1] = -1e30f; l[0] = l[1] = 0.f;

    int rg0 = q0 + w*16 + g;
    int rg1 = rg0 + 8;

    int ntiles = causal ? (blockIdx.x + 1) : 16;

    for (int t = 0; t < ntiles; t++) {
        int k0 = t * 64;
        __syncthreads();
        #pragma unroll
        for (int u = 0; u < 8; u++) {
            int lin = tid + u * 128;
            int r = lin >> 4, d0 = (lin & 15) << 2;
            *(float4*)&Ks[r*APITCH + d0] = *(const float4*)(Kb + (size_t)(k0+r)*64 + d0);
            *(float4*)&Vs[r*APITCH + d0] = *(const float4*)(Vb + (size_t)(k0+r)*64 + d0);
        }
        __syncthreads();

        // S = Q @ K^T  (warp: 16 rows x 64 cols = 8 n-tiles)
        float s[8][4];
        #pragma unroll
        for (int nt = 0; nt < 8; nt++)
            #pragma unroll
            for (int f = 0; f < 4; f++) s[nt][f] = 0.f;

        const float* Qw = Qs + (w*16 + g)*APITCH + tig;
        #pragma unroll
        for (int dc = 0; dc < 8; dc++) {
            int d0 = dc * 8;
            uint32_t a0 = __float_as_uint(Qw[d0]);
            uint32_t a1 = __float_as_uint(Qw[8*APITCH + d0]);
            uint32_t a2 = __float_as_uint(Qw[d0 + 4]);
            uint32_t a3 = __float_as_uint(Qw[8*APITCH + d0 + 4]);
            #pragma unroll
            for (int nt = 0; nt < 8; nt++) {
                const float* bp = Ks + (nt*8 + g)*APITCH + d0 + tig;
                uint32_t b0 = __float_as_uint(bp[0]);
                uint32_t b1 = __float_as_uint(bp[4]);
                mma_tf32(s[nt][0], s[nt][1], s[nt][2], s[nt][3],
                         a0, a1, a2, a3, b0, b1);
            }
        }

        // scale + causal mask
        #pragma unroll
        for (int nt = 0; nt < 8; nt++) {
            int cg = k0 + nt*8 + tig*2;
            s[nt][0] *= 0.125f; s[nt][1] *= 0.125f;
            s[nt][2] *= 0.125f; s[nt][3] *= 0.125f;
            if (causal) {
                if (cg     > rg0) s[nt][0] = -1e30f;
                if (cg + 1 > rg0) s[nt][1] = -1e30f;
                if (cg     > rg1) s[nt][2] = -1e30f;
                if (cg + 1 > rg1) s[nt][3] = -1e30f;
            }
        }

        // online softmax: row rg0 -> s[nt][0..1], row rg1 -> s[nt][2..3]
        float mx0 = -1e30f, mx1 = -1e30f;
        #pragma unroll
        for (int nt = 0; nt < 8; nt++) {
            mx0 = fmaxf(mx0, fmaxf(s[nt][0], s[nt][1]));
            mx1 = fmaxf(mx1, fmaxf(s[nt][2], s[nt][3]));
        }
        mx0 = fmaxf(mx0, __shfl_xor_sync(0xffffffffu, mx0, 1));
        mx0 = fmaxf(mx0, __shfl_xor_sync(0xffffffffu, mx0, 2));
        mx1 = fmaxf(mx1, __shfl_xor_sync(0xffffffffu, mx1, 1));
        mx1 = fmaxf(mx1, __shfl_xor_sync(0xffffffffu, mx1, 2));

        float mn0 = fmaxf(m[0], mx0), mn1 = fmaxf(m[1], mx1);
        float sc0 = __expf(m[0] - mn0), sc1 = __expf(m[1] - mn1);
        float ls0 = 0.f, ls1 = 0.f;
        #pragma unroll
        for (int nt = 0; nt < 8; nt++) {
            float p0 = cvt_tf32(__expf(s[nt][0] - mn0));
            float p1 = cvt_tf32(__expf(s[nt][1] - mn0));
            float p2 = cvt_tf32(__expf(s[nt][2] - mn1));
            float p3 = cvt_tf32(__expf(s[nt][3] - mn1));
            s[nt][0] = p0; s[nt][1] = p1; s[nt][2] = p2; s[nt][3] = p3;
            ls0 += p0 + p1; ls1 += p2 + p3;
        }
        ls0 += __shfl_xor_sync(0xffffffffu, ls0, 1);
        ls0 += __shfl_xor_sync(0xffffffffu, ls0, 2);
        ls1 += __shfl_xor_sync(0xffffffffu, ls1, 1);
        ls1 += __shfl_xor_sync(0xffffffffu, ls1, 2);
        l[0] = l[0] * sc0 + ls0; m[0] = mn0;
        l[1] = l[1] * sc1 + ls1; m[1] = mn1;
        #pragma unroll
        for (int nt = 0; nt < 8; nt++) {
            o[nt][0] *= sc0; o[nt][1] *= sc0;
            o[nt][2] *= sc1; o[nt][3] *= sc1;
        }

        // store P (warp-private region)
        float* Pw = Ps + (w*16)*APITCH;
        #pragma unroll
        for (int nt = 0; nt < 8; nt++) {
            int cc = nt*8 + tig*2;
            Pw[g*APITCH + cc]         = s[nt][0];
            Pw[g*APITCH + cc + 1]     = s[nt][1];
            Pw[(g+8)*APITCH + cc]     = s[nt][2];
            Pw[(g+8)*APITCH + cc + 1] = s[nt][3];
        }
        __syncwarp();

        // O += P @ V  (A = P m16k8 chunks, B = V^T)
        const float* Pr = Ps + (w*16 + g)*APITCH + tig;
        #pragma unroll
        for (int cc = 0; cc < 8; cc++) {
            int c0 = cc * 8;
            uint32_t a0 = __float_as_uint(Pr[c0]);
            uint32_t a1 = __float_as_uint(Pr[8*APITCH + c0]);
            uint32_t a2 = __float_as_uint(Pr[c0 + 4]);
            uint32_t a3 = __float_as_uint(Pr[8*APITCH + c0 + 4]);
            #pragma unroll
            for (int nt = 0; nt < 8; nt++) {
                const float* bp = Vs + (c0 + tig)*APITCH + nt*8 + g;
                uint32_t b0 = __float_as_uint(bp[0]);
                uint32_t b1 = __float_as_uint(bp[4*APITCH]);
                mma_tf32(o[nt][0], o[nt][1], o[nt][2], o[nt][3],
                         a0, a1, a2, a3, b0, b1);
            }
        }
    }

    // write output in [B, S, H*HD] layout, tf32-rounded
    float inv0 = 1.0f / l[0], inv1 = 1.0f / l[1];
    int b_ = bh >> 4, h_ = bh & 15;
    float* Ob = O + ((size_t)b_ << 20) + h_ * 64;
    #pragma unroll
    for (int nt = 0; nt < 8; nt++) {
        int d = nt*8 + tig*2;
        float2 v0 = make_float2(cvt_tf32(o[nt][0]*inv0), cvt_tf32(o[nt][1]*inv0));
        float2 v1 = make_float2(cvt_tf32(o[nt][2]*inv1), cvt_tf32(o[nt][3]*inv1));
        *(float2*)(Ob + (size_t)rg0 * 1024 + d) = v0;
        *(float2*)(Ob + (size_t)rg1 * 1024 + d) = v1;
    }
}

// ---------------------------------------------------------------------------
// Host launch
// ---------------------------------------------------------------------------
extern "C" void kernel_launch(void* const* d_in, const int* in_sizes, int n_in,
                              void* d_out, int out_size)
{
    (void)in_sizes; (void)n_in; (void)out_size;
    const float* tgt       = (const float*)d_in[0];
    const float* memory    = (const float*)d_in[1];
    const float* Wq        = (const float*)d_in[2];
    const float* Wk        = (const float*)d_in[3];
    const float* Wv        = (const float*)d_in[4];
    const float* Wo        = (const float*)d_in[5];
    const float* mha_in_w  = (const float*)d_in[6];
    const float* mha_in_b  = (const float*)d_in[7];
    const float* mha_out_w = (const float*)d_in[8];
    const float* mha_out_b = (const float*)d_in[9];
    const float* W1        = (const float*)d_in[10];
    const float* b1        = (const float*)d_in[11];
    const float* W2        = (const float*)d_in[12];
    const float* b2        = (const float*)d_in[13];
    const float* g1        = (const float*)d_in[14];
    const float* be1       = (const float*)d_in[15];
    const float* g2        = (const float*)d_in[16];
    const float* be2       = (const float*)d_in[17];
    const float* g3        = (const float*)d_in[18];
    const float* be3       = (const float*)d_in[19];

    float* xout = (float*)d_out;
    float* kout = xout + (size_t)NELEM;
    float* vout = kout + (size_t)NELEM;

    float *ln, *q, *k2, *v2, *o, *x1, *x2, *h1, *rw;
    cudaGetSymbolAddress((void**)&ln, g_ln);
    cudaGetSymbolAddress((void**)&q,  g_q);
    cudaGetSymbolAddress((void**)&k2, g_k2);
    cudaGetSymbolAddress((void**)&v2, g_v2);
    cudaGetSymbolAddress((void**)&o,  g_o);
    cudaGetSymbolAddress((void**)&x1, g_x1);
    cudaGetSymbolAddress((void**)&x2, g_x2);
    cudaGetSymbolAddress((void**)&h1, g_h1);
    cudaGetSymbolAddress((void**)&rw, g_rw);

    cudaFuncSetAttribute(attn_kernel,
        cudaFuncAttributeMaxDynamicSharedMemorySize, ATTN_SMEM);
    cudaFuncSetAttribute(gemm_tf32_kernel,
        cudaFuncAttributeMaxDynamicSharedMemorySize, GEMM_SMEM);

    dim3 gProj(DMODEL/128, TOK/128);      // (8, 32)
    dim3 gFF1 (DFF_/128,  TOK/128);       // (32, 32)
    dim3 gAttn(16, 64);                   // 64-row q blocks x (B*H)

    round_all_kernel<<<20480, 256>>>(Wq, Wk, Wv, Wo, mha_in_w, mha_out_w,
                                     W1, W2, memory, rw);

    // ---- self-attention ----
    ln_kernel<<<TOK, 256>>>(tgt, g1, be1, ln);
    gemm_tf32_kernel<<<gProj, 512, GEMM_SMEM>>>(ln, rw+RW_WQ, nullptr, nullptr, q,    TOK, DMODEL, DMODEL, 0, 1, 1);
    gemm_tf32_kernel<<<gProj, 512, GEMM_SMEM>>>(ln, rw+RW_WK, nullptr, nullptr, kout, TOK, DMODEL, DMODEL, 0, 1, 1);
    gemm_tf32_kernel<<<gProj, 512, GEMM_SMEM>>>(ln, rw+RW_WV, nullptr, nullptr, vout, TOK, DMODEL, DMODEL, 0, 1, 1);
    attn_kernel<<<gAttn, 128, ATTN_SMEM>>>(q, kout, vout, o, 1);
    gemm_tf32_kernel<<<gProj, 512, GEMM_SMEM>>>(o, rw+RW_WO, nullptr, tgt, x1, TOK, DMODEL, DMODEL, 0, 0, 0);

    // ---- cross-attention ----
    ln_kernel<<<TOK, 256>>>(x1, g2, be2, ln);
    gemm_tf32_kernel<<<gProj, 512, GEMM_SMEM>>>(ln,        rw+RW_INW,         mha_in_b,        nullptr, q,  TOK, DMODEL, DMODEL, 0, 1, 1);
    gemm_tf32_kernel<<<gProj, 512, GEMM_SMEM>>>(rw+RW_MEM, rw+RW_INW+1048576, mha_in_b + 1024, nullptr, k2, TOK, DMODEL, DMODEL, 0, 1, 1);
    gemm_tf32_kernel<<<gProj, 512, GEMM_SMEM>>>(rw+RW_MEM, rw+RW_INW+2097152, mha_in_b + 2048, nullptr, v2, TOK, DMODEL, DMODEL, 0, 1, 1);
    attn_kernel<<<gAttn, 128, ATTN_SMEM>>>(q, k2, v2, o, 0);
    gemm_tf32_kernel<<<gProj, 512, GEMM_SMEM>>>(o, rw+RW_OUTW, mha_out_b, x1, x2, TOK, DMODEL, DMODEL, 0, 0, 0);

    // ---- FFN ----
    ln_kernel<<<TOK, 256>>>(x2, g3, be3, ln);
    gemm_tf32_kernel<<<gFF1,  512, GEMM_SMEM>>>(ln, rw+RW_W1, b1, nullptr, h1,   TOK, DFF_,   DMODEL, 1, 0, 1);
    gemm_tf32_kernel<<<gProj, 512, GEMM_SMEM>>>(h1, rw+RW_W2, b2, x2,      xout, TOK, DMODEL, DFF_,   0, 0, 0);
}

// round 7
// speedup vs baseline: 3.5022x; 1.1148x over previous
#include <cuda_runtime.h>
#include <cuda_bf16.h>
#include <math.h>
#include <stdint.h>

// ---------------------------------------------------------------------------
// B=4, S=SM=1024, D=1024, H=16, HD=64, DFF=4096
// Outputs: x[B,S,D], sa_k[B,H,S,HD], sa_v[B,H,S,HD] concatenated in d_out.
// ---------------------------------------------------------------------------

#define TOK    4096
#define DMODEL 1024
#define DFF_   4096
#define NELEM  4194304

__device__ float g_ln[NELEM];
__device__ float g_q [NELEM];
__device__ float g_k2[NELEM];
__device__ float g_v2[NELEM];
__device__ float g_o [NELEM];
__device__ float g_x1[NELEM];
__device__ float g_x2[NELEM];
__device__ float g_h1[16777216];    // 4096 x 4096
__device__ float g_rw[20971520];    // tf32-rounded weights + memory

#define RW_WQ   0
#define RW_WK   1048576
#define RW_WV   2097152
#define RW_WO   3145728
#define RW_INW  4194304
#define RW_OUTW 7340032
#define RW_W1   8388608
#define RW_W2   12582912
#define RW_MEM  16777216

// single dynamic-smem declaration for the whole TU
extern __shared__ char dyn_smem[];

__device__ __forceinline__ float cvt_tf32(float x) {
    uint32_t u;
    asm("cvt.rna.tf32.f32 %0, %1;" : "=r"(u) : "f"(x));
    return __uint_as_float(u);
}

__device__ __forceinline__ void mma_tf32(
    float& c0, float& c1, float& c2, float& c3,
    uint32_t a0, uint32_t a1, uint32_t a2, uint32_t a3,
    uint32_t b0, uint32_t b1)
{
    asm volatile(
        "mma.sync.aligned.m16n8k8.row.col.f32.tf32.tf32.f32 "
        "{%0,%1,%2,%3}, {%4,%5,%6,%7}, {%8,%9}, {%0,%1,%2,%3};"
        : "+f"(c0), "+f"(c1), "+f"(c2), "+f"(c3)
        : "r"(a0), "r"(a1), "r"(a2), "r"(a3), "r"(b0), "r"(b1));
}

__device__ __forceinline__ void cp16(uint32_t dst, const float* src) {
    asm volatile("cp.async.cg.shared.global [%0], [%1], 16;"
                 :: "r"(dst), "l"(src));
}

// ---------------------------------------------------------------------------
// Round weights + memory to tf32 (rna) into g_rw.
// ---------------------------------------------------------------------------
__global__ __launch_bounds__(256) void round_all_kernel(
    const float* __restrict__ wq, const float* __restrict__ wk,
    const float* __restrict__ wv, const float* __restrict__ wo,
    const float* __restrict__ inw, const float* __restrict__ outw,
    const float* __restrict__ w1, const float* __restrict__ w2,
    const float* __restrict__ mem, float* __restrict__ dst)
{
    int i = blockIdx.x * 256 + threadIdx.x;
    const float* src;
    int base;
    if      (i < 262144)  { src = wq;   base = 0; }
    else if (i < 524288)  { src = wk;   base = 262144; }
    else if (i < 786432)  { src = wv;   base = 524288; }
    else if (i < 1048576) { src = wo;   base = 786432; }
    else if (i < 1835008) { src = inw;  base = 1048576; }
    else if (i < 2097152) { src = outw; base = 1835008; }
    else if (i < 3145728) { src = w1;   base = 2097152; }
    else if (i < 4194304) { src = w2;   base = 3145728; }
    else                  { src = mem;  base = 4194304; }
    float4 v = ((const float4*)src)[i - base];
    v.x = cvt_tf32(v.x); v.y = cvt_tf32(v.y);
    v.z = cvt_tf32(v.z); v.w = cvt_tf32(v.w);
    ((float4*)dst)[i] = v;
}

// ---------------------------------------------------------------------------
// LayerNorm (tf32-rounded output)
// ---------------------------------------------------------------------------
__global__ __launch_bounds__(256) void ln_kernel(
    const float* __restrict__ x, const float* __restrict__ g,
    const float* __restrict__ be, float* __restrict__ y)
{
    int row = blockIdx.x;
    const float* xr = x + (size_t)row * DMODEL;
    int c = threadIdx.x * 4;
    float4 v = *(const float4*)(xr + c);
    float s  = v.x + v.y + v.z + v.w;
    float ss = v.x*v.x + v.y*v.y + v.z*v.z + v.w*v.w;
    #pragma unroll
    for (int o = 16; o > 0; o >>= 1) {
        s  += __shfl_xor_sync(0xffffffffu, s,  o);
        ss += __shfl_xor_sync(0xffffffffu, ss, o);
    }
    __shared__ float sm[8], sm2[8];
    int w = threadIdx.x >> 5, lane = threadIdx.x & 31;
    if (lane == 0) { sm[w] = s; sm2[w] = ss; }
    __syncthreads();
    s = 0.f; ss = 0.f;
    #pragma unroll
    for (int i = 0; i < 8; i++) { s += sm[i]; ss += sm2[i]; }
    float mu   = s  * (1.0f / DMODEL);
    float var  = ss * (1.0f / DMODEL) - mu * mu;
    float rstd = rsqrtf(var + 1e-5f);
    float4 gv = *(const float4*)(g + c);
    float4 bv = *(const float4*)(be + c);
    float4 o;
    o.x = cvt_tf32((v.x - mu) * rstd * gv.x + bv.x);
    o.y = cvt_tf32((v.y - mu) * rstd * gv.y + bv.y);
    o.z = cvt_tf32((v.z - mu) * rstd * gv.z + bv.z);
    o.w = cvt_tf32((v.w - mu) * rstd * gv.w + bv.w);
    *(float4*)(y + (size_t)row * DMODEL + c) = o;
}

// ---------------------------------------------------------------------------
// tf32 mma.sync GEMM (NT): C[M,N] = A[M,K] @ B[N,K]^T
// (+bias)(+relu)(+res)(+roundC)(+scatter to [B,H,S,HD])
// CTA 128x128x32, 256 threads = 8 warps (2x4), warp tile 64x32.
// 3-stage cp.async; 2 CTAs/SM (launch_bounds(256,2), smem 108KB x2 = 216KB).
// Inputs must be pre-rounded tf32.
// ---------------------------------------------------------------------------
#define GBUF 4608                    // 128*36 floats per matrix per stage
#define STAGEB (2*GBUF)
#define GEMM_SMEM (3*STAGEB*4)       // 110592 bytes

__global__ __launch_bounds__(256, 2) void gemm_tf32_kernel(
    const float* __restrict__ A, const float* __restrict__ B,
    const float* __restrict__ bias, const float* __restrict__ res,
    float* __restrict__ C, int M, int N, int K,
    int relu, int scatter, int roundC)
{
    float* smem = (float*)dyn_smem;
    uint32_t sbase;
    asm("{ .reg .u64 t; cvta.to.shared.u64 t, %1; cvt.u32.u64 %0, t; }"
        : "=r"(sbase) : "l"((char*)dyn_smem));

    int tid  = threadIdx.x;
    int lane = tid & 31;
    int warp = tid >> 5;            // 0..7
    int g    = lane >> 2;
    int tig  = lane & 3;
    int wm   = warp >> 2;           // 0..1
    int wn   = warp & 3;            // 0..3
    int m0 = blockIdx.y * 128, n0 = blockIdx.x * 128;

    float c[4][4][4];
    #pragma unroll
    for (int i = 0; i < 4; i++)
        #pragma unroll
        for (int j = 0; j < 4; j++)
            #pragma unroll
            for (int f = 0; f < 4; f++) c[i][j][f] = 0.f;

    int srow = tid >> 3;            // 0..31
    int kseg = (tid & 7) * 4;       // 0..28

    const float* Ab = A + (size_t)m0 * K;
    const float* Bb = B + (size_t)n0 * K;
    int NIT = K >> 5;

    uint32_t stA[4], stB[4];
    #pragma unroll
    for (int t = 0; t < 4; t++) {
        int row = srow + t * 32;
        stA[t] = sbase + (uint32_t)(row * 36 + kseg) * 4;
        stB[t] = stA[t] + GBUF * 4;
    }

    // prologue: stages 0 and 1
    #pragma unroll
    for (int s = 0; s < 2; s++) {
        int k0 = s << 5;
        uint32_t so = (uint32_t)(s * STAGEB) * 4;
        #pragma unroll
        for (int t = 0; t < 4; t++) {
            int row = srow + t * 32;
            cp16(stA[t] + so, Ab + (size_t)row * K + k0 + kseg);
            cp16(stB[t] + so, Bb + (size_t)row * K + k0 + kseg);
        }
        asm volatile("cp.async.commit_group;");
    }

    int bufc = 0, bufn = 2;
    for (int kk = 0; kk < NIT; kk++) {
        asm volatile("cp.async.wait_group 1;");
        __syncthreads();

        if (kk + 2 < NIT) {
            int k0 = (kk + 2) << 5;
            uint32_t so = (uint32_t)(bufn * STAGEB) * 4;
            #pragma unroll
            for (int t = 0; t < 4; t++) {
                int row = srow + t * 32;
                cp16(stA[t] + so, Ab + (size_t)row * K + k0 + kseg);
                cp16(stB[t] + so, Bb + (size_t)row * K + k0 + kseg);
            }
        }
        asm volatile("cp.async.commit_group;");

        const float* Ac = smem + bufc * STAGEB;
        const float* Bc = Ac + GBUF;
        const float* Awp = Ac + (wm * 64 + g) * 36 + tig;
        const float* Bwp = Bc + (wn * 32 + g) * 36 + tig;

        #pragma unroll
        for (int ks = 0; ks < 4; ks++) {
            int k0 = ks * 8;
            uint32_t af[4][4], bf[4][2];
            #pragma unroll
            for (int mt = 0; mt < 4; mt++) {
                const float* p = Awp + mt * (16 * 36) + k0;
                af[mt][0] = __float_as_uint(p[0]);
                af[mt][2] = __float_as_uint(p[4]);
                af[mt][1] = __float_as_uint(p[8 * 36]);
                af[mt][3] = __float_as_uint(p[8 * 36 + 4]);
            }
            #pragma unroll
            for (int nt = 0; nt < 4; nt++) {
                const float* p = Bwp + nt * (8 * 36) + k0;
                bf[nt][0] = __float_as_uint(p[0]);
                bf[nt][1] = __float_as_uint(p[4]);
            }
            #pragma unroll
            for (int mt = 0; mt < 4; mt++)
                #pragma unroll
                for (int nt = 0; nt < 4; nt++)
                    mma_tf32(c[mt][nt][0], c[mt][nt][1], c[mt][nt][2], c[mt][nt][3],
                             af[mt][0], af[mt][1], af[mt][2], af[mt][3],
                             bf[nt][0], bf[nt][1]);
        }
        bufc = (bufc == 2) ? 0 : bufc + 1;
        bufn = (bufn == 2) ? 0 : bufn + 1;
    }

    // epilogue
    #pragma unroll
    for (int mt = 0; mt < 4; mt++) {
        int row0 = m0 + wm * 64 + mt * 16 + g;
        int row1 = row0 + 8;
        #pragma unroll
        for (int nt = 0; nt < 4; nt++) {
            int col = n0 + wn * 32 + nt * 8 + tig * 2;
            float v00 = c[mt][nt][0], v01 = c[mt][nt][1];
            float v10 = c[mt][nt][2], v11 = c[mt][nt][3];
            if (bias) {
                float b0v = bias[col], b1v = bias[col + 1];
                v00 += b0v; v01 += b1v; v10 += b0v; v11 += b1v;
            }
            if (relu) {
                v00 = fmaxf(v00, 0.f); v01 = fmaxf(v01, 0.f);
                v10 = fmaxf(v10, 0.f); v11 = fmaxf(v11, 0.f);
            }
            if (res) {
                v00 += res[(size_t)row0 * N + col];
                v01 += res[(size_t)row0 * N + col + 1];
                v10 += res[(size_t)row1 * N + col];
                v11 += res[(size_t)row1 * N + col + 1];
            }
            if (roundC) {
                v00 = cvt_tf32(v00); v01 = cvt_tf32(v01);
                v10 = cvt_tf32(v10); v11 = cvt_tf32(v11);
            }
            if (scatter) {
                int h_ = col >> 6, d_ = col & 63;
                {
                    int b_ = row0 >> 10, s_ = row0 & 1023;
                    float* p = C + (((size_t)(b_ * 16 + h_) << 10) + s_) * 64 + d_;
                    p[0] = v00; p[1] = v01;
                }
                {
                    int b_ = row1 >> 10, s_ = row1 & 1023;
                    float* p = C + (((size_t)(b_ * 16 + h_) << 10) + s_) * 64 + d_;
                    p[0] = v10; p[1] = v11;
                }
            } else {
                *(float2*)(C + (size_t)row0 * N + col) = make_float2(v00, v01);
                *(float2*)(C + (size_t)row1 * N + col) = make_float2(v10, v11);
            }
        }
    }
}

// ---------------------------------------------------------------------------
// Tensor-core flash attention (tf32 mma.sync), HD=64, Skv=1024.
// Q,K,V in [B,H,S,64] (pre-rounded tf32). 128 threads = 4 warps; each warp
// owns 16 q-rows of a 64-row q block. QK^T and PV via m16n8k8; P routed
// through per-warp smem (syncwarp only). Output [B,S,H*HD], tf32-rounded.
// ---------------------------------------------------------------------------
#define APITCH 68
#define ATTN_SMEM (4*64*APITCH*4)   // Qs,Ks,Vs,Ps = 69632 B

__global__ __launch_bounds__(128, 3) void attn_kernel(
    const float* __restrict__ Q, const float* __restrict__ K,
    const float* __restrict__ V, float* __restrict__ O, int causal)
{
    float* Qs = (float*)dyn_smem;          // [64][68] q rows
    float* Ks = Qs + 64*APITCH;            // [64][68] k rows
    float* Vs = Ks + 64*APITCH;            // [64][68] v rows
    float* Ps = Vs + 64*APITCH;            // [64][68] p rows (warp w: rows w*16..)

    int tid  = threadIdx.x;
    int lane = tid & 31;
    int w    = tid >> 5;        // 0..3
    int g    = lane >> 2;       // 0..7
    int tig  = lane & 3;        // 0..3
    int q0 = blockIdx.x * 64;
    int bh = blockIdx.y;

    const float* Qb = Q + ((size_t)bh * 1024 + q0) * 64;
    const float* Kb = K + (size_t)bh * 1024 * 64;
    const float* Vb = V + (size_t)bh * 1024 * 64;

    // load Q tile (64x64), row-major
    #pragma unroll
    for (int t = 0; t < 8; t++) {
        int lin = tid + t * 128;
        int r = lin >> 4, d0 = (lin & 15) << 2;
        *(float4*)&Qs[r*APITCH + d0] = *(const float4*)(Qb + r*64 + d0);
    }

    float o[8][4];
    float m[2], l[2];
    #pragma unroll
    for (int nt = 0; nt < 8; nt++)
        #pragma unroll
        for (int f = 0; f < 4; f++) o[nt][f] = 0.f;
    m[0] = m[1] = -1e30f; l[0] = l[1] = 0.f;

    int rg0 = q0 + w*16 + g;
    int rg1 = rg0 + 8;

    int ntiles = causal ? (blockIdx.x + 1) : 16;

    for (int t = 0; t < ntiles; t++) {
        int k0 = t * 64;
        __syncthreads();
        #pragma unroll
        for (int u = 0; u < 8; u++) {
            int lin = tid + u * 128;
            int r = lin >> 4, d0 = (lin & 15) << 2;
            *(float4*)&Ks[r*APITCH + d0] = *(const float4*)(Kb + (size_t)(k0+r)*64 + d0);
            *(float4*)&Vs[r*APITCH + d0] = *(const float4*)(Vb + (size_t)(k0+r)*64 + d0);
        }
        __syncthreads();

        // S = Q @ K^T  (warp: 16 rows x 64 cols = 8 n-tiles)
        float s[8][4];
        #pragma unroll
        for (int nt = 0; nt < 8; nt++)
            #pragma unroll
            for (int f = 0; f < 4; f++) s[nt][f] = 0.f;

        const float* Qw = Qs + (w*16 + g)*APITCH + tig;
        #pragma unroll
        for (int dc = 0; dc < 8; dc++) {
            int d0 = dc * 8;
            uint32_t a0 = __float_as_uint(Qw[d0]);
            uint32_t a1 = __float_as_uint(Qw[8*APITCH + d0]);
            uint32_t a2 = __float_as_uint(Qw[d0 + 4]);
            uint32_t a3 = __float_as_uint(Qw[8*APITCH + d0 + 4]);
            #pragma unroll
            for (int nt = 0; nt < 8; nt++) {
                const float* bp = Ks + (nt*8 + g)*APITCH + d0 + tig;
                uint32_t b0 = __float_as_uint(bp[0]);
                uint32_t b1 = __float_as_uint(bp[4]);
                mma_tf32(s[nt][0], s[nt][1], s[nt][2], s[nt][3],
                         a0, a1, a2, a3, b0, b1);
            }
        }

        // scale + causal mask
        #pragma unroll
        for (int nt = 0; nt < 8; nt++) {
            int cg = k0 + nt*8 + tig*2;
            s[nt][0] *= 0.125f; s[nt][1] *= 0.125f;
            s[nt][2] *= 0.125f; s[nt][3] *= 0.125f;
            if (causal) {
                if (cg     > rg0) s[nt][0] = -1e30f;
                if (cg + 1 > rg0) s[nt][1] = -1e30f;
                if (cg     > rg1) s[nt][2] = -1e30f;
                if (cg + 1 > rg1) s[nt][3] = -1e30f;
            }
        }

        // online softmax: row rg0 -> s[nt][0..1], row rg1 -> s[nt][2..3]
        float mx0 = -1e30f, mx1 = -1e30f;
        #pragma unroll
        for (int nt = 0; nt < 8; nt++) {
            mx0 = fmaxf(mx0, fmaxf(s[nt][0], s[nt][1]));
            mx1 = fmaxf(mx1, fmaxf(s[nt][2], s[nt][3]));
        }
        mx0 = fmaxf(mx0, __shfl_xor_sync(0xffffffffu, mx0, 1));
        mx0 = fmaxf(mx0, __shfl_xor_sync(0xffffffffu, mx0, 2));
        mx1 = fmaxf(mx1, __shfl_xor_sync(0xffffffffu, mx1, 1));
        mx1 = fmaxf(mx1, __shfl_xor_sync(0xffffffffu, mx1, 2));

        float mn0 = fmaxf(m[0], mx0), mn1 = fmaxf(m[1], mx1);
        float sc0 = __expf(m[0] - mn0), sc1 = __expf(m[1] - mn1);
        float ls0 = 0.f, ls1 = 0.f;
        #pragma unroll
        for (int nt = 0; nt < 8; nt++) {
            float p0 = cvt_tf32(__expf(s[nt][0] - mn0));
            float p1 = cvt_tf32(__expf(s[nt][1] - mn0));
            float p2 = cvt_tf32(__expf(s[nt][2] - mn1));
            float p3 = cvt_tf32(__expf(s[nt][3] - mn1));
            s[nt][0] = p0; s[nt][1] = p1; s[nt][2] = p2; s[nt][3] = p3;
            ls0 += p0 + p1; ls1 += p2 + p3;
        }
        ls0 += __shfl_xor_sync(0xffffffffu, ls0, 1);
        ls0 += __shfl_xor_sync(0xffffffffu, ls0, 2);
        ls1 += __shfl_xor_sync(0xffffffffu, ls1, 1);
        ls1 += __shfl_xor_sync(0xffffffffu, ls1, 2);
        l[0] = l[0] * sc0 + ls0; m[0] = mn0;
        l[1] = l[1] * sc1 + ls1; m[1] = mn1;
        #pragma unroll
        for (int nt = 0; nt < 8; nt++) {
            o[nt][0] *= sc0; o[nt][1] *= sc0;
            o[nt][2] *= sc1; o[nt][3] *= sc1;
        }

        // store P (warp-private region)
        float* Pw = Ps + (w*16)*APITCH;
        #pragma unroll
        for (int nt = 0; nt < 8; nt++) {
            int cc = nt*8 + tig*2;
            Pw[g*APITCH + cc]         = s[nt][0];
            Pw[g*APITCH + cc + 1]     = s[nt][1];
            Pw[(g+8)*APITCH + cc]     = s[nt][2];
            Pw[(g+8)*APITCH + cc + 1] = s[nt][3];
        }
        __syncwarp();

        // O += P @ V  (A = P m16k8 chunks, B = V^T)
        const float* Pr = Ps + (w*16 + g)*APITCH + tig;
        #pragma unroll
        for (int cc = 0; cc < 8; cc++) {
            int c0 = cc * 8;
            uint32_t a0 = __float_as_uint(Pr[c0]);
            uint32_t a1 = __float_as_uint(Pr[8*APITCH + c0]);
            uint32_t a2 = __float_as_uint(Pr[c0 + 4]);
            uint32_t a3 = __float_as_uint(Pr[8*APITCH + c0 + 4]);
            #pragma unroll
            for (int nt = 0; nt < 8; nt++) {
                const float* bp = Vs + (c0 + tig)*APITCH + nt*8 + g;
                uint32_t b0 = __float_as_uint(bp[0]);
                uint32_t b1 = __float_as_uint(bp[4*APITCH]);
                mma_tf32(o[nt][0], o[nt][1], o[nt][2], o[nt][3],
                         a0, a1, a2, a3, b0, b1);
            }
        }
    }

    // write output in [B, S, H*HD] layout, tf32-rounded
    float inv0 = 1.0f / l[0], inv1 = 1.0f / l[1];
    int b_ = bh >> 4, h_ = bh & 15;
    float* Ob = O + ((size_t)b_ << 20) + h_ * 64;
    #pragma unroll
    for (int nt = 0; nt < 8; nt++) {
        int d = nt*8 + tig*2;
        float2 v0 = make_float2(cvt_tf32(o[nt][0]*inv0), cvt_tf32(o[nt][1]*inv0));
        float2 v1 = make_float2(cvt_tf32(o[nt][2]*inv1), cvt_tf32(o[nt][3]*inv1));
        *(float2*)(Ob + (size_t)rg0 * 1024 + d) = v0;
        *(float2*)(Ob + (size_t)rg1 * 1024 + d) = v1;
    }
}

// ---------------------------------------------------------------------------
// Host launch
// ---------------------------------------------------------------------------
extern "C" void kernel_launch(void* const* d_in, const int* in_sizes, int n_in,
                              void* d_out, int out_size)
{
    (void)in_sizes; (void)n_in; (void)out_size;
    const float* tgt       = (const float*)d_in[0];
    const float* memory    = (const float*)d_in[1];
    const float* Wq        = (const float*)d_in[2];
    const float* Wk        = (const float*)d_in[3];
    const float* Wv        = (const float*)d_in[4];
    const float* Wo        = (const float*)d_in[5];
    const float* mha_in_w  = (const float*)d_in[6];
    const float* mha_in_b  = (const float*)d_in[7];
    const float* mha_out_w = (const float*)d_in[8];
    const float* mha_out_b = (const float*)d_in[9];
    const float* W1        = (const float*)d_in[10];
    const float* b1        = (const float*)d_in[11];
    const float* W2        = (const float*)d_in[12];
    const float* b2        = (const float*)d_in[13];
    const float* g1        = (const float*)d_in[14];
    const float* be1       = (const float*)d_in[15];
    const float* g2        = (const float*)d_in[16];
    const float* be2       = (const float*)d_in[17];
    const float* g3        = (const float*)d_in[18];
    const float* be3       = (const float*)d_in[19];

    float* xout = (float*)d_out;
    float* kout = xout + (size_t)NELEM;
    float* vout = kout + (size_t)NELEM;

    float *ln, *q, *k2, *v2, *o, *x1, *x2, *h1, *rw;
    cudaGetSymbolAddress((void**)&ln, g_ln);
    cudaGetSymbolAddress((void**)&q,  g_q);
    cudaGetSymbolAddress((void**)&k2, g_k2);
    cudaGetSymbolAddress((void**)&v2, g_v2);
    cudaGetSymbolAddress((void**)&o,  g_o);
    cudaGetSymbolAddress((void**)&x1, g_x1);
    cudaGetSymbolAddress((void**)&x2, g_x2);
    cudaGetSymbolAddress((void**)&h1, g_h1);
    cudaGetSymbolAddress((void**)&rw, g_rw);

    cudaFuncSetAttribute(attn_kernel,
        cudaFuncAttributeMaxDynamicSharedMemorySize, ATTN_SMEM);
    cudaFuncSetAttribute(gemm_tf32_kernel,
        cudaFuncAttributeMaxDynamicSharedMemorySize, GEMM_SMEM);

    dim3 gProj(DMODEL/128, TOK/128);      // (8, 32)
    dim3 gFF1 (DFF_/128,  TOK/128);       // (32, 32)
    dim3 gAttn(16, 64);                   // 64-row q blocks x (B*H)

    round_all_kernel<<<20480, 256>>>(Wq, Wk, Wv, Wo, mha_in_w, mha_out_w,
                                     W1, W2, memory, rw);

    // ---- self-attention ----
    ln_kernel<<<TOK, 256>>>(tgt, g1, be1, ln);
    gemm_tf32_kernel<<<gProj, 256, GEMM_SMEM>>>(ln, rw+RW_WQ, nullptr, nullptr, q,    TOK, DMODEL, DMODEL, 0, 1, 1);
    gemm_tf32_kernel<<<gProj, 256, GEMM_SMEM>>>(ln, rw+RW_WK, nullptr, nullptr, kout, TOK, DMODEL, DMODEL, 0, 1, 1);
    gemm_tf32_kernel<<<gProj, 256, GEMM_SMEM>>>(ln, rw+RW_WV, nullptr, nullptr, vout, TOK, DMODEL, DMODEL, 0, 1, 1);
    attn_kernel<<<gAttn, 128, ATTN_SMEM>>>(q, kout, vout, o, 1);
    gemm_tf32_kernel<<<gProj, 256, GEMM_SMEM>>>(o, rw+RW_WO, nullptr, tgt, x1, TOK, DMODEL, DMODEL, 0, 0, 0);

    // ---- cross-attention ----
    ln_kernel<<<TOK, 256>>>(x1, g2, be2, ln);
    gemm_tf32_kernel<<<gProj, 256, GEMM_SMEM>>>(ln,        rw+RW_INW,         mha_in_b,        nullptr, q,  TOK, DMODEL, DMODEL, 0, 1, 1);
    gemm_tf32_kernel<<<gProj, 256, GEMM_SMEM>>>(rw+RW_MEM, rw+RW_INW+1048576, mha_in_b + 1024, nullptr, k2, TOK, DMODEL, DMODEL, 0, 1, 1);
    gemm_tf32_kernel<<<gProj, 256, GEMM_SMEM>>>(rw+RW_MEM, rw+RW_INW+2097152, mha_in_b + 2048, nullptr, v2, TOK, DMODEL, DMODEL, 0, 1, 1);
    attn_kernel<<<gAttn, 128, ATTN_SMEM>>>(q, k2, v2, o, 0);
    gemm_tf32_kernel<<<gProj, 256, GEMM_SMEM>>>(o, rw+RW_OUTW, mha_out_b, x1, x2, TOK, DMODEL, DMODEL, 0, 0, 0);

    // ---- FFN ----
    ln_kernel<<<TOK, 256>>>(x2, g3, be3, ln);
    gemm_tf32_kernel<<<gFF1,  256, GEMM_SMEM>>>(ln, rw+RW_W1, b1, nullptr, h1,   TOK, DFF_,   DMODEL, 1, 0, 1);
    gemm_tf32_kernel<<<gProj, 256, GEMM_SMEM>>>(h1, rw+RW_W2, b2, x2,      xout, TOK, DMODEL, DFF_,   0, 0, 0);
}

// round 8
// speedup vs baseline: 4.2348x; 1.2092x over previous
#include <cuda_runtime.h>
#include <cuda_fp16.h>
#include <math.h>
#include <stdint.h>

// ---------------------------------------------------------------------------
// B=4, S=SM=1024, D=1024, H=16, HD=64, DFF=4096
// Outputs: x[B,S,D], sa_k[B,H,S,HD], sa_v[B,H,S,HD] concatenated in d_out.
// fp16 tensor-core pipeline: all GEMM operands pre-rounded to half (11-bit
// significand == tf32), accumulation fp32.
// ---------------------------------------------------------------------------

#define TOK    4096
#define DMODEL 1024
#define DFF_   4096
#define NELEM  4194304

// Scratch. Halves live in reinterpreted float arrays.
__device__ float g_ln[NELEM/2];       // half[NELEM]
__device__ float g_q [NELEM/2];
__device__ float g_k2[NELEM/2];
__device__ float g_v2[NELEM/2];
__device__ float g_o [NELEM/2];
__device__ float g_x1[NELEM];
__device__ float g_x2[NELEM];
__device__ float g_h1[8388608];       // half[16777216]
__device__ float g_rw[10485760];      // half[20971520] rounded weights+memory

#define RW_WQ   0
#define RW_WK   1048576
#define RW_WV   2097152
#define RW_WO   3145728
#define RW_INW  4194304
#define RW_OUTW 7340032
#define RW_W1   8388608
#define RW_W2   12582912
#define RW_MEM  16777216

extern __shared__ char dyn_smem[];

__device__ __forceinline__ float cvt_tf32(float x) {
    uint32_t u;
    asm("cvt.rna.tf32.f32 %0, %1;" : "=r"(u) : "f"(x));
    return __uint_as_float(u);
}

__device__ __forceinline__ void mma_f16(
    float& c0, float& c1, float& c2, float& c3,
    uint32_t a0, uint32_t a1, uint32_t a2, uint32_t a3,
    uint32_t b0, uint32_t b1)
{
    asm volatile(
        "mma.sync.aligned.m16n8k16.row.col.f32.f16.f16.f32 "
        "{%0,%1,%2,%3}, {%4,%5,%6,%7}, {%8,%9}, {%0,%1,%2,%3};"
        : "+f"(c0), "+f"(c1), "+f"(c2), "+f"(c3)
        : "r"(a0), "r"(a1), "r"(a2), "r"(a3), "r"(b0), "r"(b1));
}

__device__ __forceinline__ void mma_tf32(
    float& c0, float& c1, float& c2, float& c3,
    uint32_t a0, uint32_t a1, uint32_t a2, uint32_t a3,
    uint32_t b0, uint32_t b1)
{
    asm volatile(
        "mma.sync.aligned.m16n8k8.row.col.f32.tf32.tf32.f32 "
        "{%0,%1,%2,%3}, {%4,%5,%6,%7}, {%8,%9}, {%0,%1,%2,%3};"
        : "+f"(c0), "+f"(c1), "+f"(c2), "+f"(c3)
        : "r"(a0), "r"(a1), "r"(a2), "r"(a3), "r"(b0), "r"(b1));
}

__device__ __forceinline__ void cp16(uint32_t dst, const void* src) {
    asm volatile("cp.async.cg.shared.global [%0], [%1], 16;"
                 :: "r"(dst), "l"(src));
}

// ---------------------------------------------------------------------------
// Round weights + memory to half into g_rw. Grid covers 5242880 float4 reads.
// ---------------------------------------------------------------------------
__global__ __launch_bounds__(256) void round_all_kernel(
    const float* __restrict__ wq, const float* __restrict__ wk,
    const float* __restrict__ wv, const float* __restrict__ wo,
    const float* __restrict__ inw, const float* __restrict__ outw,
    const float* __restrict__ w1, const float* __restrict__ w2,
    const float* __restrict__ mem, __half* __restrict__ dst)
{
    int i = blockIdx.x * 256 + threadIdx.x;   // float4 index
    const float* src;
    int base;
    if      (i < 262144)  { src = wq;   base = 0; }
    else if (i < 524288)  { src = wk;   base = 262144; }
    else if (i < 786432)  { src = wv;   base = 524288; }
    else if (i < 1048576) { src = wo;   base = 786432; }
    else if (i < 1835008) { src = inw;  base = 1048576; }
    else if (i < 2097152) { src = outw; base = 1835008; }
    else if (i < 3145728) { src = w1;   base = 2097152; }
    else if (i < 4194304) { src = w2;   base = 3145728; }
    else                  { src = mem;  base = 4194304; }
    float4 v = ((const float4*)src)[i - base];
    __half2 h0 = __floats2half2_rn(v.x, v.y);
    __half2 h1 = __floats2half2_rn(v.z, v.w);
    *(__half2*)(dst + (size_t)i * 4)     = h0;
    *(__half2*)(dst + (size_t)i * 4 + 2) = h1;
}

// ---------------------------------------------------------------------------
// LayerNorm, half output
// ---------------------------------------------------------------------------
__global__ __launch_bounds__(256) void ln_kernel(
    const float* __restrict__ x, const float* __restrict__ g,
    const float* __restrict__ be, __half* __restrict__ y)
{
    int row = blockIdx.x;
    const float* xr = x + (size_t)row * DMODEL;
    int c = threadIdx.x * 4;
    float4 v = *(const float4*)(xr + c);
    float s  = v.x + v.y + v.z + v.w;
    float ss = v.x*v.x + v.y*v.y + v.z*v.z + v.w*v.w;
    #pragma unroll
    for (int o = 16; o > 0; o >>= 1) {
        s  += __shfl_xor_sync(0xffffffffu, s,  o);
        ss += __shfl_xor_sync(0xffffffffu, ss, o);
    }
    __shared__ float sm[8], sm2[8];
    int w = threadIdx.x >> 5, lane = threadIdx.x & 31;
    if (lane == 0) { sm[w] = s; sm2[w] = ss; }
    __syncthreads();
    s = 0.f; ss = 0.f;
    #pragma unroll
    for (int i = 0; i < 8; i++) { s += sm[i]; ss += sm2[i]; }
    float mu   = s  * (1.0f / DMODEL);
    float var  = ss * (1.0f / DMODEL) - mu * mu;
    float rstd = rsqrtf(var + 1e-5f);
    float4 gv = *(const float4*)(g + c);
    float4 bv = *(const float4*)(be + c);
    __half2 h0 = __floats2half2_rn((v.x - mu) * rstd * gv.x + bv.x,
                                   (v.y - mu) * rstd * gv.y + bv.y);
    __half2 h1 = __floats2half2_rn((v.z - mu) * rstd * gv.z + bv.z,
                                   (v.w - mu) * rstd * gv.w + bv.w);
    __half* yr = y + (size_t)row * DMODEL + c;
    *(__half2*)yr       = h0;
    *(__half2*)(yr + 2) = h1;
}

// ---------------------------------------------------------------------------
// fp16 mma.sync GEMM (NT): C = A[M,K] @ B[N,K]^T (+bias fp32)(+relu)(+res fp32)
// halfOut: C stored as half (optionally scattered to [B,H,S,HD]); Cf != 0:
// additional fp32 scatter copy (for sa_k / sa_v d_out slots).
// CTA 128x128x64, 256 threads = 8 warps (2x4), warp tile 64x32, m16n8k16.
// 3-stage cp.async, pitch 72 halfs (144B: 16B-aligned rows, conflict-free
// 4g+tig bank pattern). 2 CTAs/SM.
// ---------------------------------------------------------------------------
#define BKH 64
#define PITCH 72                      // halfs per smem row
#define MSTG (128*PITCH)              // halfs per matrix per stage (9216)
#define STAGEH (2*MSTG)               // halfs per stage (A+B)
#define GEMM_SMEM (3*STAGEH*2)        // 110592 bytes

__global__ __launch_bounds__(256, 2) void gemm_f16_kernel(
    const __half* __restrict__ A, const __half* __restrict__ B,
    const float* __restrict__ bias, const float* __restrict__ res,
    void* __restrict__ C, float* __restrict__ Cf,
    int M, int N, int K, int relu, int scatter, int halfOut)
{
    __half* smem = (__half*)dyn_smem;
    uint32_t sbase;
    asm("{ .reg .u64 t; cvta.to.shared.u64 t, %1; cvt.u32.u64 %0, t; }"
        : "=r"(sbase) : "l"((char*)dyn_smem));

    int tid  = threadIdx.x;
    int lane = tid & 31;
    int warp = tid >> 5;
    int g    = lane >> 2;
    int tig  = lane & 3;
    int wm   = warp >> 2;             // 0..1
    int wn   = warp & 3;              // 0..3
    int m0 = blockIdx.y * 128, n0 = blockIdx.x * 128;

    float c[4][4][4];
    #pragma unroll
    for (int i = 0; i < 4; i++)
        #pragma unroll
        for (int j = 0; j < 4; j++)
            #pragma unroll
            for (int f = 0; f < 4; f++) c[i][j][f] = 0.f;

    const __half* Ab = A + (size_t)m0 * K;
    const __half* Bb = B + (size_t)n0 * K;
    int NIT = K >> 6;

    // staging geometry: 1024 16B-chunks per matrix per stage; 4 per thread
    int chrow[4], chc[4];
    uint32_t stA[4], stB[4];
    #pragma unroll
    for (int t = 0; t < 4; t++) {
        int chunk = tid + t * 256;    // 0..1023
        chrow[t] = chunk >> 3;        // 0..127
        chc[t]   = (chunk & 7) * 8;   // half offset within row
        stA[t] = sbase + (uint32_t)(chrow[t] * PITCH + chc[t]) * 2;
        stB[t] = stA[t] + MSTG * 2;
    }

    // prologue: stages 0,1
    #pragma unroll
    for (int s = 0; s < 2; s++) {
        int k0 = s << 6;
        uint32_t so = (uint32_t)(s * STAGEH) * 2;
        #pragma unroll
        for (int t = 0; t < 4; t++) {
            cp16(stA[t] + so, Ab + (size_t)chrow[t] * K + k0 + chc[t]);
            cp16(stB[t] + so, Bb + (size_t)chrow[t] * K + k0 + chc[t]);
        }
        asm volatile("cp.async.commit_group;");
    }

    int bufc = 0, bufn = 2;
    for (int kk = 0; kk < NIT; kk++) {
        asm volatile("cp.async.wait_group 1;");
        __syncthreads();

        if (kk + 2 < NIT) {
            int k0 = (kk + 2) << 6;
            uint32_t so = (uint32_t)(bufn * STAGEH) * 2;
            #pragma unroll
            for (int t = 0; t < 4; t++) {
                cp16(stA[t] + so, Ab + (size_t)chrow[t] * K + k0 + chc[t]);
                cp16(stB[t] + so, Bb + (size_t)chrow[t] * K + k0 + chc[t]);
            }
        }
        asm volatile("cp.async.commit_group;");

        const __half* Ac = smem + bufc * STAGEH;
        const __half* Bc = Ac + MSTG;
        const __half* Awp = Ac + (wm * 64 + g) * PITCH + tig * 2;
        const __half* Bwp = Bc + (wn * 32 + g) * PITCH + tig * 2;

        #pragma unroll
        for (int ks = 0; ks < 4; ks++) {
            int k0 = ks * 16;
            uint32_t af[4][4], bf[4][2];
            #pragma unroll
            for (int mt = 0; mt < 4; mt++) {
                const __half* p = Awp + mt * (16 * PITCH) + k0;
                af[mt][0] = *(const uint32_t*)(p);
                af[mt][1] = *(const uint32_t*)(p + 8 * PITCH);
                af[mt][2] = *(const uint32_t*)(p + 8);
                af[mt][3] = *(const uint32_t*)(p + 8 * PITCH + 8);
            }
            #pragma unroll
            for (int nt = 0; nt < 4; nt++) {
                const __half* p = Bwp + nt * (8 * PITCH) + k0;
                bf[nt][0] = *(const uint32_t*)(p);
                bf[nt][1] = *(const uint32_t*)(p + 8);
            }
            #pragma unroll
            for (int mt = 0; mt < 4; mt++)
                #pragma unroll
                for (int nt = 0; nt < 4; nt++)
                    mma_f16(c[mt][nt][0], c[mt][nt][1], c[mt][nt][2], c[mt][nt][3],
                            af[mt][0], af[mt][1], af[mt][2], af[mt][3],
                            bf[nt][0], bf[nt][1]);
        }
        bufc = (bufc == 2) ? 0 : bufc + 1;
        bufn = (bufn == 2) ? 0 : bufn + 1;
    }

    // epilogue
    __half* Ch = (__half*)C;
    float*  Cfl = (float*)C;
    #pragma unroll
    for (int mt = 0; mt < 4; mt++) {
        int row0 = m0 + wm * 64 + mt * 16 + g;
        int row1 = row0 + 8;
        #pragma unroll
        for (int nt = 0; nt < 4; nt++) {
            int col = n0 + wn * 32 + nt * 8 + tig * 2;
            float v00 = c[mt][nt][0], v01 = c[mt][nt][1];
            float v10 = c[mt][nt][2], v11 = c[mt][nt][3];
            if (bias) {
                float b0v = bias[col], b1v = bias[col + 1];
                v00 += b0v; v01 += b1v; v10 += b0v; v11 += b1v;
            }
            if (relu) {
                v00 = fmaxf(v00, 0.f); v01 = fmaxf(v01, 0.f);
                v10 = fmaxf(v10, 0.f); v11 = fmaxf(v11, 0.f);
            }
            if (res) {
                v00 += res[(size_t)row0 * N + col];
                v01 += res[(size_t)row0 * N + col + 1];
                v10 += res[(size_t)row1 * N + col];
                v11 += res[(size_t)row1 * N + col + 1];
            }
            if (scatter) {
                int h_ = col >> 6, d_ = col & 63;
                int b0_ = row0 >> 10, s0_ = row0 & 1023;
                int b1_ = row1 >> 10, s1_ = row1 & 1023;
                size_t o0 = (((size_t)(b0_ * 16 + h_) << 10) + s0_) * 64 + d_;
                size_t o1 = (((size_t)(b1_ * 16 + h_) << 10) + s1_) * 64 + d_;
                *(__half2*)(Ch + o0) = __floats2half2_rn(v00, v01);
                *(__half2*)(Ch + o1) = __floats2half2_rn(v10, v11);
                if (Cf) {
                    *(float2*)(Cf + o0) = make_float2(v00, v01);
                    *(float2*)(Cf + o1) = make_float2(v10, v11);
                }
            } else if (halfOut) {
                *(__half2*)(Ch + (size_t)row0 * N + col) = __floats2half2_rn(v00, v01);
                *(__half2*)(Ch + (size_t)row1 * N + col) = __floats2half2_rn(v10, v11);
            } else {
                *(float2*)(Cfl + (size_t)row0 * N + col) = make_float2(v00, v01);
                *(float2*)(Cfl + (size_t)row1 * N + col) = make_float2(v10, v11);
            }
        }
    }
}

// ---------------------------------------------------------------------------
// Flash attention (tf32 mma core, half I/O), HD=64, Skv=1024.
// Q,K,V half in [B,H,S,64]; O half in [B,S,H*HD] (transpose fused).
// ---------------------------------------------------------------------------
#define APITCH 68
#define ATTN_SMEM (4*64*APITCH*4)   // 69632 B

__global__ __launch_bounds__(128, 3) void attn_kernel(
    const __half* __restrict__ Q, const __half* __restrict__ K,
    const __half* __restrict__ V, __half* __restrict__ O, int causal)
{
    float* Qs = (float*)dyn_smem;          // Qt [d][r] pitch 68 (transposed)
    float* Ks = Qs + 64*APITCH;            // Kt [d][c]
    float* Vs = Ks + 64*APITCH;            // Vs [c][d] pitch 64
    float* Ps = Vs + 64*APITCH;            // P rows, warp-private

    int tid  = threadIdx.x;
    int lane = tid & 31;
    int w    = tid >> 5;
    int g    = lane >> 2;
    int tig  = lane & 3;
    int q0 = blockIdx.x * 64;
    int bh = blockIdx.y;

    const __half* Qb = Q + ((size_t)bh * 1024 + q0) * 64;
    const __half* Kb = K + (size_t)bh * 1024 * 64;
    const __half* Vb = V + (size_t)bh * 1024 * 64;

    // load Q tile (64x64 halfs) transposed into float smem
    #pragma unroll
    for (int t = 0; t < 4; t++) {
        int chunk = tid + t * 128;
        int r = chunk >> 3, c8 = (chunk & 7) * 8;
        uint4 raw = *(const uint4*)(Qb + r * 64 + c8);
        const __half2* hp = (const __half2*)&raw;
        #pragma unroll
        for (int j = 0; j < 4; j++) {
            float2 f = __half22float2(hp[j]);
            Qs[(c8 + j*2    ) * APITCH + r] = f.x;
            Qs[(c8 + j*2 + 1) * APITCH + r] = f.y;
        }
    }

    float o[8][4];
    float m[2], l[2];
    #pragma unroll
    for (int nt = 0; nt < 8; nt++)
        #pragma unroll
        for (int f = 0; f < 4; f++) o[nt][f] = 0.f;
    m[0] = m[1] = -1e30f; l[0] = l[1] = 0.f;

    int rg0 = q0 + w*16 + g;
    int rg1 = rg0 + 8;
    int ntiles = causal ? (blockIdx.x + 1) : 16;

    for (int t = 0; t < ntiles; t++) {
        int k0 = t * 64;
        __syncthreads();
        #pragma unroll
        for (int u = 0; u < 4; u++) {
            int chunk = tid + u * 128;
            int r = chunk >> 3, c8 = (chunk & 7) * 8;
            uint4 kraw = *(const uint4*)(Kb + (size_t)(k0 + r) * 64 + c8);
            uint4 vraw = *(const uint4*)(Vb + (size_t)(k0 + r) * 64 + c8);
            const __half2* kp = (const __half2*)&kraw;
            const __half2* vp = (const __half2*)&vraw;
            float vtmp[8];
            #pragma unroll
            for (int j = 0; j < 4; j++) {
                float2 fk = __half22float2(kp[j]);
                Ks[(c8 + j*2    ) * APITCH + r] = fk.x;
                Ks[(c8 + j*2 + 1) * APITCH + r] = fk.y;
                float2 fv = __half22float2(vp[j]);
                vtmp[j*2] = fv.x; vtmp[j*2+1] = fv.y;
            }
            *(float4*)&Vs[r*64 + c8]     = make_float4(vtmp[0], vtmp[1], vtmp[2], vtmp[3]);
            *(float4*)&Vs[r*64 + c8 + 4] = make_float4(vtmp[4], vtmp[5], vtmp[6], vtmp[7]);
        }
        __syncthreads();

        // S = Q @ K^T  (tf32 mma on float smem — values are half-exact)
        float s[8][4];
        #pragma unroll
        for (int nt = 0; nt < 8; nt++)
            #pragma unroll
            for (int f = 0; f < 4; f++) s[nt][f] = 0.f;

        // A-fragments from transposed Qt: Qt[d][r] -> A[r][d] with r rows
        const float* Qw = Qs + (w*16 + g);   // row index within [d][r]: Qt[d*68 + r]
        #pragma unroll
        for (int dc = 0; dc < 8; dc++) {
            int d0 = dc * 8;
            uint32_t a0 = __float_as_uint(Qs[(d0 + tig) * APITCH + (w*16 + g)]);
            uint32_t a1 = __float_as_uint(Qs[(d0 + tig) * APITCH + (w*16 + g + 8)]);
            uint32_t a2 = __float_as_uint(Qs[(d0 + tig + 4) * APITCH + (w*16 + g)]);
            uint32_t a3 = __float_as_uint(Qs[(d0 + tig + 4) * APITCH + (w*16 + g + 8)]);
            #pragma unroll
            for (int nt = 0; nt < 8; nt++) {
                uint32_t b0 = __float_as_uint(Ks[(d0 + tig) * APITCH + nt*8 + g]);
                uint32_t b1 = __float_as_uint(Ks[(d0 + tig + 4) * APITCH + nt*8 + g]);
                mma_tf32(s[nt][0], s[nt][1], s[nt][2], s[nt][3],
                         a0, a1, a2, a3, b0, b1);
            }
        }
        (void)Qw;

        // scale + causal mask
        #pragma unroll
        for (int nt = 0; nt < 8; nt++) {
            int cg = k0 + nt*8 + tig*2;
            s[nt][0] *= 0.125f; s[nt][1] *= 0.125f;
            s[nt][2] *= 0.125f; s[nt][3] *= 0.125f;
            if (causal) {
                if (cg     > rg0) s[nt][0] = -1e30f;
                if (cg + 1 > rg0) s[nt][1] = -1e30f;
                if (cg     > rg1) s[nt][2] = -1e30f;
                if (cg + 1 > rg1) s[nt][3] = -1e30f;
            }
        }

        // online softmax
        float mx0 = -1e30f, mx1 = -1e30f;
        #pragma unroll
        for (int nt = 0; nt < 8; nt++) {
            mx0 = fmaxf(mx0, fmaxf(s[nt][0], s[nt][1]));
            mx1 = fmaxf(mx1, fmaxf(s[nt][2], s[nt][3]));
        }
        mx0 = fmaxf(mx0, __shfl_xor_sync(0xffffffffu, mx0, 1));
        mx0 = fmaxf(mx0, __shfl_xor_sync(0xffffffffu, mx0, 2));
        mx1 = fmaxf(mx1, __shfl_xor_sync(0xffffffffu, mx1, 1));
        mx1 = fmaxf(mx1, __shfl_xor_sync(0xffffffffu, mx1, 2));

        float mn0 = fmaxf(m[0], mx0), mn1 = fmaxf(m[1], mx1);
        float sc0 = __expf(m[0] - mn0), sc1 = __expf(m[1] - mn1);
        float ls0 = 0.f, ls1 = 0.f;
        #pragma unroll
        for (int nt = 0; nt < 8; nt++) {
            float p0 = cvt_tf32(__expf(s[nt][0] - mn0));
            float p1 = cvt_tf32(__expf(s[nt][1] - mn0));
            float p2 = cvt_tf32(__expf(s[nt][2] - mn1));
            float p3 = cvt_tf32(__expf(s[nt][3] - mn1));
            s[nt][0] = p0; s[nt][1] = p1; s[nt][2] = p2; s[nt][3] = p3;
            ls0 += p0 + p1; ls1 += p2 + p3;
        }
        ls0 += __shfl_xor_sync(0xffffffffu, ls0, 1);
        ls0 += __shfl_xor_sync(0xffffffffu, ls0, 2);
        ls1 += __shfl_xor_sync(0xffffffffu, ls1, 1);
        ls1 += __shfl_xor_sync(0xffffffffu, ls1, 2);
        l[0] = l[0] * sc0 + ls0; m[0] = mn0;
        l[1] = l[1] * sc1 + ls1; m[1] = mn1;
        #pragma unroll
        for (int nt = 0; nt < 8; nt++) {
            o[nt][0] *= sc0; o[nt][1] *= sc0;
            o[nt][2] *= sc1; o[nt][3] *= sc1;
        }

        // store P (warp-private rows w*16..w*16+15, pitch 68)
        float* Pw = Ps + (w*16)*APITCH;
        #pragma unroll
        for (int nt = 0; nt < 8; nt++) {
            int cc = nt*8 + tig*2;
            Pw[g*APITCH + cc]         = s[nt][0];
            Pw[g*APITCH + cc + 1]     = s[nt][1];
            Pw[(g+8)*APITCH + cc]     = s[nt][2];
            Pw[(g+8)*APITCH + cc + 1] = s[nt][3];
        }
        __syncwarp();

        // O += P @ V
        const float* Pr = Ps + (w*16 + g)*APITCH + tig;
        #pragma unroll
        for (int cc = 0; cc < 8; cc++) {
            int c0 = cc * 8;
            uint32_t a0 = __float_as_uint(Pr[c0]);
            uint32_t a1 = __float_as_uint(Pr[8*APITCH + c0]);
            uint32_t a2 = __float_as_uint(Pr[c0 + 4]);
            uint32_t a3 = __float_as_uint(Pr[8*APITCH + c0 + 4]);
            #pragma unroll
            for (int nt = 0; nt < 8; nt++) {
                const float* bp = Vs + (c0 + tig)*64 + nt*8 + g;
                uint32_t b0 = __float_as_uint(bp[0]);
                uint32_t b1 = __float_as_uint(bp[4*64]);
                mma_tf32(o[nt][0], o[nt][1], o[nt][2], o[nt][3],
                         a0, a1, a2, a3, b0, b1);
            }
        }
    }

    // output in [B, S, H*HD] half
    float inv0 = 1.0f / l[0], inv1 = 1.0f / l[1];
    int b_ = bh >> 4, h_ = bh & 15;
    __half* Ob = O + ((size_t)b_ << 20) + h_ * 64;
    #pragma unroll
    for (int nt = 0; nt < 8; nt++) {
        int d = nt*8 + tig*2;
        *(__half2*)(Ob + (size_t)rg0 * 1024 + d) =
            __floats2half2_rn(o[nt][0]*inv0, o[nt][1]*inv0);
        *(__half2*)(Ob + (size_t)rg1 * 1024 + d) =
            __floats2half2_rn(o[nt][2]*inv1, o[nt][3]*inv1);
    }
}

// ---------------------------------------------------------------------------
// Host launch
// ---------------------------------------------------------------------------
extern "C" void kernel_launch(void* const* d_in, const int* in_sizes, int n_in,
                              void* d_out, int out_size)
{
    (void)in_sizes; (void)n_in; (void)out_size;
    const float* tgt       = (const float*)d_in[0];
    const float* memory    = (const float*)d_in[1];
    const float* Wq        = (const float*)d_in[2];
    const float* Wk        = (const float*)d_in[3];
    const float* Wv        = (const float*)d_in[4];
    const float* Wo        = (const float*)d_in[5];
    const float* mha_in_w  = (const float*)d_in[6];
    const float* mha_in_b  = (const float*)d_in[7];
    const float* mha_out_w = (const float*)d_in[8];
    const float* mha_out_b = (const float*)d_in[9];
    const float* W1        = (const float*)d_in[10];
    const float* b1        = (const float*)d_in[11];
    const float* W2        = (const float*)d_in[12];
    const float* b2        = (const float*)d_in[13];
    const float* g1        = (const float*)d_in[14];
    const float* be1       = (const float*)d_in[15];
    const float* g2        = (const float*)d_in[16];
    const float* be2       = (const float*)d_in[17];
    const float* g3        = (const float*)d_in[18];
    const float* be3       = (const float*)d_in[19];

    float* xout = (float*)d_out;
    float* kout = xout + (size_t)NELEM;
    float* vout = kout + (size_t)NELEM;

    void *lnp, *qp, *k2p, *v2p, *op, *x1p, *x2p, *h1p, *rwp;
    cudaGetSymbolAddress(&lnp, g_ln);
    cudaGetSymbolAddress(&qp,  g_q);
    cudaGetSymbolAddress(&k2p, g_k2);
    cudaGetSymbolAddress(&v2p, g_v2);
    cudaGetSymbolAddress(&op,  g_o);
    cudaGetSymbolAddress(&x1p, g_x1);
    cudaGetSymbolAddress(&x2p, g_x2);
    cudaGetSymbolAddress(&h1p, g_h1);
    cudaGetSymbolAddress(&rwp, g_rw);

    __half* lnh = (__half*)lnp;
    __half* qh  = (__half*)qp;
    __half* k2h = (__half*)k2p;
    __half* v2h = (__half*)v2p;
    __half* oh  = (__half*)op;
    float*  x1  = (float*)x1p;
    float*  x2  = (float*)x2p;
    __half* h1h = (__half*)h1p;
    __half* rwh = (__half*)rwp;

    cudaFuncSetAttribute(attn_kernel,
        cudaFuncAttributeMaxDynamicSharedMemorySize, ATTN_SMEM);
    cudaFuncSetAttribute(gemm_f16_kernel,
        cudaFuncAttributeMaxDynamicSharedMemorySize, GEMM_SMEM);

    dim3 gProj(DMODEL/128, TOK/128);      // (8, 32)
    dim3 gFF1 (DFF_/128,  TOK/128);       // (32, 32)
    dim3 gAttn(16, 64);

    round_all_kernel<<<20480, 256>>>(Wq, Wk, Wv, Wo, mha_in_w, mha_out_w,
                                     W1, W2, memory, rwh);

    // ---- self-attention ----
    ln_kernel<<<TOK, 256>>>(tgt, g1, be1, lnh);
    gemm_f16_kernel<<<gProj, 256, GEMM_SMEM>>>(lnh, rwh+RW_WQ, nullptr, nullptr, qh,  nullptr, TOK, DMODEL, DMODEL, 0, 1, 1);
    gemm_f16_kernel<<<gProj, 256, GEMM_SMEM>>>(lnh, rwh+RW_WK, nullptr, nullptr, k2h, kout,    TOK, DMODEL, DMODEL, 0, 1, 1);
    gemm_f16_kernel<<<gProj, 256, GEMM_SMEM>>>(lnh, rwh+RW_WV, nullptr, nullptr, v2h, vout,    TOK, DMODEL, DMODEL, 0, 1, 1);
    attn_kernel<<<gAttn, 128, ATTN_SMEM>>>(qh, k2h, v2h, oh, 1);
    gemm_f16_kernel<<<gProj, 256, GEMM_SMEM>>>(oh, rwh+RW_WO, nullptr, tgt, x1, nullptr, TOK, DMODEL, DMODEL, 0, 0, 0);

    // ---- cross-attention ----
    ln_kernel<<<TOK, 256>>>(x1, g2, be2, lnh);
    gemm_f16_kernel<<<gProj, 256, GEMM_SMEM>>>(lnh,        rwh+RW_INW,         mha_in_b,        nullptr, qh,  nullptr, TOK, DMODEL, DMODEL, 0, 1, 1);
    gemm_f16_kernel<<<gProj, 256, GEMM_SMEM>>>(rwh+RW_MEM, rwh+RW_INW+1048576, mha_in_b + 1024, nullptr, k2h, nullptr, TOK, DMODEL, DMODEL, 0, 1, 1);
    gemm_f16_kernel<<<gProj, 256, GEMM_SMEM>>>(rwh+RW_MEM, rwh+RW_INW+2097152, mha_in_b + 2048, nullptr, v2h, nullptr, TOK, DMODEL, DMODEL, 0, 1, 1);
    attn_kernel<<<gAttn, 128, ATTN_SMEM>>>(qh, k2h, v2h, oh, 0);
    gemm_f16_kernel<<<gProj, 256, GEMM_SMEM>>>(oh, rwh+RW_OUTW, mha_out_b, x1, x2, nullptr, TOK, DMODEL, DMODEL, 0, 0, 0);

    // ---- FFN ----
    ln_kernel<<<TOK, 256>>>(x2, g3, be3, lnh);
    gemm_f16_kernel<<<gFF1,  256, GEMM_SMEM>>>(lnh, rwh+RW_W1, b1, nullptr, h1h, nullptr, TOK, DFF_,   DMODEL, 1, 0, 1);
    gemm_f16_kernel<<<gProj, 256, GEMM_SMEM>>>(h1h, rwh+RW_W2, b2, x2,      xout, nullptr, TOK, DMODEL, DFF_,   0, 0, 0);
}

// round 9
// speedup vs baseline: 4.7110x; 1.1124x over previous
#include <cuda_runtime.h>
#include <cuda_fp16.h>
#include <math.h>
#include <stdint.h>

// ---------------------------------------------------------------------------
// B=4, S=SM=1024, D=1024, H=16, HD=64, DFF=4096
// Outputs: x[B,S,D], sa_k[B,H,S,HD], sa_v[B,H,S,HD] concatenated in d_out.
//
// fp16 tensor-core pipeline. All GEMM operands live in a "tile format":
// a [R][K] half matrix is stored as contiguous 16KB tiles (128 rows x 64 k),
// tile (ti,tj) at ((ti*(K/64)+tj)<<14) bytes, and inside a tile the 16B atoms
// are SW128-xor swizzled: byte(r,c) = r*128 + ((c*2) ^ ((r&7)<<4)).
// Producers (round/ln/attention/FF1-epilogue) write this format directly, so
// the GEMM loads each stage with TWO cp.async.bulk ops (no per-thread copies).
// ---------------------------------------------------------------------------

#define TOK    4096
#define DMODEL 1024
#define DFF_   4096
#define NELEM  4194304

// Scratch (halves live in reinterpreted float arrays)
__device__ float g_ln[NELEM/2];       // half[NELEM], tile fmt K=1024
__device__ float g_q [NELEM/2];       // half, linear [B,H,S,64]
__device__ float g_k2[NELEM/2];
__device__ float g_v2[NELEM/2];
__device__ float g_o [NELEM/2];       // half, tile fmt K=1024 ([4096][1024])
__device__ float g_x1[NELEM];
__device__ float g_x2[NELEM];
__device__ float g_h1[8388608];       // half[16.7M], tile fmt K=4096
__device__ float g_rw[10485760];      // half[20.9M], tile fmt weights+memory

#define RW_WQ   0
#define RW_WK   1048576
#define RW_WV   2097152
#define RW_WO   3145728
#define RW_INW  4194304
#define RW_OUTW 7340032
#define RW_W1   8388608
#define RW_W2   12582912
#define RW_MEM  16777216

extern __shared__ char dyn_smem[];

__device__ __forceinline__ float cvt_tf32(float x) {
    uint32_t u;
    asm("cvt.rna.tf32.f32 %0, %1;" : "=r"(u) : "f"(x));
    return __uint_as_float(u);
}

// half-index into a tile-format matrix with K columns
__device__ __forceinline__ size_t tile_off(int row, int col, int Kdim) {
    size_t tile = (size_t)((row >> 7) * (Kdim >> 6) + (col >> 6));
    uint32_t inb = (uint32_t)(((row & 127) << 7) +
                              ((((col & 63) << 1)) ^ ((row & 7) << 4)));
    return (tile << 13) + (inb >> 1);
}

__device__ __forceinline__ void mma_f16(
    float& c0, float& c1, float& c2, float& c3,
    uint32_t a0, uint32_t a1, uint32_t a2, uint32_t a3,
    uint32_t b0, uint32_t b1)
{
    asm volatile(
        "mma.sync.aligned.m16n8k16.row.col.f32.f16.f16.f32 "
        "{%0,%1,%2,%3}, {%4,%5,%6,%7}, {%8,%9}, {%0,%1,%2,%3};"
        : "+f"(c0), "+f"(c1), "+f"(c2), "+f"(c3)
        : "r"(a0), "r"(a1), "r"(a2), "r"(a3), "r"(b0), "r"(b1));
}

__device__ __forceinline__ void mma_tf32(
    float& c0, float& c1, float& c2, float& c3,
    uint32_t a0, uint32_t a1, uint32_t a2, uint32_t a3,
    uint32_t b0, uint32_t b1)
{
    asm volatile(
        "mma.sync.aligned.m16n8k8.row.col.f32.tf32.tf32.f32 "
        "{%0,%1,%2,%3}, {%4,%5,%6,%7}, {%8,%9}, {%0,%1,%2,%3};"
        : "+f"(c0), "+f"(c1), "+f"(c2), "+f"(c3)
        : "r"(a0), "r"(a1), "r"(a2), "r"(a3), "r"(b0), "r"(b1));
}

#define MBARRIER_INIT(mbar, count) \
    asm volatile("mbarrier.init.shared.b64 [%0], %1;" \
        :: "r"((uint32_t)(mbar)), "r"((uint32_t)(count)) : "memory")

#define MBARRIER_EXPECT_TX(mbar, tx) \
    asm volatile("mbarrier.arrive.expect_tx.shared.b64 _, [%0], %1;" \
        :: "r"((uint32_t)(mbar)), "r"((uint32_t)(tx)) : "memory")

#define MBARRIER_WAIT_PARITY(mbar, parity) do { \
    uint32_t _mbar = (uint32_t)(mbar); \
    uint32_t _par  = (uint32_t)(parity); \
    uint32_t _done; \
    asm volatile( \
        "{\n\t.reg .pred p;\n\t" \
        "mbarrier.try_wait.parity.acquire.cta.shared::cta.b64 p, [%1], %2;\n\t" \
        "selp.b32 %0, 1, 0, p;\n\t}" \
        : "=r"(_done) : "r"(_mbar), "r"(_par) : "memory"); \
    if (!_done) { \
        asm volatile( \
            "{\n\t.reg .pred P1;\n\t" \
            "WAIT_LOOP_%=:\n\t" \
            "mbarrier.try_wait.parity.acquire.cta.shared::cta.b64 P1, [%0], %1, 0x989680;\n\t" \
            "@P1 bra.uni WAIT_DONE_%=;\n\t" \
            "bra.uni WAIT_LOOP_%=;\n\t" \
            "WAIT_DONE_%=:\n\t}" \
            :: "r"(_mbar), "r"(_par) : "memory"); \
    } \
} while (0)

__device__ __forceinline__ void bulk_g2s(uint32_t dst, const void* src,
                                         uint32_t bytes, uint32_t mbar) {
    asm volatile(
        "cp.async.bulk.shared::cluster.global.mbarrier::complete_tx::bytes "
        "[%0], [%1], %2, [%3];"
        :: "r"(dst), "l"(src), "r"(bytes), "r"(mbar) : "memory");
}

// ---------------------------------------------------------------------------
// Round weights + memory to half into g_rw (tile format per region).
// Each thread handles one float4 = 4 halfs (8B, within one 16B atom).
// ---------------------------------------------------------------------------
__global__ __launch_bounds__(256) void round_all_kernel(
    const float* __restrict__ wq, const float* __restrict__ wk,
    const float* __restrict__ wv, const float* __restrict__ wo,
    const float* __restrict__ inw, const float* __restrict__ outw,
    const float* __restrict__ w1, const float* __restrict__ w2,
    const float* __restrict__ mem, __half* __restrict__ dst)
{
    int i = blockIdx.x * 256 + threadIdx.x;   // float4 index, 0..5242879
    const float* src;
    int base, Kdim;
    if      (i < 262144)  { src = wq;   base = 0;       Kdim = 1024; }
    else if (i < 524288)  { src = wk;   base = 262144;  Kdim = 1024; }
    else if (i < 786432)  { src = wv;   base = 524288;  Kdim = 1024; }
    else if (i < 1048576) { src = wo;   base = 786432;  Kdim = 1024; }
    else if (i < 1835008) { src = inw;  base = 1048576; Kdim = 1024; }
    else if (i < 2097152) { src = outw; base = 1835008; Kdim = 1024; }
    else if (i < 3145728) { src = w1;   base = 2097152; Kdim = 1024; }
    else if (i < 4194304) { src = w2;   base = 3145728; Kdim = 4096; }
    else                  { src = mem;  base = 4194304; Kdim = 1024; }
    float4 v = ((const float4*)src)[i - base];
    int lin = (i - base) * 4;             // half index within region
    int row = lin / Kdim, col = lin % Kdim;
    size_t off = (size_t)(base << 2) + tile_off(row, col, Kdim);
    __half2 h0 = __floats2half2_rn(v.x, v.y);
    __half2 h1 = __floats2half2_rn(v.z, v.w);
    *(__half2*)(dst + off)     = h0;
    *(__half2*)(dst + off + 2) = h1;
}

// ---------------------------------------------------------------------------
// LayerNorm -> half tile format (K=1024)
// ---------------------------------------------------------------------------
__global__ __launch_bounds__(256) void ln_kernel(
    const float* __restrict__ x, const float* __restrict__ g,
    const float* __restrict__ be, __half* __restrict__ y)
{
    int row = blockIdx.x;
    const float* xr = x + (size_t)row * DMODEL;
    int c = threadIdx.x * 4;
    float4 v = *(const float4*)(xr + c);
    float s  = v.x + v.y + v.z + v.w;
    float ss = v.x*v.x + v.y*v.y + v.z*v.z + v.w*v.w;
    #pragma unroll
    for (int o = 16; o > 0; o >>= 1) {
        s  += __shfl_xor_sync(0xffffffffu, s,  o);
        ss += __shfl_xor_sync(0xffffffffu, ss, o);
    }
    __shared__ float sm[8], sm2[8];
    int w = threadIdx.x >> 5, lane = threadIdx.x & 31;
    if (lane == 0) { sm[w] = s; sm2[w] = ss; }
    __syncthreads();
    s = 0.f; ss = 0.f;
    #pragma unroll
    for (int i = 0; i < 8; i++) { s += sm[i]; ss += sm2[i]; }
    float mu   = s  * (1.0f / DMODEL);
    float var  = ss * (1.0f / DMODEL) - mu * mu;
    float rstd = rsqrtf(var + 1e-5f);
    float4 gv = *(const float4*)(g + c);
    float4 bv = *(const float4*)(be + c);
    __half2 h0 = __floats2half2_rn((v.x - mu) * rstd * gv.x + bv.x,
                                   (v.y - mu) * rstd * gv.y + bv.y);
    __half2 h1 = __floats2half2_rn((v.z - mu) * rstd * gv.z + bv.z,
                                   (v.w - mu) * rstd * gv.w + bv.w);
    size_t off = tile_off(row, c, 1024);
    *(__half2*)(y + off)     = h0;
    *(__half2*)(y + off + 2) = h1;
}

// ---------------------------------------------------------------------------
// fp16 GEMM (NT) on tile-format operands: C = A[M,K] @ B[N,K]^T
// Stage load = 2x cp.async.bulk (16KB A-tile + 16KB B-tile) via mbarrier.
// CTA 128x128x64, 256 threads, 8 warps (2x4), warp tile 64x32, m16n8k16.
// 3 stages (96KB) + mbars. 2 CTAs/SM.
// Outputs: scatter half [B,H,S,64] (+optional fp32 copy), fp32 linear,
// or half tile-format with column count outK (FF1 -> FF2 chain).
// ---------------------------------------------------------------------------
#define MBAR_OFF 98304
#define GEMM_SMEM (98304 + 64)

__global__ __launch_bounds__(256, 2) void gemm_f16_kernel(
    const __half* __restrict__ A, const __half* __restrict__ B,
    const float* __restrict__ bias, const float* __restrict__ res,
    void* __restrict__ C, float* __restrict__ Cf,
    int M, int N, int K, int relu, int scatter, int halfOut, int outK)
{
    uint32_t sbase;
    asm("{ .reg .u64 t; cvta.to.shared.u64 t, %1; cvt.u32.u64 %0, t; }"
        : "=r"(sbase) : "l"((char*)dyn_smem));

    int tid  = threadIdx.x;
    int lane = tid & 31;
    int warp = tid >> 5;
    int g    = lane >> 2;
    int tig  = lane & 3;
    int wm   = warp >> 2;             // 0..1
    int wn   = warp & 3;              // 0..3
    int bx = blockIdx.x, by = blockIdx.y;
    int m0 = by * 128, n0 = bx * 128;
    int TK = K >> 6;
    int NIT = TK;

    if (tid < 3) MBARRIER_INIT(sbase + MBAR_OFF + tid * 8, 1);
    __syncthreads();

    float c[4][4][4];
    #pragma unroll
    for (int i = 0; i < 4; i++)
        #pragma unroll
        for (int j = 0; j < 4; j++)
            #pragma unroll
            for (int f = 0; f < 4; f++) c[i][j][f] = 0.f;

    #define ISSUE_STAGE(s_) do { \
        if (tid == 0) { \
            int s__ = (s_); \
            uint32_t mb = sbase + MBAR_OFF + (s__ % 3) * 8; \
            MBARRIER_EXPECT_TX(mb, 32768u); \
            uint32_t d = sbase + (uint32_t)(s__ % 3) * 32768u; \
            const char* as_ = (const char*)A + ((size_t)(by * TK + s__) << 14); \
            const char* bs_ = (const char*)B + ((size_t)(bx * TK + s__) << 14); \
            bulk_g2s(d,           as_, 16384u, mb); \
            bulk_g2s(d + 16384u,  bs_, 16384u, mb); \
        } \
    } while (0)

    ISSUE_STAGE(0);
    ISSUE_STAGE(1);

    // precomputed row byte-offsets and xor key base
    uint32_t ra[4], rb[4];
    #pragma unroll
    for (int mt = 0; mt < 4; mt++) ra[mt] = (uint32_t)((wm*64 + mt*16 + g) * 128);
    #pragma unroll
    for (int nt = 0; nt < 4; nt++) rb[nt] = (uint32_t)((wn*32 + nt*8 + g) * 128);
    uint32_t xr = (uint32_t)(g << 4);

    for (int i = 0; i < NIT; i++) {
        __syncthreads();
        if (i + 2 < NIT) ISSUE_STAGE(i + 2);
        MBARRIER_WAIT_PARITY(sbase + MBAR_OFF + (i % 3) * 8, (i / 3) & 1);

        const char* As = (const char*)dyn_smem + (i % 3) * 32768;
        const char* Bs = As + 16384;

        #pragma unroll
        for (int ks = 0; ks < 4; ks++) {
            uint32_t key  = ((uint32_t)(ks * 32 + tig * 4)) ^ xr;
            uint32_t key2 = key ^ 16u;
            uint32_t af[4][4], bf[4][2];
            #pragma unroll
            for (int mt = 0; mt < 4; mt++) {
                af[mt][0] = *(const uint32_t*)(As + ra[mt] + key);
                af[mt][1] = *(const uint32_t*)(As + ra[mt] + 1024 + key);
                af[mt][2] = *(const uint32_t*)(As + ra[mt] + key2);
                af[mt][3] = *(const uint32_t*)(As + ra[mt] + 1024 + key2);
            }
            #pragma unroll
            for (int nt = 0; nt < 4; nt++) {
                bf[nt][0] = *(const uint32_t*)(Bs + rb[nt] + key);
                bf[nt][1] = *(const uint32_t*)(Bs + rb[nt] + key2);
            }
            #pragma unroll
            for (int mt = 0; mt < 4; mt++)
                #pragma unroll
                for (int nt = 0; nt < 4; nt++)
                    mma_f16(c[mt][nt][0], c[mt][nt][1], c[mt][nt][2], c[mt][nt][3],
                            af[mt][0], af[mt][1], af[mt][2], af[mt][3],
                            bf[nt][0], bf[nt][1]);
        }
    }
    #undef ISSUE_STAGE

    // epilogue
    __half* Ch = (__half*)C;
    float*  Cfl = (float*)C;
    #pragma unroll
    for (int mt = 0; mt < 4; mt++) {
        int row0 = m0 + wm * 64 + mt * 16 + g;
        int row1 = row0 + 8;
        #pragma unroll
        for (int nt = 0; nt < 4; nt++) {
            int col = n0 + wn * 32 + nt * 8 + tig * 2;
            float v00 = c[mt][nt][0], v01 = c[mt][nt][1];
            float v10 = c[mt][nt][2], v11 = c[mt][nt][3];
            if (bias) {
                float b0v = bias[col], b1v = bias[col + 1];
                v00 += b0v; v01 += b1v; v10 += b0v; v11 += b1v;
            }
            if (relu) {
                v00 = fmaxf(v00, 0.f); v01 = fmaxf(v01, 0.f);
                v10 = fmaxf(v10, 0.f); v11 = fmaxf(v11, 0.f);
            }
            if (res) {
                v00 += res[(size_t)row0 * N + col];
                v01 += res[(size_t)row0 * N + col + 1];
                v10 += res[(size_t)row1 * N + col];
                v11 += res[(size_t)row1 * N + col + 1];
            }
            if (scatter) {
                int h_ = col >> 6, d_ = col & 63;
                int b0_ = row0 >> 10, s0_ = row0 & 1023;
                int b1_ = row1 >> 10, s1_ = row1 & 1023;
                size_t o0 = (((size_t)(b0_ * 16 + h_) << 10) + s0_) * 64 + d_;
                size_t o1 = (((size_t)(b1_ * 16 + h_) << 10) + s1_) * 64 + d_;
                *(__half2*)(Ch + o0) = __floats2half2_rn(v00, v01);
                *(__half2*)(Ch + o1) = __floats2half2_rn(v10, v11);
                if (Cf) {
                    *(float2*)(Cf + o0) = make_float2(v00, v01);
                    *(float2*)(Cf + o1) = make_float2(v10, v11);
                }
            } else if (halfOut) {
                *(__half2*)(Ch + tile_off(row0, col, outK)) = __floats2half2_rn(v00, v01);
                *(__half2*)(Ch + tile_off(row1, col, outK)) = __floats2half2_rn(v10, v11);
            } else {
                *(float2*)(Cfl + (size_t)row0 * N + col) = make_float2(v00, v01);
                *(float2*)(Cfl + (size_t)row1 * N + col) = make_float2(v10, v11);
            }
        }
    }
}

// ---------------------------------------------------------------------------
// Flash attention (tf32 mma core, half I/O), HD=64, Skv=1024.
// Q,K,V half linear [B,H,S,64]; O half in TILE FORMAT ([4096][1024], K=1024)
// since it feeds the out-projection GEMM.
// ---------------------------------------------------------------------------
#define APITCH 68
#define ATTN_SMEM (4*64*APITCH*4)   // 69632 B

__global__ __launch_bounds__(128, 3) void attn_kernel(
    const __half* __restrict__ Q, const __half* __restrict__ K,
    const __half* __restrict__ V, __half* __restrict__ O, int causal)
{
    float* Qs = (float*)dyn_smem;
    float* Ks = Qs + 64*APITCH;
    float* Vs = Ks + 64*APITCH;
    float* Ps = Vs + 64*APITCH;

    int tid  = threadIdx.x;
    int lane = tid & 31;
    int w    = tid >> 5;
    int g    = lane >> 2;
    int tig  = lane & 3;
    int q0 = blockIdx.x * 64;
    int bh = blockIdx.y;

    const __half* Qb = Q + ((size_t)bh * 1024 + q0) * 64;
    const __half* Kb = K + (size_t)bh * 1024 * 64;
    const __half* Vb = V + (size_t)bh * 1024 * 64;

    #pragma unroll
    for (int t = 0; t < 4; t++) {
        int chunk = tid + t * 128;
        int r = chunk >> 3, c8 = (chunk & 7) * 8;
        uint4 raw = *(const uint4*)(Qb + r * 64 + c8);
        const __half2* hp = (const __half2*)&raw;
        #pragma unroll
        for (int j = 0; j < 4; j++) {
            float2 f = __half22float2(hp[j]);
            Qs[(c8 + j*2    ) * APITCH + r] = f.x;
            Qs[(c8 + j*2 + 1) * APITCH + r] = f.y;
        }
    }

    float o[8][4];
    float m[2], l[2];
    #pragma unroll
    for (int nt = 0; nt < 8; nt++)
        #pragma unroll
        for (int f = 0; f < 4; f++) o[nt][f] = 0.f;
    m[0] = m[1] = -1e30f; l[0] = l[1] = 0.f;

    int rg0 = q0 + w*16 + g;
    int rg1 = rg0 + 8;
    int ntiles = causal ? (blockIdx.x + 1) : 16;

    for (int t = 0; t < ntiles; t++) {
        int k0 = t * 64;
        __syncthreads();
        #pragma unroll
        for (int u = 0; u < 4; u++) {
            int chunk = tid + u * 128;
            int r = chunk >> 3, c8 = (chunk & 7) * 8;
            uint4 kraw = *(const uint4*)(Kb + (size_t)(k0 + r) * 64 + c8);
            uint4 vraw = *(const uint4*)(Vb + (size_t)(k0 + r) * 64 + c8);
            const __half2* kp = (const __half2*)&kraw;
            const __half2* vp = (const __half2*)&vraw;
            float vtmp[8];
            #pragma unroll
            for (int j = 0; j < 4; j++) {
                float2 fk = __half22float2(kp[j]);
                Ks[(c8 + j*2    ) * APITCH + r] = fk.x;
                Ks[(c8 + j*2 + 1) * APITCH + r] = fk.y;
                float2 fv = __half22float2(vp[j]);
                vtmp[j*2] = fv.x; vtmp[j*2+1] = fv.y;
            }
            *(float4*)&Vs[r*64 + c8]     = make_float4(vtmp[0], vtmp[1], vtmp[2], vtmp[3]);
            *(float4*)&Vs[r*64 + c8 + 4] = make_float4(vtmp[4], vtmp[5], vtmp[6], vtmp[7]);
        }
        __syncthreads();

        float s[8][4];
        #pragma unroll
        for (int nt = 0; nt < 8; nt++)
            #pragma unroll
            for (int f = 0; f < 4; f++) s[nt][f] = 0.f;

        #pragma unroll
        for (int dc = 0; dc < 8; dc++) {
            int d0 = dc * 8;
            uint32_t a0 = __float_as_uint(Qs[(d0 + tig) * APITCH + (w*16 + g)]);
            uint32_t a1 = __float_as_uint(Qs[(d0 + tig) * APITCH + (w*16 + g + 8)]);
            uint32_t a2 = __float_as_uint(Qs[(d0 + tig + 4) * APITCH + (w*16 + g)]);
            uint32_t a3 = __float_as_uint(Qs[(d0 + tig + 4) * APITCH + (w*16 + g + 8)]);
            #pragma unroll
            for (int nt = 0; nt < 8; nt++) {
                uint32_t b0 = __float_as_uint(Ks[(d0 + tig) * APITCH + nt*8 + g]);
                uint32_t b1 = __float_as_uint(Ks[(d0 + tig + 4) * APITCH + nt*8 + g]);
                mma_tf32(s[nt][0], s[nt][1], s[nt][2], s[nt][3],
                         a0, a1, a2, a3, b0, b1);
            }
        }

        #pragma unroll
        for (int nt = 0; nt < 8; nt++) {
            int cg = k0 + nt*8 + tig*2;
            s[nt][0] *= 0.125f; s[nt][1] *= 0.125f;
            s[nt][2] *= 0.125f; s[nt][3] *= 0.125f;
            if (causal) {
                if (cg     > rg0) s[nt][0] = -1e30f;
                if (cg + 1 > rg0) s[nt][1] = -1e30f;
                if (cg     > rg1) s[nt][2] = -1e30f;
                if (cg + 1 > rg1) s[nt][3] = -1e30f;
            }
        }

        float mx0 = -1e30f, mx1 = -1e30f;
        #pragma unroll
        for (int nt = 0; nt < 8; nt++) {
            mx0 = fmaxf(mx0, fmaxf(s[nt][0], s[nt][1]));
            mx1 = fmaxf(mx1, fmaxf(s[nt][2], s[nt][3]));
        }
        mx0 = fmaxf(mx0, __shfl_xor_sync(0xffffffffu, mx0, 1));
        mx0 = fmaxf(mx0, __shfl_xor_sync(0xffffffffu, mx0, 2));
        mx1 = fmaxf(mx1, __shfl_xor_sync(0xffffffffu, mx1, 1));
        mx1 = fmaxf(mx1, __shfl_xor_sync(0xffffffffu, mx1, 2));

        float mn0 = fmaxf(m[0], mx0), mn1 = fmaxf(m[1], mx1);
        float sc0 = __expf(m[0] - mn0), sc1 = __expf(m[1] - mn1);
        float ls0 = 0.f, ls1 = 0.f;
        #pragma unroll
        for (int nt = 0; nt < 8; nt++) {
            float p0 = cvt_tf32(__expf(s[nt][0] - mn0));
            float p1 = cvt_tf32(__expf(s[nt][1] - mn0));
            float p2 = cvt_tf32(__expf(s[nt][2] - mn1));
            float p3 = cvt_tf32(__expf(s[nt][3] - mn1));
            s[nt][0] = p0; s[nt][1] = p1; s[nt][2] = p2; s[nt][3] = p3;
            ls0 += p0 + p1; ls1 += p2 + p3;
        }
        ls0 += __shfl_xor_sync(0xffffffffu, ls0, 1);
        ls0 += __shfl_xor_sync(0xffffffffu, ls0, 2);
        ls1 += __shfl_xor_sync(0xffffffffu, ls1, 1);
        ls1 += __shfl_xor_sync(0xffffffffu, ls1, 2);
        l[0] = l[0] * sc0 + ls0; m[0] = mn0;
        l[1] = l[1] * sc1 + ls1; m[1] = mn1;
        #pragma unroll
        for (int nt = 0; nt < 8; nt++) {
            o[nt][0] *= sc0; o[nt][1] *= sc0;
            o[nt][2] *= sc1; o[nt][3] *= sc1;
        }

        float* Pw = Ps + (w*16)*APITCH;
        #pragma unroll
        for (int nt = 0; nt < 8; nt++) {
            int cc = nt*8 + tig*2;
            Pw[g*APITCH + cc]         = s[nt][0];
            Pw[g*APITCH + cc + 1]     = s[nt][1];
            Pw[(g+8)*APITCH + cc]     = s[nt][2];
            Pw[(g+8)*APITCH + cc + 1] = s[nt][3];
        }
        __syncwarp();

        const float* Pr = Ps + (w*16 + g)*APITCH + tig;
        #pragma unroll
        for (int cc = 0; cc < 8; cc++) {
            int c0 = cc * 8;
            uint32_t a0 = __float_as_uint(Pr[c0]);
            uint32_t a1 = __float_as_uint(Pr[8*APITCH + c0]);
            uint32_t a2 = __float_as_uint(Pr[c0 + 4]);
            uint32_t a3 = __float_as_uint(Pr[8*APITCH + c0 + 4]);
            #pragma unroll
            for (int nt = 0; nt < 8; nt++) {
                const float* bp = Vs + (c0 + tig)*64 + nt*8 + g;
                uint32_t b0 = __float_as_uint(bp[0]);
                uint32_t b1 = __float_as_uint(bp[4*64]);
                mma_tf32(o[nt][0], o[nt][1], o[nt][2], o[nt][3],
                         a0, a1, a2, a3, b0, b1);
            }
        }
    }

    // output in tile format: row = b*1024 + seq, col = h*64 + d, K=1024
    float inv0 = 1.0f / l[0], inv1 = 1.0f / l[1];
    int b_ = bh >> 4, h_ = bh & 15;
    int row0 = b_ * 1024 + rg0;
    int row1 = b_ * 1024 + rg1;
    #pragma unroll
    for (int nt = 0; nt < 8; nt++) {
        int col = h_ * 64 + nt*8 + tig*2;
        *(__half2*)(O + tile_off(row0, col, 1024)) =
            __floats2half2_rn(o[nt][0]*inv0, o[nt][1]*inv0);
        *(__half2*)(O + tile_off(row1, col, 1024)) =
            __floats2half2_rn(o[nt][2]*inv1, o[nt][3]*inv1);
    }
}

// ---------------------------------------------------------------------------
// Host launch
// ---------------------------------------------------------------------------
extern "C" void kernel_launch(void* const* d_in, const int* in_sizes, int n_in,
                              void* d_out, int out_size)
{
    (void)in_sizes; (void)n_in; (void)out_size;
    const float* tgt       = (const float*)d_in[0];
    const float* memory    = (const float*)d_in[1];
    const float* Wq        = (const float*)d_in[2];
    const float* Wk        = (const float*)d_in[3];
    const float* Wv        = (const float*)d_in[4];
    const float* Wo        = (const float*)d_in[5];
    const float* mha_in_w  = (const float*)d_in[6];
    const float* mha_in_b  = (const float*)d_in[7];
    const float* mha_out_w = (const float*)d_in[8];
    const float* mha_out_b = (const float*)d_in[9];
    const float* W1        = (const float*)d_in[10];
    const float* b1        = (const float*)d_in[11];
    const float* W2        = (const float*)d_in[12];
    const float* b2        = (const float*)d_in[13];
    const float* g1        = (const float*)d_in[14];
    const float* be1       = (const float*)d_in[15];
    const float* g2        = (const float*)d_in[16];
    const float* be2       = (const float*)d_in[17];
    const float* g3        = (const float*)d_in[18];
    const float* be3       = (const float*)d_in[19];

    float* xout = (float*)d_out;
    float* kout = xout + (size_t)NELEM;
    float* vout = kout + (size_t)NELEM;

    void *lnp, *qp, *k2p, *v2p, *op, *x1p, *x2p, *h1p, *rwp;
    cudaGetSymbolAddress(&lnp, g_ln);
    cudaGetSymbolAddress(&qp,  g_q);
    cudaGetSymbolAddress(&k2p, g_k2);
    cudaGetSymbolAddress(&v2p, g_v2);
    cudaGetSymbolAddress(&op,  g_o);
    cudaGetSymbolAddress(&x1p, g_x1);
    cudaGetSymbolAddress(&x2p, g_x2);
    cudaGetSymbolAddress(&h1p, g_h1);
    cudaGetSymbolAddress(&rwp, g_rw);

    __half* lnh = (__half*)lnp;
    __half* qh  = (__half*)qp;
    __half* k2h = (__half*)k2p;
    __half* v2h = (__half*)v2p;
    __half* oh  = (__half*)op;
    float*  x1  = (float*)x1p;
    float*  x2  = (float*)x2p;
    __half* h1h = (__half*)h1p;
    __half* rwh = (__half*)rwp;

    cudaFuncSetAttribute(attn_kernel,
        cudaFuncAttributeMaxDynamicSharedMemorySize, ATTN_SMEM);
    cudaFuncSetAttribute(gemm_f16_kernel,
        cudaFuncAttributeMaxDynamicSharedMemorySize, GEMM_SMEM);

    dim3 gProj(DMODEL/128, TOK/128);      // (8, 32)
    dim3 gFF1 (DFF_/128,  TOK/128);       // (32, 32)
    dim3 gAttn(16, 64);

    round_all_kernel<<<20480, 256>>>(Wq, Wk, Wv, Wo, mha_in_w, mha_out_w,
                                     W1, W2, memory, rwh);

    // ---- self-attention ----
    ln_kernel<<<TOK, 256>>>(tgt, g1, be1, lnh);
    gemm_f16_kernel<<<gProj, 256, GEMM_SMEM>>>(lnh, rwh+RW_WQ, nullptr, nullptr, qh,  nullptr, TOK, DMODEL, DMODEL, 0, 1, 0, 0);
    gemm_f16_kernel<<<gProj, 256, GEMM_SMEM>>>(lnh, rwh+RW_WK, nullptr, nullptr, k2h, kout,    TOK, DMODEL, DMODEL, 0, 1, 0, 0);
    gemm_f16_kernel<<<gProj, 256, GEMM_SMEM>>>(lnh, rwh+RW_WV, nullptr, nullptr, v2h, vout,    TOK, DMODEL, DMODEL, 0, 1, 0, 0);
    attn_kernel<<<gAttn, 128, ATTN_SMEM>>>(qh, k2h, v2h, oh, 1);
    gemm_f16_kernel<<<gProj, 256, GEMM_SMEM>>>(oh, rwh+RW_WO, nullptr, tgt, x1, nullptr, TOK, DMODEL, DMODEL, 0, 0, 0, 0);

    // ---- cross-attention ----
    ln_kernel<<<TOK, 256>>>(x1, g2, be2, lnh);
    gemm_f16_kernel<<<gProj, 256, GEMM_SMEM>>>(lnh,        rwh+RW_INW,         mha_in_b,        nullptr, qh,  nullptr, TOK, DMODEL, DMODEL, 0, 1, 0, 0);
    gemm_f16_kernel<<<gProj, 256, GEMM_SMEM>>>(rwh+RW_MEM, rwh+RW_INW+1048576, mha_in_b + 1024, nullptr, k2h, nullptr, TOK, DMODEL, DMODEL, 0, 1, 0, 0);
    gemm_f16_kernel<<<gProj, 256, GEMM_SMEM>>>(rwh+RW_MEM, rwh+RW_INW+2097152, mha_in_b + 2048, nullptr, v2h, nullptr, TOK, DMODEL, DMODEL, 0, 1, 0, 0);
    attn_kernel<<<gAttn, 128, ATTN_SMEM>>>(qh, k2h, v2h, oh, 0);
    gemm_f16_kernel<<<gProj, 256, GEMM_SMEM>>>(oh, rwh+RW_OUTW, mha_out_b, x1, x2, nullptr, TOK, DMODEL, DMODEL, 0, 0, 0, 0);

    // ---- FFN ----
    ln_kernel<<<TOK, 256>>>(x2, g3, be3, lnh);
    gemm_f16_kernel<<<gFF1,  256, GEMM_SMEM>>>(lnh, rwh+RW_W1, b1, nullptr, h1h, nullptr, TOK, DFF_,   DMODEL, 1, 0, 1, 4096);
    gemm_f16_kernel<<<gProj, 256, GEMM_SMEM>>>(h1h, rwh+RW_W2, b2, x2,      xout, nullptr, TOK, DMODEL, DFF_,   0, 0, 0, 0);
}

// round 10
// speedup vs baseline: 6.8729x; 1.4589x over previous
#include <cuda_runtime.h>
#include <cuda_fp16.h>
#include <math.h>
#include <stdint.h>

// ---------------------------------------------------------------------------
// B=4, S=SM=1024, D=1024, H=16, HD=64, DFF=4096
// Outputs: x[B,S,D], sa_k[B,H,S,HD], sa_v[B,H,S,HD] concatenated in d_out.
//
// fp16 tensor-core pipeline. GEMM operands in "tile format": [R][K] half
// matrix as contiguous 16KB tiles (128 rows x 64 k), tile (ti,tj) at
// ((ti*(K/64)+tj)<<14) bytes; inside a tile byte(r,c) = r*128 +
// ((c*2) ^ ((r&7)<<4)). GEMM stages load via cp.async.bulk (2x16KB).
// Weight concatenation is free in this format -> fused QKV projections.
// ---------------------------------------------------------------------------

#define TOK    4096
#define DMODEL 1024
#define DFF_   4096
#define NELEM  4194304

__device__ float g_ln[NELEM/2];       // half, tile fmt K=1024
__device__ float g_q [NELEM/2];       // half, linear [B,H,S,64]
__device__ float g_k2[NELEM/2];
__device__ float g_v2[NELEM/2];
__device__ float g_o [NELEM/2];       // half, tile fmt K=1024
__device__ float g_x1[NELEM];
__device__ float g_x2[NELEM];
__device__ float g_h1[8388608];       // half, tile fmt K=4096
__device__ float g_rw[10485760];      // half, tile fmt weights+memory

#define RW_WQ   0
#define RW_WK   1048576
#define RW_WV   2097152
#define RW_WO   3145728
#define RW_INW  4194304
#define RW_OUTW 7340032
#define RW_W1   8388608
#define RW_W2   12582912
#define RW_MEM  16777216

extern __shared__ char dyn_smem[];

// half-index into a tile-format matrix with K columns
__device__ __forceinline__ size_t tile_off(int row, int col, int Kdim) {
    size_t tile = (size_t)((row >> 7) * (Kdim >> 6) + (col >> 6));
    uint32_t inb = (uint32_t)(((row & 127) << 7) +
                              ((((col & 63) << 1)) ^ ((row & 7) << 4)));
    return (tile << 13) + (inb >> 1);
}

__device__ __forceinline__ void mma_f16(
    float& c0, float& c1, float& c2, float& c3,
    uint32_t a0, uint32_t a1, uint32_t a2, uint32_t a3,
    uint32_t b0, uint32_t b1)
{
    asm volatile(
        "mma.sync.aligned.m16n8k16.row.col.f32.f16.f16.f32 "
        "{%0,%1,%2,%3}, {%4,%5,%6,%7}, {%8,%9}, {%0,%1,%2,%3};"
        : "+f"(c0), "+f"(c1), "+f"(c2), "+f"(c3)
        : "r"(a0), "r"(a1), "r"(a2), "r"(a3), "r"(b0), "r"(b1));
}

#define MBARRIER_INIT(mbar, count) \
    asm volatile("mbarrier.init.shared.b64 [%0], %1;" \
        :: "r"((uint32_t)(mbar)), "r"((uint32_t)(count)) : "memory")

#define MBARRIER_EXPECT_TX(mbar, tx) \
    asm volatile("mbarrier.arrive.expect_tx.shared.b64 _, [%0], %1;" \
        :: "r"((uint32_t)(mbar)), "r"((uint32_t)(tx)) : "memory")

#define MBARRIER_WAIT_PARITY(mbar, parity) do { \
    uint32_t _mbar = (uint32_t)(mbar); \
    uint32_t _par  = (uint32_t)(parity); \
    uint32_t _done; \
    asm volatile( \
        "{\n\t.reg .pred p;\n\t" \
        "mbarrier.try_wait.parity.acquire.cta.shared::cta.b64 p, [%1], %2;\n\t" \
        "selp.b32 %0, 1, 0, p;\n\t}" \
        : "=r"(_done) : "r"(_mbar), "r"(_par) : "memory"); \
    if (!_done) { \
        asm volatile( \
            "{\n\t.reg .pred P1;\n\t" \
            "WAIT_LOOP_%=:\n\t" \
            "mbarrier.try_wait.parity.acquire.cta.shared::cta.b64 P1, [%0], %1, 0x989680;\n\t" \
            "@P1 bra.uni WAIT_DONE_%=;\n\t" \
            "bra.uni WAIT_LOOP_%=;\n\t" \
            "WAIT_DONE_%=:\n\t}" \
            :: "r"(_mbar), "r"(_par) : "memory"); \
    } \
} while (0)

__device__ __forceinline__ void bulk_g2s(uint32_t dst, const void* src,
                                         uint32_t bytes, uint32_t mbar) {
    asm volatile(
        "cp.async.bulk.shared::cluster.global.mbarrier::complete_tx::bytes "
        "[%0], [%1], %2, [%3];"
        :: "r"(dst), "l"(src), "r"(bytes), "r"(mbar) : "memory");
}

// ---------------------------------------------------------------------------
// Round weights + memory to half into g_rw (tile format per region).
// ---------------------------------------------------------------------------
__global__ __launch_bounds__(256) void round_all_kernel(
    const float* __restrict__ wq, const float* __restrict__ wk,
    const float* __restrict__ wv, const float* __restrict__ wo,
    const float* __restrict__ inw, const float* __restrict__ outw,
    const float* __restrict__ w1, const float* __restrict__ w2,
    const float* __restrict__ mem, __half* __restrict__ dst)
{
    int i = blockIdx.x * 256 + threadIdx.x;   // float4 index, 0..5242879
    const float* src;
    int base, Kdim;
    if      (i < 262144)  { src = wq;   base = 0;       Kdim = 1024; }
    else if (i < 524288)  { src = wk;   base = 262144;  Kdim = 1024; }
    else if (i < 786432)  { src = wv;   base = 524288;  Kdim = 1024; }
    else if (i < 1048576) { src = wo;   base = 786432;  Kdim = 1024; }
    else if (i < 1835008) { src = inw;  base = 1048576; Kdim = 1024; }
    else if (i < 2097152) { src = outw; base = 1835008; Kdim = 1024; }
    else if (i < 3145728) { src = w1;   base = 2097152; Kdim = 1024; }
    else if (i < 4194304) { src = w2;   base = 3145728; Kdim = 4096; }
    else                  { src = mem;  base = 4194304; Kdim = 1024; }
    float4 v = ((const float4*)src)[i - base];
    int lin = (i - base) * 4;
    int row = lin / Kdim, col = lin % Kdim;
    size_t off = (size_t)(base << 2) + tile_off(row, col, Kdim);
    *(__half2*)(dst + off)     = __floats2half2_rn(v.x, v.y);
    *(__half2*)(dst + off + 2) = __floats2half2_rn(v.z, v.w);
}

// ---------------------------------------------------------------------------
// LayerNorm -> half tile format (K=1024)
// ---------------------------------------------------------------------------
__global__ __launch_bounds__(256) void ln_kernel(
    const float* __restrict__ x, const float* __restrict__ g,
    const float* __restrict__ be, __half* __restrict__ y)
{
    int row = blockIdx.x;
    const float* xr = x + (size_t)row * DMODEL;
    int c = threadIdx.x * 4;
    float4 v = *(const float4*)(xr + c);
    float s  = v.x + v.y + v.z + v.w;
    float ss = v.x*v.x + v.y*v.y + v.z*v.z + v.w*v.w;
    #pragma unroll
    for (int o = 16; o > 0; o >>= 1) {
        s  += __shfl_xor_sync(0xffffffffu, s,  o);
        ss += __shfl_xor_sync(0xffffffffu, ss, o);
    }
    __shared__ float sm[8], sm2[8];
    int w = threadIdx.x >> 5, lane = threadIdx.x & 31;
    if (lane == 0) { sm[w] = s; sm2[w] = ss; }
    __syncthreads();
    s = 0.f; ss = 0.f;
    #pragma unroll
    for (int i = 0; i < 8; i++) { s += sm[i]; ss += sm2[i]; }
    float mu   = s  * (1.0f / DMODEL);
    float var  = ss * (1.0f / DMODEL) - mu * mu;
    float rstd = rsqrtf(var + 1e-5f);
    float4 gv = *(const float4*)(g + c);
    float4 bv = *(const float4*)(be + c);
    size_t off = tile_off(row, c, 1024);
    *(__half2*)(y + off)     = __floats2half2_rn((v.x - mu) * rstd * gv.x + bv.x,
                                                 (v.y - mu) * rstd * gv.y + bv.y);
    *(__half2*)(y + off + 2) = __floats2half2_rn((v.z - mu) * rstd * gv.z + bv.z,
                                                 (v.w - mu) * rstd * gv.w + bv.w);
}

// ---------------------------------------------------------------------------
// fp16 GEMM (NT) on tile-format operands: C = A[M,K] @ B[N,K]^T
// scatter=1: multi-section QKV epilogue. Section = (col>>10)+secbase:
//   0 -> Cq half [B,H,S,64];  1 -> Ck half (+Cfk fp32);  2 -> Cv (+Cfv).
// scatter=0: halfOut? tile-format(outK) : fp32 linear.
// CTA 128x128x64, 256 thr, warp tile 64x32, 3-stage cp.async.bulk, 2 CTAs/SM.
// ---------------------------------------------------------------------------
#define MBAR_OFF 98304
#define GEMM_SMEM (98304 + 64)

__global__ __launch_bounds__(256, 2) void gemm_f16_kernel(
    const __half* __restrict__ A, const __half* __restrict__ B,
    const float* __restrict__ bias, const float* __restrict__ res,
    void* __restrict__ C, __half* __restrict__ Ck, __half* __restrict__ Cv,
    float* __restrict__ Cfk, float* __restrict__ Cfv,
    int M, int N, int K, int relu, int scatter, int secbase,
    int halfOut, int outK)
{
    uint32_t sbase;
    asm("{ .reg .u64 t; cvta.to.shared.u64 t, %1; cvt.u32.u64 %0, t; }"
        : "=r"(sbase) : "l"((char*)dyn_smem));

    int tid  = threadIdx.x;
    int lane = tid & 31;
    int warp = tid >> 5;
    int g    = lane >> 2;
    int tig  = lane & 3;
    int wm   = warp >> 2;
    int wn   = warp & 3;
    int bx = blockIdx.x, by = blockIdx.y;
    int m0 = by * 128, n0 = bx * 128;
    int TK = K >> 6;
    int NIT = TK;

    if (tid < 3) MBARRIER_INIT(sbase + MBAR_OFF + tid * 8, 1);
    __syncthreads();

    float c[4][4][4];
    #pragma unroll
    for (int i = 0; i < 4; i++)
        #pragma unroll
        for (int j = 0; j < 4; j++)
            #pragma unroll
            for (int f = 0; f < 4; f++) c[i][j][f] = 0.f;

    #define ISSUE_STAGE(s_) do { \
        if (tid == 0) { \
            int s__ = (s_); \
            uint32_t mb = sbase + MBAR_OFF + (s__ % 3) * 8; \
            MBARRIER_EXPECT_TX(mb, 32768u); \
            uint32_t d = sbase + (uint32_t)(s__ % 3) * 32768u; \
            const char* as_ = (const char*)A + ((size_t)(by * TK + s__) << 14); \
            const char* bs_ = (const char*)B + ((size_t)(bx * TK + s__) << 14); \
            bulk_g2s(d,           as_, 16384u, mb); \
            bulk_g2s(d + 16384u,  bs_, 16384u, mb); \
        } \
    } while (0)

    ISSUE_STAGE(0);
    ISSUE_STAGE(1);

    uint32_t ra[4], rb[4];
    #pragma unroll
    for (int mt = 0; mt < 4; mt++) ra[mt] = (uint32_t)((wm*64 + mt*16 + g) * 128);
    #pragma unroll
    for (int nt = 0; nt < 4; nt++) rb[nt] = (uint32_t)((wn*32 + nt*8 + g) * 128);
    uint32_t xr = (uint32_t)(g << 4);

    for (int i = 0; i < NIT; i++) {
        __syncthreads();
        if (i + 2 < NIT) ISSUE_STAGE(i + 2);
        MBARRIER_WAIT_PARITY(sbase + MBAR_OFF + (i % 3) * 8, (i / 3) & 1);

        const char* As = (const char*)dyn_smem + (i % 3) * 32768;
        const char* Bs = As + 16384;

        #pragma unroll
        for (int ks = 0; ks < 4; ks++) {
            uint32_t key  = ((uint32_t)(ks * 32 + tig * 4)) ^ xr;
            uint32_t key2 = key ^ 16u;
            uint32_t af[4][4], bf[4][2];
            #pragma unroll
            for (int mt = 0; mt < 4; mt++) {
                af[mt][0] = *(const uint32_t*)(As + ra[mt] + key);
                af[mt][1] = *(const uint32_t*)(As + ra[mt] + 1024 + key);
                af[mt][2] = *(const uint32_t*)(As + ra[mt] + key2);
                af[mt][3] = *(const uint32_t*)(As + ra[mt] + 1024 + key2);
            }
            #pragma unroll
            for (int nt = 0; nt < 4; nt++) {
                bf[nt][0] = *(const uint32_t*)(Bs + rb[nt] + key);
                bf[nt][1] = *(const uint32_t*)(Bs + rb[nt] + key2);
            }
            #pragma unroll
            for (int mt = 0; mt < 4; mt++)
                #pragma unroll
                for (int nt = 0; nt < 4; nt++)
                    mma_f16(c[mt][nt][0], c[mt][nt][1], c[mt][nt][2], c[mt][nt][3],
                            af[mt][0], af[mt][1], af[mt][2], af[mt][3],
                            bf[nt][0], bf[nt][1]);
        }
    }
    #undef ISSUE_STAGE

    // epilogue
    __half* Ch = (__half*)C;
    float*  Cfl = (float*)C;
    #pragma unroll
    for (int mt = 0; mt < 4; mt++) {
        int row0 = m0 + wm * 64 + mt * 16 + g;
        int row1 = row0 + 8;
        #pragma unroll
        for (int nt = 0; nt < 4; nt++) {
            int col = n0 + wn * 32 + nt * 8 + tig * 2;
            float v00 = c[mt][nt][0], v01 = c[mt][nt][1];
            float v10 = c[mt][nt][2], v11 = c[mt][nt][3];
            if (bias) {
                float b0v = bias[col], b1v = bias[col + 1];
                v00 += b0v; v01 += b1v; v10 += b0v; v11 += b1v;
            }
            if (relu) {
                v00 = fmaxf(v00, 0.f); v01 = fmaxf(v01, 0.f);
                v10 = fmaxf(v10, 0.f); v11 = fmaxf(v11, 0.f);
            }
            if (res) {
                v00 += res[(size_t)row0 * N + col];
                v01 += res[(size_t)row0 * N + col + 1];
                v10 += res[(size_t)row1 * N + col];
                v11 += res[(size_t)row1 * N + col + 1];
            }
            if (scatter) {
                int sec = (col >> 10) + secbase;
                int cl = col & 1023;
                int h_ = cl >> 6, d_ = cl & 63;
                int b0_ = row0 >> 10, s0_ = row0 & 1023;
                int b1_ = row1 >> 10, s1_ = row1 & 1023;
                size_t o0 = (((size_t)(b0_ * 16 + h_) << 10) + s0_) * 64 + d_;
                size_t o1 = (((size_t)(b1_ * 16 + h_) << 10) + s1_) * 64 + d_;
                __half2 hv0 = __floats2half2_rn(v00, v01);
                __half2 hv1 = __floats2half2_rn(v10, v11);
                if (sec == 0) {
                    *(__half2*)(Ch + o0) = hv0;
                    *(__half2*)(Ch + o1) = hv1;
                } else if (sec == 1) {
                    *(__half2*)(Ck + o0) = hv0;
                    *(__half2*)(Ck + o1) = hv1;
                    if (Cfk) {
                        *(float2*)(Cfk + o0) = make_float2(v00, v01);
                        *(float2*)(Cfk + o1) = make_float2(v10, v11);
                    }
                } else {
                    *(__half2*)(Cv + o0) = hv0;
                    *(__half2*)(Cv + o1) = hv1;
                    if (Cfv) {
                        *(float2*)(Cfv + o0) = make_float2(v00, v01);
                        *(float2*)(Cfv + o1) = make_float2(v10, v11);
                    }
                }
            } else if (halfOut) {
                *(__half2*)(Ch + tile_off(row0, col, outK)) = __floats2half2_rn(v00, v01);
                *(__half2*)(Ch + tile_off(row1, col, outK)) = __floats2half2_rn(v10, v11);
            } else {
                *(float2*)(Cfl + (size_t)row0 * N + col) = make_float2(v00, v01);
                *(float2*)(Cfl + (size_t)row1 * N + col) = make_float2(v10, v11);
            }
        }
    }
}

// ---------------------------------------------------------------------------
// Flash attention, fp16 m16n8k16 core, HD=64, Skv=1024.
// Q,K,V half linear [B,H,S,64]; O half tile format (K=1024).
// Smem: Qs/Ks row-major half [64][72]; Vt transposed half [64][72]; Ps half.
// 128 threads = 4 warps, each owns 16 q rows of a 64-row block.
// ---------------------------------------------------------------------------
#define HP 72
#define ATTN_SMEM (4*64*HP*2)    // 36864 B

__global__ __launch_bounds__(128, 4) void attn_kernel(
    const __half* __restrict__ Q, const __half* __restrict__ K,
    const __half* __restrict__ V, __half* __restrict__ O, int causal)
{
    __half* Qs = (__half*)dyn_smem;       // [64][HP] q rows
    __half* Ks = Qs + 64*HP;              // [64][HP] k rows
    __half* Vt = Ks + 64*HP;              // [64][HP] V transposed: Vt[d][c]
    __half* Ps = Vt + 64*HP;              // [64][HP] p rows (warp-private 16)

    int tid  = threadIdx.x;
    int lane = tid & 31;
    int w    = tid >> 5;
    int g    = lane >> 2;
    int tig  = lane & 3;
    int q0 = blockIdx.x * 64;
    int bh = blockIdx.y;

    const __half* Qb = Q + ((size_t)bh * 1024 + q0) * 64;
    const __half* Kb = K + (size_t)bh * 1024 * 64;
    const __half* Vb = V + (size_t)bh * 1024 * 64;

    // load Q tile (64 rows x 128B) straight into row-major half smem
    #pragma unroll
    for (int t = 0; t < 4; t++) {
        int chunk = tid + t * 128;
        int r = chunk >> 3, c8 = (chunk & 7) * 8;
        *(uint4*)&Qs[r*HP + c8] = *(const uint4*)(Qb + r * 64 + c8);
    }

    float o[8][4];
    float m[2], l[2];
    #pragma unroll
    for (int nt = 0; nt < 8; nt++)
        #pragma unroll
        for (int f = 0; f < 4; f++) o[nt][f] = 0.f;
    m[0] = m[1] = -1e30f; l[0] = l[1] = 0.f;

    int rg0 = q0 + w*16 + g;
    int rg1 = rg0 + 8;
    int ntiles = causal ? (blockIdx.x + 1) : 16;

    for (int t = 0; t < ntiles; t++) {
        int k0 = t * 64;
        __syncthreads();
        #pragma unroll
        for (int u = 0; u < 4; u++) {
            int chunk = tid + u * 128;
            int r = chunk >> 3, c8 = (chunk & 7) * 8;
            *(uint4*)&Ks[r*HP + c8] = *(const uint4*)(Kb + (size_t)(k0 + r) * 64 + c8);
            uint4 vraw = *(const uint4*)(Vb + (size_t)(k0 + r) * 64 + c8);
            const __half* vh = (const __half*)&vraw;
            #pragma unroll
            for (int j = 0; j < 8; j++)
                Vt[(c8 + j)*HP + r] = vh[j];
        }
        __syncthreads();

        // S = Q @ K^T  (fp16 mma, 4 k-chunks of 16)
        float s[8][4];
        #pragma unroll
        for (int nt = 0; nt < 8; nt++)
            #pragma unroll
            for (int f = 0; f < 4; f++) s[nt][f] = 0.f;

        const __half* Qw = Qs + (w*16 + g)*HP + tig*2;
        #pragma unroll
        for (int kc = 0; kc < 4; kc++) {
            int kb = kc * 16;
            uint32_t a0 = *(const uint32_t*)(Qw + kb);
            uint32_t a1 = *(const uint32_t*)(Qw + 8*HP + kb);
            uint32_t a2 = *(const uint32_t*)(Qw + kb + 8);
            uint32_t a3 = *(const uint32_t*)(Qw + 8*HP + kb + 8);
            #pragma unroll
            for (int nt = 0; nt < 8; nt++) {
                const __half* Kw = Ks + (nt*8 + g)*HP + kb + tig*2;
                uint32_t b0 = *(const uint32_t*)(Kw);
                uint32_t b1 = *(const uint32_t*)(Kw + 8);
                mma_f16(s[nt][0], s[nt][1], s[nt][2], s[nt][3],
                        a0, a1, a2, a3, b0, b1);
            }
        }

        // scale + causal mask
        #pragma unroll
        for (int nt = 0; nt < 8; nt++) {
            int cg = k0 + nt*8 + tig*2;
            s[nt][0] *= 0.125f; s[nt][1] *= 0.125f;
            s[nt][2] *= 0.125f; s[nt][3] *= 0.125f;
            if (causal) {
                if (cg     > rg0) s[nt][0] = -1e30f;
                if (cg + 1 > rg0) s[nt][1] = -1e30f;
                if (cg     > rg1) s[nt][2] = -1e30f;
                if (cg + 1 > rg1) s[nt][3] = -1e30f;
            }
        }

        // online softmax (rows rg0: [0,1], rg1: [2,3])
        float mx0 = -1e30f, mx1 = -1e30f;
        #pragma unroll
        for (int nt = 0; nt < 8; nt++) {
            mx0 = fmaxf(mx0, fmaxf(s[nt][0], s[nt][1]));
            mx1 = fmaxf(mx1, fmaxf(s[nt][2], s[nt][3]));
        }
        mx0 = fmaxf(mx0, __shfl_xor_sync(0xffffffffu, mx0, 1));
        mx0 = fmaxf(mx0, __shfl_xor_sync(0xffffffffu, mx0, 2));
        mx1 = fmaxf(mx1, __shfl_xor_sync(0xffffffffu, mx1, 1));
        mx1 = fmaxf(mx1, __shfl_xor_sync(0xffffffffu, mx1, 2));

        float mn0 = fmaxf(m[0], mx0), mn1 = fmaxf(m[1], mx1);
        float sc0 = __expf(m[0] - mn0), sc1 = __expf(m[1] - mn1);
        float ls0 = 0.f, ls1 = 0.f;

        __half* Pw = Ps + (w*16)*HP;
        #pragma unroll
        for (int nt = 0; nt < 8; nt++) {
            float p0 = __expf(s[nt][0] - mn0);
            float p1 = __expf(s[nt][1] - mn0);
            float p2 = __expf(s[nt][2] - mn1);
            float p3 = __expf(s[nt][3] - mn1);
            __half2 h01 = __floats2half2_rn(p0, p1);
            __half2 h23 = __floats2half2_rn(p2, p3);
            int cc = nt*8 + tig*2;
            *(__half2*)(Pw + g*HP + cc)     = h01;
            *(__half2*)(Pw + (g+8)*HP + cc) = h23;
            float2 f01 = __half22float2(h01);
            float2 f23 = __half22float2(h23);
            ls0 += f01.x + f01.y;
            ls1 += f23.x + f23.y;
        }
        ls0 += __shfl_xor_sync(0xffffffffu, ls0, 1);
        ls0 += __shfl_xor_sync(0xffffffffu, ls0, 2);
        ls1 += __shfl_xor_sync(0xffffffffu, ls1, 1);
        ls1 += __shfl_xor_sync(0xffffffffu, ls1, 2);
        l[0] = l[0] * sc0 + ls0; m[0] = mn0;
        l[1] = l[1] * sc1 + ls1; m[1] = mn1;
        #pragma unroll
        for (int nt = 0; nt < 8; nt++) {
            o[nt][0] *= sc0; o[nt][1] *= sc0;
            o[nt][2] *= sc1; o[nt][3] *= sc1;
        }
        __syncwarp();

        // O += P @ V  (fp16 mma; B from transposed Vt)
        const __half* Pr = Ps + (w*16 + g)*HP + tig*2;
        #pragma unroll
        for (int kc = 0; kc < 4; kc++) {
            int cb = kc * 16;
            uint32_t a0 = *(const uint32_t*)(Pr + cb);
            uint32_t a1 = *(const uint32_t*)(Pr + 8*HP + cb);
            uint32_t a2 = *(const uint32_t*)(Pr + cb + 8);
            uint32_t a3 = *(const uint32_t*)(Pr + 8*HP + cb + 8);
            #pragma unroll
            for (int nt = 0; nt < 8; nt++) {
                const __half* Vw = Vt + (nt*8 + g)*HP + cb + tig*2;
                uint32_t b0 = *(const uint32_t*)(Vw);
                uint32_t b1 = *(const uint32_t*)(Vw + 8);
                mma_f16(o[nt][0], o[nt][1], o[nt][2], o[nt][3],
                        a0, a1, a2, a3, b0, b1);
            }
        }
    }

    // output in tile format: row = b*1024 + seq, col = h*64 + d, K=1024
    float inv0 = 1.0f / l[0], inv1 = 1.0f / l[1];
    int b_ = bh >> 4, h_ = bh & 15;
    int row0 = b_ * 1024 + rg0;
    int row1 = b_ * 1024 + rg1;
    #pragma unroll
    for (int nt = 0; nt < 8; nt++) {
        int col = h_ * 64 + nt*8 + tig*2;
        *(__half2*)(O + tile_off(row0, col, 1024)) =
            __floats2half2_rn(o[nt][0]*inv0, o[nt][1]*inv0);
        *(__half2*)(O + tile_off(row1, col, 1024)) =
            __floats2half2_rn(o[nt][2]*inv1, o[nt][3]*inv1);
    }
}

// ---------------------------------------------------------------------------
// Host launch
// ---------------------------------------------------------------------------
extern "C" void kernel_launch(void* const* d_in, const int* in_sizes, int n_in,
                              void* d_out, int out_size)
{
    (void)in_sizes; (void)n_in; (void)out_size;
    const float* tgt       = (const float*)d_in[0];
    const float* memory    = (const float*)d_in[1];
    const float* Wq        = (const float*)d_in[2];
    const float* Wk        = (const float*)d_in[3];
    const float* Wv        = (const float*)d_in[4];
    const float* Wo        = (const float*)d_in[5];
    const float* mha_in_w  = (const float*)d_in[6];
    const float* mha_in_b  = (const float*)d_in[7];
    const float* mha_out_w = (const float*)d_in[8];
    const float* mha_out_b = (const float*)d_in[9];
    const float* W1        = (const float*)d_in[10];
    const float* b1        = (const float*)d_in[11];
    const float* W2        = (const float*)d_in[12];
    const float* b2        = (const float*)d_in[13];
    const float* g1        = (const float*)d_in[14];
    const float* be1       = (const float*)d_in[15];
    const float* g2        = (const float*)d_in[16];
    const float* be2       = (const float*)d_in[17];
    const float* g3        = (const float*)d_in[18];
    const float* be3       = (const float*)d_in[19];

    float* xout = (float*)d_out;
    float* kout = xout + (size_t)NELEM;
    float* vout = kout + (size_t)NELEM;

    void *lnp, *qp, *k2p, *v2p, *op, *x1p, *x2p, *h1p, *rwp;
    cudaGetSymbolAddress(&lnp, g_ln);
    cudaGetSymbolAddress(&qp,  g_q);
    cudaGetSymbolAddress(&k2p, g_k2);
    cudaGetSymbolAddress(&v2p, g_v2);
    cudaGetSymbolAddress(&op,  g_o);
    cudaGetSymbolAddress(&x1p, g_x1);
    cudaGetSymbolAddress(&x2p, g_x2);
    cudaGetSymbolAddress(&h1p, g_h1);
    cudaGetSymbolAddress(&rwp, g_rw);

    __half* lnh = (__half*)lnp;
    __half* qh  = (__half*)qp;
    __half* k2h = (__half*)k2p;
    __half* v2h = (__half*)v2p;
    __half* oh  = (__half*)op;
    float*  x1  = (float*)x1p;
    float*  x2  = (float*)x2p;
    __half* h1h = (__half*)h1p;
    __half* rwh = (__half*)rwp;

    cudaFuncSetAttribute(attn_kernel,
        cudaFuncAttributeMaxDynamicSharedMemorySize, ATTN_SMEM);
    cudaFuncSetAttribute(gemm_f16_kernel,
        cudaFuncAttributeMaxDynamicSharedMemorySize, GEMM_SMEM);

    dim3 gQKV (3*DMODEL/128, TOK/128);    // (24, 32) fused self-QKV
    dim3 gKV  (2*DMODEL/128, TOK/128);    // (16, 32) fused cross-KV
    dim3 gProj(DMODEL/128, TOK/128);      // (8, 32)
    dim3 gFF1 (DFF_/128,  TOK/128);       // (32, 32)
    dim3 gAttn(16, 64);

    round_all_kernel<<<20480, 256>>>(Wq, Wk, Wv, Wo, mha_in_w, mha_out_w,
                                     W1, W2, memory, rwh);

    // ---- self-attention (fused QKV) ----
    ln_kernel<<<TOK, 256>>>(tgt, g1, be1, lnh);
    gemm_f16_kernel<<<gQKV, 256, GEMM_SMEM>>>(
        lnh, rwh+RW_WQ, nullptr, nullptr,
        qh, k2h, v2h, kout, vout,
        TOK, 3*DMODEL, DMODEL, 0, 1, 0, 0, 0);
    attn_kernel<<<gAttn, 128, ATTN_SMEM>>>(qh, k2h, v2h, oh, 1);
    gemm_f16_kernel<<<gProj, 256, GEMM_SMEM>>>(
        oh, rwh+RW_WO, nullptr, tgt,
        x1, nullptr, nullptr, nullptr, nullptr,
        TOK, DMODEL, DMODEL, 0, 0, 0, 0, 0);

    // ---- cross-attention (q alone, fused KV) ----
    ln_kernel<<<TOK, 256>>>(x1, g2, be2, lnh);
    gemm_f16_kernel<<<gProj, 256, GEMM_SMEM>>>(
        lnh, rwh+RW_INW, mha_in_b, nullptr,
        qh, nullptr, nullptr, nullptr, nullptr,
        TOK, DMODEL, DMODEL, 0, 1, 0, 0, 0);
    gemm_f16_kernel<<<gKV, 256, GEMM_SMEM>>>(
        rwh+RW_MEM, rwh+RW_INW+1048576, mha_in_b + 1024, nullptr,
        nullptr, k2h, v2h, nullptr, nullptr,
        TOK, 2*DMODEL, DMODEL, 0, 1, 1, 0, 0);
    attn_kernel<<<gAttn, 128, ATTN_SMEM>>>(qh, k2h, v2h, oh, 0);
    gemm_f16_kernel<<<gProj, 256, GEMM_SMEM>>>(
        oh, rwh+RW_OUTW, mha_out_b, x1,
        x2, nullptr, nullptr, nullptr, nullptr,
        TOK, DMODEL, DMODEL, 0, 0, 0, 0, 0);

    // ---- FFN ----
    ln_kernel<<<TOK, 256>>>(x2, g3, be3, lnh);
    gemm_f16_kernel<<<gFF1, 256, GEMM_SMEM>>>(
        lnh, rwh+RW_W1, b1, nullptr,
        h1h, nullptr, nullptr, nullptr, nullptr,
        TOK, DFF_, DMODEL, 1, 0, 0, 1, 4096);
    gemm_f16_kernel<<<gProj, 256, GEMM_SMEM>>>(
        h1h, rwh+RW_W2, b2, x2,
        xout, nullptr, nullptr, nullptr, nullptr,
        TOK, DMODEL, DFF_, 0, 0, 0, 0, 0);
}

// round 11
// speedup vs baseline: 8.5694x; 1.2468x over previous
#include <cuda_runtime.h>
#include <cuda_fp16.h>
#include <math.h>
#include <stdint.h>

// ---------------------------------------------------------------------------
// B=4, S=SM=1024, D=1024, H=16, HD=64, DFF=4096
// Outputs: x[B,S,D], sa_k[B,H,S,HD], sa_v[B,H,S,HD] concatenated in d_out.
//
// fp16 tensor-core pipeline. GEMM operands in "tile format": [R][K] half
// matrix as contiguous 16KB tiles (128 rows x 64 k); inside a tile
// byte(r,c) = r*128 + ((c*2) ^ ((r&7)<<4)). GEMM stages load via
// cp.async.bulk; fragments via ldmatrix. Fused QKV / KV projections.
// ---------------------------------------------------------------------------

#define TOK    4096
#define DMODEL 1024
#define DFF_   4096
#define NELEM  4194304

__device__ float g_ln[NELEM/2];       // half, tile fmt K=1024
__device__ float g_q [NELEM/2];       // half, linear [B,H,S,64]
__device__ float g_k2[NELEM/2];
__device__ float g_v2[NELEM/2];
__device__ float g_o [NELEM/2];       // half, tile fmt K=1024
__device__ float g_x1[NELEM];
__device__ float g_x2[NELEM];
__device__ float g_h1[8388608];       // half, tile fmt K=4096
__device__ float g_rw[10485760];      // half, tile fmt weights+memory

#define RW_WQ   0
#define RW_WK   1048576
#define RW_WV   2097152
#define RW_WO   3145728
#define RW_INW  4194304
#define RW_OUTW 7340032
#define RW_W1   8388608
#define RW_W2   12582912
#define RW_MEM  16777216

extern __shared__ char dyn_smem[];

// half-index into a tile-format matrix with K columns
__device__ __forceinline__ size_t tile_off(int row, int col, int Kdim) {
    size_t tile = (size_t)((row >> 7) * (Kdim >> 6) + (col >> 6));
    uint32_t inb = (uint32_t)(((row & 127) << 7) +
                              ((((col & 63) << 1)) ^ ((row & 7) << 4)));
    return (tile << 13) + (inb >> 1);
}

__device__ __forceinline__ void mma_f16(
    float& c0, float& c1, float& c2, float& c3,
    uint32_t a0, uint32_t a1, uint32_t a2, uint32_t a3,
    uint32_t b0, uint32_t b1)
{
    asm volatile(
        "mma.sync.aligned.m16n8k16.row.col.f32.f16.f16.f32 "
        "{%0,%1,%2,%3}, {%4,%5,%6,%7}, {%8,%9}, {%0,%1,%2,%3};"
        : "+f"(c0), "+f"(c1), "+f"(c2), "+f"(c3)
        : "r"(a0), "r"(a1), "r"(a2), "r"(a3), "r"(b0), "r"(b1));
}

__device__ __forceinline__ void ldm_x4(uint32_t* r, uint32_t addr) {
    asm volatile("ldmatrix.sync.aligned.m8n8.x4.shared.b16 {%0,%1,%2,%3}, [%4];"
        : "=r"(r[0]), "=r"(r[1]), "=r"(r[2]), "=r"(r[3]) : "r"(addr));
}
__device__ __forceinline__ void ldm_x4_t(uint32_t* r, uint32_t addr) {
    asm volatile("ldmatrix.sync.aligned.m8n8.x4.trans.shared.b16 {%0,%1,%2,%3}, [%4];"
        : "=r"(r[0]), "=r"(r[1]), "=r"(r[2]), "=r"(r[3]) : "r"(addr));
}

#define MBARRIER_INIT(mbar, count) \
    asm volatile("mbarrier.init.shared.b64 [%0], %1;" \
        :: "r"((uint32_t)(mbar)), "r"((uint32_t)(count)) : "memory")

#define MBARRIER_EXPECT_TX(mbar, tx) \
    asm volatile("mbarrier.arrive.expect_tx.shared.b64 _, [%0], %1;" \
        :: "r"((uint32_t)(mbar)), "r"((uint32_t)(tx)) : "memory")

#define MBARRIER_WAIT_PARITY(mbar, parity) do { \
    uint32_t _mbar = (uint32_t)(mbar); \
    uint32_t _par  = (uint32_t)(parity); \
    uint32_t _done; \
    asm volatile( \
        "{\n\t.reg .pred p;\n\t" \
        "mbarrier.try_wait.parity.acquire.cta.shared::cta.b64 p, [%1], %2;\n\t" \
        "selp.b32 %0, 1, 0, p;\n\t}" \
        : "=r"(_done) : "r"(_mbar), "r"(_par) : "memory"); \
    if (!_done) { \
        asm volatile( \
            "{\n\t.reg .pred P1;\n\t" \
            "WAIT_LOOP_%=:\n\t" \
            "mbarrier.try_wait.parity.acquire.cta.shared::cta.b64 P1, [%0], %1, 0x989680;\n\t" \
            "@P1 bra.uni WAIT_DONE_%=;\n\t" \
            "bra.uni WAIT_LOOP_%=;\n\t" \
            "WAIT_DONE_%=:\n\t}" \
            :: "r"(_mbar), "r"(_par) : "memory"); \
    } \
} while (0)

__device__ __forceinline__ void bulk_g2s(uint32_t dst, const void* src,
                                         uint32_t bytes, uint32_t mbar) {
    asm volatile(
        "cp.async.bulk.shared::cluster.global.mbarrier::complete_tx::bytes "
        "[%0], [%1], %2, [%3];"
        :: "r"(dst), "l"(src), "r"(bytes), "r"(mbar) : "memory");
}

__device__ __forceinline__ void cp16(uint32_t dst, const void* src) {
    asm volatile("cp.async.cg.shared.global [%0], [%1], 16;"
                 :: "r"(dst), "l"(src));
}

// ---------------------------------------------------------------------------
// Round weights + memory to half into g_rw (tile format per region).
// ---------------------------------------------------------------------------
__global__ __launch_bounds__(256) void round_all_kernel(
    const float* __restrict__ wq, const float* __restrict__ wk,
    const float* __restrict__ wv, const float* __restrict__ wo,
    const float* __restrict__ inw, const float* __restrict__ outw,
    const float* __restrict__ w1, const float* __restrict__ w2,
    const float* __restrict__ mem, __half* __restrict__ dst)
{
    int i = blockIdx.x * 256 + threadIdx.x;   // float4 index, 0..5242879
    const float* src;
    int base, Kdim;
    if      (i < 262144)  { src = wq;   base = 0;       Kdim = 1024; }
    else if (i < 524288)  { src = wk;   base = 262144;  Kdim = 1024; }
    else if (i < 786432)  { src = wv;   base = 524288;  Kdim = 1024; }
    else if (i < 1048576) { src = wo;   base = 786432;  Kdim = 1024; }
    else if (i < 1835008) { src = inw;  base = 1048576; Kdim = 1024; }
    else if (i < 2097152) { src = outw; base = 1835008; Kdim = 1024; }
    else if (i < 3145728) { src = w1;   base = 2097152; Kdim = 1024; }
    else if (i < 4194304) { src = w2;   base = 3145728; Kdim = 4096; }
    else                  { src = mem;  base = 4194304; Kdim = 1024; }
    float4 v = ((const float4*)src)[i - base];
    int lin = (i - base) * 4;
    int row = lin / Kdim, col = lin % Kdim;
    size_t off = (size_t)(base << 2) + tile_off(row, col, Kdim);
    *(__half2*)(dst + off)     = __floats2half2_rn(v.x, v.y);
    *(__half2*)(dst + off + 2) = __floats2half2_rn(v.z, v.w);
}

// ---------------------------------------------------------------------------
// LayerNorm -> half tile format (K=1024)
// ---------------------------------------------------------------------------
__global__ __launch_bounds__(256) void ln_kernel(
    const float* __restrict__ x, const float* __restrict__ g,
    const float* __restrict__ be, __half* __restrict__ y)
{
    int row = blockIdx.x;
    const float* xr = x + (size_t)row * DMODEL;
    int c = threadIdx.x * 4;
    float4 v = *(const float4*)(xr + c);
    float s  = v.x + v.y + v.z + v.w;
    float ss = v.x*v.x + v.y*v.y + v.z*v.z + v.w*v.w;
    #pragma unroll
    for (int o = 16; o > 0; o >>= 1) {
        s  += __shfl_xor_sync(0xffffffffu, s,  o);
        ss += __shfl_xor_sync(0xffffffffu, ss, o);
    }
    __shared__ float sm[8], sm2[8];
    int w = threadIdx.x >> 5, lane = threadIdx.x & 31;
    if (lane == 0) { sm[w] = s; sm2[w] = ss; }
    __syncthreads();
    s = 0.f; ss = 0.f;
    #pragma unroll
    for (int i = 0; i < 8; i++) { s += sm[i]; ss += sm2[i]; }
    float mu   = s  * (1.0f / DMODEL);
    float var  = ss * (1.0f / DMODEL) - mu * mu;
    float rstd = rsqrtf(var + 1e-5f);
    float4 gv = *(const float4*)(g + c);
    float4 bv = *(const float4*)(be + c);
    size_t off = tile_off(row, c, 1024);
    *(__half2*)(y + off)     = __floats2half2_rn((v.x - mu) * rstd * gv.x + bv.x,
                                                 (v.y - mu) * rstd * gv.y + bv.y);
    *(__half2*)(y + off + 2) = __floats2half2_rn((v.z - mu) * rstd * gv.z + bv.z,
                                                 (v.w - mu) * rstd * gv.w + bv.w);
}

// ---------------------------------------------------------------------------
// fp16 GEMM (NT) on tile-format operands: C = A[M,K] @ B[N,K]^T
// cp.async.bulk stage loads; ldmatrix fragment loads.
// CTA 128x128x64, 256 thr, warp tile 64x32, 3 stages, 2 CTAs/SM.
// scatter=1: multi-section QKV epilogue (sec = (col>>10)+secbase).
// ---------------------------------------------------------------------------
#define MBAR_OFF 98304
#define GEMM_SMEM (98304 + 64)

__global__ __launch_bounds__(256, 2) void gemm_f16_kernel(
    const __half* __restrict__ A, const __half* __restrict__ B,
    const float* __restrict__ bias, const float* __restrict__ res,
    void* __restrict__ C, __half* __restrict__ Ck, __half* __restrict__ Cv,
    float* __restrict__ Cfk, float* __restrict__ Cfv,
    int M, int N, int K, int relu, int scatter, int secbase,
    int halfOut, int outK)
{
    uint32_t sbase;
    asm("{ .reg .u64 t; cvta.to.shared.u64 t, %1; cvt.u32.u64 %0, t; }"
        : "=r"(sbase) : "l"((char*)dyn_smem));

    int tid  = threadIdx.x;
    int lane = tid & 31;
    int warp = tid >> 5;
    int g    = lane >> 2;
    int tig  = lane & 3;
    int wm   = warp >> 2;
    int wn   = warp & 3;
    int lrow = lane & 7;
    int lmat = lane >> 3;
    int bx = blockIdx.x, by = blockIdx.y;
    int m0 = by * 128, n0 = bx * 128;
    int TK = K >> 6;
    int NIT = TK;

    if (tid < 3) MBARRIER_INIT(sbase + MBAR_OFF + tid * 8, 1);
    __syncthreads();

    float c[4][4][4];
    #pragma unroll
    for (int i = 0; i < 4; i++)
        #pragma unroll
        for (int j = 0; j < 4; j++)
            #pragma unroll
            for (int f = 0; f < 4; f++) c[i][j][f] = 0.f;

    #define ISSUE_STAGE(s_) do { \
        if (tid == 0) { \
            int s__ = (s_); \
            uint32_t mb = sbase + MBAR_OFF + (s__ % 3) * 8; \
            MBARRIER_EXPECT_TX(mb, 32768u); \
            uint32_t d = sbase + (uint32_t)(s__ % 3) * 32768u; \
            const char* as_ = (const char*)A + ((size_t)(by * TK + s__) << 14); \
            const char* bs_ = (const char*)B + ((size_t)(bx * TK + s__) << 14); \
            bulk_g2s(d,           as_, 16384u, mb); \
            bulk_g2s(d + 16384u,  bs_, 16384u, mb); \
        } \
    } while (0)

    ISSUE_STAGE(0);
    ISSUE_STAGE(1);

    // ldmatrix per-lane geometry (tile format, SW128)
    uint32_t key   = (uint32_t)lrow << 4;
    uint32_t rowA0 = (uint32_t)((wm*64 + (lmat & 1)*8 + lrow) * 128);
    uint32_t cbA   = (uint32_t)((lmat >> 1) * 16);
    uint32_t rowB0 = (uint32_t)((wn*32 + (lmat >> 1)*8 + lrow) * 128);
    uint32_t cbB   = (uint32_t)((lmat & 1) * 16);

    for (int i = 0; i < NIT; i++) {
        __syncthreads();
        if (i + 2 < NIT) ISSUE_STAGE(i + 2);
        MBARRIER_WAIT_PARITY(sbase + MBAR_OFF + (i % 3) * 8, (i / 3) & 1);

        uint32_t stg = sbase + (uint32_t)(i % 3) * 32768u;

        #pragma unroll
        for (int ks = 0; ks < 4; ks++) {
            uint32_t offA = (((uint32_t)(ks * 32)) | cbA) ^ key;
            uint32_t offB = (((uint32_t)(ks * 32)) | cbB) ^ key;
            uint32_t aaddr = stg + rowA0 + offA;
            uint32_t baddr = stg + 16384u + rowB0 + offB;

            uint32_t af[4][4], bf[2][4];
            #pragma unroll
            for (int mt = 0; mt < 4; mt++)
                ldm_x4(af[mt], aaddr + mt * 2048u);
            #pragma unroll
            for (int p = 0; p < 2; p++)
                ldm_x4(bf[p], baddr + p * 2048u);

            #pragma unroll
            for (int mt = 0; mt < 4; mt++) {
                #pragma unroll
                for (int p = 0; p < 2; p++) {
                    mma_f16(c[mt][2*p][0], c[mt][2*p][1], c[mt][2*p][2], c[mt][2*p][3],
                            af[mt][0], af[mt][1], af[mt][2], af[mt][3],
                            bf[p][0], bf[p][1]);
                    mma_f16(c[mt][2*p+1][0], c[mt][2*p+1][1], c[mt][2*p+1][2], c[mt][2*p+1][3],
                            af[mt][0], af[mt][1], af[mt][2], af[mt][3],
                            bf[p][2], bf[p][3]);
                }
            }
        }
    }
    #undef ISSUE_STAGE

    // epilogue
    __half* Ch = (__half*)C;
    float*  Cfl = (float*)C;
    #pragma unroll
    for (int mt = 0; mt < 4; mt++) {
        int row0 = m0 + wm * 64 + mt * 16 + g;
        int row1 = row0 + 8;
        #pragma unroll
        for (int nt = 0; nt < 4; nt++) {
            int col = n0 + wn * 32 + nt * 8 + tig * 2;
            float v00 = c[mt][nt][0], v01 = c[mt][nt][1];
            float v10 = c[mt][nt][2], v11 = c[mt][nt][3];
            if (bias) {
                float b0v = bias[col], b1v = bias[col + 1];
                v00 += b0v; v01 += b1v; v10 += b0v; v11 += b1v;
            }
            if (relu) {
                v00 = fmaxf(v00, 0.f); v01 = fmaxf(v01, 0.f);
                v10 = fmaxf(v10, 0.f); v11 = fmaxf(v11, 0.f);
            }
            if (res) {
                v00 += res[(size_t)row0 * N + col];
                v01 += res[(size_t)row0 * N + col + 1];
                v10 += res[(size_t)row1 * N + col];
                v11 += res[(size_t)row1 * N + col + 1];
            }
            if (scatter) {
                int sec = (col >> 10) + secbase;
                int cl = col & 1023;
                int h_ = cl >> 6, d_ = cl & 63;
                int b0_ = row0 >> 10, s0_ = row0 & 1023;
                int b1_ = row1 >> 10, s1_ = row1 & 1023;
                size_t o0 = (((size_t)(b0_ * 16 + h_) << 10) + s0_) * 64 + d_;
                size_t o1 = (((size_t)(b1_ * 16 + h_) << 10) + s1_) * 64 + d_;
                __half2 hv0 = __floats2half2_rn(v00, v01);
                __half2 hv1 = __floats2half2_rn(v10, v11);
                if (sec == 0) {
                    *(__half2*)(Ch + o0) = hv0;
                    *(__half2*)(Ch + o1) = hv1;
                } else if (sec == 1) {
                    *(__half2*)(Ck + o0) = hv0;
                    *(__half2*)(Ck + o1) = hv1;
                    if (Cfk) {
                        *(float2*)(Cfk + o0) = make_float2(v00, v01);
                        *(float2*)(Cfk + o1) = make_float2(v10, v11);
                    }
                } else {
                    *(__half2*)(Cv + o0) = hv0;
                    *(__half2*)(Cv + o1) = hv1;
                    if (Cfv) {
                        *(float2*)(Cfv + o0) = make_float2(v00, v01);
                        *(float2*)(Cfv + o1) = make_float2(v10, v11);
                    }
                }
            } else if (halfOut) {
                *(__half2*)(Ch + tile_off(row0, col, outK)) = __floats2half2_rn(v00, v01);
                *(__half2*)(Ch + tile_off(row1, col, outK)) = __floats2half2_rn(v10, v11);
            } else {
                *(float2*)(Cfl + (size_t)row0 * N + col) = make_float2(v00, v01);
                *(float2*)(Cfl + (size_t)row1 * N + col) = make_float2(v10, v11);
            }
        }
    }
}

// ---------------------------------------------------------------------------
// Flash attention, fp16 m16n8k16 core + ldmatrix, HD=64, Skv=1024.
// Q,K,V half linear [B,H,S,64]; O half tile format (K=1024).
// Smem (bytes): Q[0,9216), K0[9216), V0[18432), K1[27648), V1[36864),
// P[46080,55296). K/V double-buffered via cp.async. 4 CTAs/SM.
// ---------------------------------------------------------------------------
#define HP 72
#define ATTN_SMEM 55296
#define SOFF_K 9216
#define SOFF_V 18432
#define SOFF_P 46080

__global__ __launch_bounds__(128, 4) void attn_kernel(
    const __half* __restrict__ Q, const __half* __restrict__ K,
    const __half* __restrict__ V, __half* __restrict__ O, int causal)
{
    uint32_t sbase;
    asm("{ .reg .u64 t; cvta.to.shared.u64 t, %1; cvt.u32.u64 %0, t; }"
        : "=r"(sbase) : "l"((char*)dyn_smem));
    __half* Qs = (__half*)dyn_smem;
    __half* Ps = (__half*)(dyn_smem + SOFF_P);

    int tid  = threadIdx.x;
    int lane = tid & 31;
    int w    = tid >> 5;
    int g    = lane >> 2;
    int tig  = lane & 3;
    int lrow = lane & 7;
    int lmat = lane >> 3;
    int q0 = blockIdx.x * 64;
    int bh = blockIdx.y;

    const __half* Qb = Q + ((size_t)bh * 1024 + q0) * 64;
    const __half* Kb = K + (size_t)bh * 1024 * 64;
    const __half* Vb = V + (size_t)bh * 1024 * 64;

    // load Q tile (64 rows x 128B) row-major
    #pragma unroll
    for (int t = 0; t < 4; t++) {
        int chunk = tid + t * 128;
        int r = chunk >> 3, c8 = (chunk & 7) * 8;
        *(uint4*)&Qs[r*HP + c8] = *(const uint4*)(Qb + r * 64 + c8);
    }

    // ldmatrix per-lane geometry (pitch 144B rows, conflict-free)
    uint32_t qrow = (uint32_t)((w*16 + (lmat & 1)*8 + lrow) * 144 + (lmat >> 1) * 16);
    uint32_t krow[4], vrow[4];
    #pragma unroll
    for (int p = 0; p < 4; p++) {
        krow[p] = (uint32_t)((p*16 + (lmat >> 1)*8 + lrow) * 144 + (lmat & 1) * 16);
        vrow[p] = (uint32_t)(((lmat & 1)*8 + lrow) * 144 + (p*16 + (lmat >> 1)*8) * 2);
    }

    float o[8][4];
    float m[2], l[2];
    #pragma unroll
    for (int nt = 0; nt < 8; nt++)
        #pragma unroll
        for (int f = 0; f < 4; f++) o[nt][f] = 0.f;
    m[0] = m[1] = -1e30f; l[0] = l[1] = 0.f;

    int rg0 = q0 + w*16 + g;
    int rg1 = rg0 + 8;
    int ntiles = causal ? (blockIdx.x + 1) : 16;

    // K/V staging via cp.async (double buffer)
    #define STAGE_KV(t_) do { \
        int k0_ = (t_) * 64; \
        uint32_t kb_ = sbase + SOFF_K + ((t_) & 1) * 18432u; \
        uint32_t vb_ = sbase + SOFF_V + ((t_) & 1) * 18432u; \
        _Pragma("unroll") \
        for (int u_ = 0; u_ < 4; u_++) { \
            int ch_ = tid + u_ * 128; \
            int r_ = ch_ >> 3, c16_ = (ch_ & 7) * 16; \
            cp16(kb_ + r_ * 144 + c16_, Kb + (size_t)(k0_ + r_) * 64 + (ch_ & 7) * 8); \
            cp16(vb_ + r_ * 144 + c16_, Vb + (size_t)(k0_ + r_) * 64 + (ch_ & 7) * 8); \
        } \
        asm volatile("cp.async.commit_group;"); \
    } while (0)

    STAGE_KV(0);

    for (int t = 0; t < ntiles; t++) {
        if (t + 1 < ntiles) {
            STAGE_KV(t + 1);
            asm volatile("cp.async.wait_group 1;");
        } else {
            asm volatile("cp.async.wait_group 0;");
        }
        __syncthreads();

        uint32_t kbase = sbase + SOFF_K + (t & 1) * 18432u;
        uint32_t vbase = sbase + SOFF_V + (t & 1) * 18432u;
        int k0 = t * 64;

        // S = Q @ K^T
        float s[8][4];
        #pragma unroll
        for (int nt = 0; nt < 8; nt++)
            #pragma unroll
            for (int f = 0; f < 4; f++) s[nt][f] = 0.f;

        #pragma unroll
        for (int kc = 0; kc < 4; kc++) {
            uint32_t a[4];
            ldm_x4(a, sbase + qrow + kc * 32);
            #pragma unroll
            for (int p = 0; p < 4; p++) {
                uint32_t bq[4];
                ldm_x4(bq, kbase + krow[p] + kc * 32);
                mma_f16(s[2*p][0], s[2*p][1], s[2*p][2], s[2*p][3],
                        a[0], a[1], a[2], a[3], bq[0], bq[1]);
                mma_f16(s[2*p+1][0], s[2*p+1][1], s[2*p+1][2], s[2*p+1][3],
                        a[0], a[1], a[2], a[3], bq[2], bq[3]);
            }
        }

        // scale + causal mask
        #pragma unroll
        for (int nt = 0; nt < 8; nt++) {
            int cg = k0 + nt*8 + tig*2;
            s[nt][0] *= 0.125f; s[nt][1] *= 0.125f;
            s[nt][2] *= 0.125f; s[nt][3] *= 0.125f;
            if (causal) {
                if (cg     > rg0) s[nt][0] = -1e30f;
                if (cg + 1 > rg0) s[nt][1] = -1e30f;
                if (cg     > rg1) s[nt][2] = -1e30f;
                if (cg + 1 > rg1) s[nt][3] = -1e30f;
            }
        }

        // online softmax
        float mx0 = -1e30f, mx1 = -1e30f;
        #pragma unroll
        for (int nt = 0; nt < 8; nt++) {
            mx0 = fmaxf(mx0, fmaxf(s[nt][0], s[nt][1]));
            mx1 = fmaxf(mx1, fmaxf(s[nt][2], s[nt][3]));
        }
        mx0 = fmaxf(mx0, __shfl_xor_sync(0xffffffffu, mx0, 1));
        mx0 = fmaxf(mx0, __shfl_xor_sync(0xffffffffu, mx0, 2));
        mx1 = fmaxf(mx1, __shfl_xor_sync(0xffffffffu, mx1, 1));
        mx1 = fmaxf(mx1, __shfl_xor_sync(0xffffffffu, mx1, 2));

        float mn0 = fmaxf(m[0], mx0), mn1 = fmaxf(m[1], mx1);
        float sc0 = __expf(m[0] - mn0), sc1 = __expf(m[1] - mn1);
        float ls0 = 0.f, ls1 = 0.f;

        __half* Pw = Ps + (w*16)*HP;
        #pragma unroll
        for (int nt = 0; nt < 8; nt++) {
            float p0 = __expf(s[nt][0] - mn0);
            float p1 = __expf(s[nt][1] - mn0);
            float p2 = __expf(s[nt][2] - mn1);
            float p3 = __expf(s[nt][3] - mn1);
            __half2 h01 = __floats2half2_rn(p0, p1);
            __half2 h23 = __floats2half2_rn(p2, p3);
            int cc = nt*8 + tig*2;
            *(__half2*)(Pw + g*HP + cc)     = h01;
            *(__half2*)(Pw + (g+8)*HP + cc) = h23;
            float2 f01 = __half22float2(h01);
            float2 f23 = __half22float2(h23);
            ls0 += f01.x + f01.y;
            ls1 += f23.x + f23.y;
        }
        ls0 += __shfl_xor_sync(0xffffffffu, ls0, 1);
        ls0 += __shfl_xor_sync(0xffffffffu, ls0, 2);
        ls1 += __shfl_xor_sync(0xffffffffu, ls1, 1);
        ls1 += __shfl_xor_sync(0xffffffffu, ls1, 2);
        l[0] = l[0] * sc0 + ls0; m[0] = mn0;
        l[1] = l[1] * sc1 + ls1; m[1] = mn1;
        #pragma unroll
        for (int nt = 0; nt < 8; nt++) {
            o[nt][0] *= sc0; o[nt][1] *= sc0;
            o[nt][2] *= sc1; o[nt][3] *= sc1;
        }
        __syncwarp();

        // O += P @ V  (A from P rows, B via ldmatrix.trans of row-major V)
        #pragma unroll
        for (int kc = 0; kc < 4; kc++) {
            uint32_t a[4];
            ldm_x4(a, sbase + SOFF_P + qrow + kc * 32);
            #pragma unroll
            for (int p = 0; p < 4; p++) {
                uint32_t bv[4];
                ldm_x4_t(bv, vbase + vrow[p] + kc * 2304u);
                mma_f16(o[2*p][0], o[2*p][1], o[2*p][2], o[2*p][3],
                        a[0], a[1], a[2], a[3], bv[0], bv[1]);
                mma_f16(o[2*p+1][0], o[2*p+1][1], o[2*p+1][2], o[2*p+1][3],
                        a[0], a[1], a[2], a[3], bv[2], bv[3]);
            }
        }
        __syncthreads();   // protect K/V buffers before next stage issue
    }
    #undef STAGE_KV

    // output in tile format: row = b*1024 + seq, col = h*64 + d, K=1024
    float inv0 = 1.0f / l[0], inv1 = 1.0f / l[1];
    int b_ = bh >> 4, h_ = bh & 15;
    int row0 = b_ * 1024 + rg0;
    int row1 = b_ * 1024 + rg1;
    #pragma unroll
    for (int nt = 0; nt < 8; nt++) {
        int col = h_ * 64 + nt*8 + tig*2;
        *(__half2*)(O + tile_off(row0, col, 1024)) =
            __floats2half2_rn(o[nt][0]*inv0, o[nt][1]*inv0);
        *(__half2*)(O + tile_off(row1, col, 1024)) =
            __floats2half2_rn(o[nt][2]*inv1, o[nt][3]*inv1);
    }
}

// ---------------------------------------------------------------------------
// Host launch
// ---------------------------------------------------------------------------
extern "C" void kernel_launch(void* const* d_in, const int* in_sizes, int n_in,
                              void* d_out, int out_size)
{
    (void)in_sizes; (void)n_in; (void)out_size;
    const float* tgt       = (const float*)d_in[0];
    const float* memory    = (const float*)d_in[1];
    const float* Wq        = (const float*)d_in[2];
    const float* Wk        = (const float*)d_in[3];
    const float* Wv        = (const float*)d_in[4];
    const float* Wo        = (const float*)d_in[5];
    const float* mha_in_w  = (const float*)d_in[6];
    const float* mha_in_b  = (const float*)d_in[7];
    const float* mha_out_w = (const float*)d_in[8];
    const float* mha_out_b = (const float*)d_in[9];
    const float* W1        = (const float*)d_in[10];
    const float* b1        = (const float*)d_in[11];
    const float* W2        = (const float*)d_in[12];
    const float* b2        = (const float*)d_in[13];
    const float* g1        = (const float*)d_in[14];
    const float* be1       = (const float*)d_in[15];
    const float* g2        = (const float*)d_in[16];
    const float* be2       = (const float*)d_in[17];
    const float* g3        = (const float*)d_in[18];
    const float* be3       = (const float*)d_in[19];

    float* xout = (float*)d_out;
    float* kout = xout + (size_t)NELEM;
    float* vout = kout + (size_t)NELEM;

    void *lnp, *qp, *k2p, *v2p, *op, *x1p, *x2p, *h1p, *rwp;
    cudaGetSymbolAddress(&lnp, g_ln);
    cudaGetSymbolAddress(&qp,  g_q);
    cudaGetSymbolAddress(&k2p, g_k2);
    cudaGetSymbolAddress(&v2p, g_v2);
    cudaGetSymbolAddress(&op,  g_o);
    cudaGetSymbolAddress(&x1p, g_x1);
    cudaGetSymbolAddress(&x2p, g_x2);
    cudaGetSymbolAddress(&h1p, g_h1);
    cudaGetSymbolAddress(&rwp, g_rw);

    __half* lnh = (__half*)lnp;
    __half* qh  = (__half*)qp;
    __half* k2h = (__half*)k2p;
    __half* v2h = (__half*)v2p;
    __half* oh  = (__half*)op;
    float*  x1  = (float*)x1p;
    float*  x2  = (float*)x2p;
    __half* h1h = (__half*)h1p;
    __half* rwh = (__half*)rwp;

    cudaFuncSetAttribute(attn_kernel,
        cudaFuncAttributeMaxDynamicSharedMemorySize, ATTN_SMEM);
    cudaFuncSetAttribute(gemm_f16_kernel,
        cudaFuncAttributeMaxDynamicSharedMemorySize, GEMM_SMEM);

    dim3 gQKV (3*DMODEL/128, TOK/128);    // (24, 32)
    dim3 gKV  (2*DMODEL/128, TOK/128);    // (16, 32)
    dim3 gProj(DMODEL/128, TOK/128);      // (8, 32)
    dim3 gFF1 (DFF_/128,  TOK/128);       // (32, 32)
    dim3 gAttn(16, 64);

    round_all_kernel<<<20480, 256>>>(Wq, Wk, Wv, Wo, mha_in_w, mha_out_w,
                                     W1, W2, memory, rwh);

    // ---- self-attention (fused QKV) ----
    ln_kernel<<<TOK, 256>>>(tgt, g1, be1, lnh);
    gemm_f16_kernel<<<gQKV, 256, GEMM_SMEM>>>(
        lnh, rwh+RW_WQ, nullptr, nullptr,
        qh, k2h, v2h, kout, vout,
        TOK, 3*DMODEL, DMODEL, 0, 1, 0, 0, 0);
    attn_kernel<<<gAttn, 128, ATTN_SMEM>>>(qh, k2h, v2h, oh, 1);
    gemm_f16_kernel<<<gProj, 256, GEMM_SMEM>>>(
        oh, rwh+RW_WO, nullptr, tgt,
        x1, nullptr, nullptr, nullptr, nullptr,
        TOK, DMODEL, DMODEL, 0, 0, 0, 0, 0);

    // ---- cross-attention (q alone, fused KV) ----
    ln_kernel<<<TOK, 256>>>(x1, g2, be2, lnh);
    gemm_f16_kernel<<<gProj, 256, GEMM_SMEM>>>(
        lnh, rwh+RW_INW, mha_in_b, nullptr,
        qh, nullptr, nullptr, nullptr, nullptr,
        TOK, DMODEL, DMODEL, 0, 1, 0, 0, 0);
    gemm_f16_kernel<<<gKV, 256, GEMM_SMEM>>>(
        rwh+RW_MEM, rwh+RW_INW+1048576, mha_in_b + 1024, nullptr,
        nullptr, k2h, v2h, nullptr, nullptr,
        TOK, 2*DMODEL, DMODEL, 0, 1, 1, 0, 0);
    attn_kernel<<<gAttn, 128, ATTN_SMEM>>>(qh, k2h, v2h, oh, 0);
    gemm_f16_kernel<<<gProj, 256, GEMM_SMEM>>>(
        oh, rwh+RW_OUTW, mha_out_b, x1,
        x2, nullptr, nullptr, nullptr, nullptr,
        TOK, DMODEL, DMODEL, 0, 0, 0, 0, 0);

    // ---- FFN ----
    ln_kernel<<<TOK, 256>>>(x2, g3, be3, lnh);
    gemm_f16_kernel<<<gFF1, 256, GEMM_SMEM>>>(
        lnh, rwh+RW_W1, b1, nullptr,
        h1h, nullptr, nullptr, nullptr, nullptr,
        TOK, DFF_, DMODEL, 1, 0, 0, 1, 4096);
    gemm_f16_kernel<<<gProj, 256, GEMM_SMEM>>>(
        h1h, rwh+RW_W2, b2, x2,
        xout, nullptr, nullptr, nullptr, nullptr,
        TOK, DMODEL, DFF_, 0, 0, 0, 0, 0);
}

// round 12
// speedup vs baseline: 8.7719x; 1.0236x over previous
#include <cuda_runtime.h>
#include <cuda_fp16.h>
#include <math.h>
#include <stdint.h>

// ---------------------------------------------------------------------------
// B=4, S=SM=1024, D=1024, H=16, HD=64, DFF=4096
// Outputs: x[B,S,D], sa_k[B,H,S,HD], sa_v[B,H,S,HD] concatenated in d_out.
//
// fp16 tensor-core pipeline. GEMM operands in "tile format": [R][K] half
// matrix as contiguous 16KB tiles (128 rows x 64 k); inside a tile
// byte(r,c) = r*128 + ((c*2) ^ ((r&7)<<4)). GEMM stages load via
// cp.async.bulk; fragments via ldmatrix. Fused QKV / KV projections.
// Attention: register-resident P (FA2), exp2-domain softmax with the
// 0.125*log2e factor folded into the Q projection epilogue.
// ---------------------------------------------------------------------------

#define TOK    4096
#define DMODEL 1024
#define DFF_   4096
#define NELEM  4194304

#define QSCALE 0.18033688011112042f   // 0.125 * log2(e)

__device__ float g_ln[NELEM/2];       // half, tile fmt K=1024
__device__ float g_q [NELEM/2];       // half, linear [B,H,S,64]
__device__ float g_k2[NELEM/2];
__device__ float g_v2[NELEM/2];
__device__ float g_o [NELEM/2];       // half, tile fmt K=1024
__device__ float g_x1[NELEM];
__device__ float g_x2[NELEM];
__device__ float g_h1[8388608];       // half, tile fmt K=4096
__device__ float g_rw[10485760];      // half, tile fmt weights+memory

#define RW_WQ   0
#define RW_WK   1048576
#define RW_WV   2097152
#define RW_WO   3145728
#define RW_INW  4194304
#define RW_OUTW 7340032
#define RW_W1   8388608
#define RW_W2   12582912
#define RW_MEM  16777216

extern __shared__ char dyn_smem[];

// half-index into a tile-format matrix with K columns
__device__ __forceinline__ size_t tile_off(int row, int col, int Kdim) {
    size_t tile = (size_t)((row >> 7) * (Kdim >> 6) + (col >> 6));
    uint32_t inb = (uint32_t)(((row & 127) << 7) +
                              ((((col & 63) << 1)) ^ ((row & 7) << 4)));
    return (tile << 13) + (inb >> 1);
}

__device__ __forceinline__ void mma_f16(
    float& c0, float& c1, float& c2, float& c3,
    uint32_t a0, uint32_t a1, uint32_t a2, uint32_t a3,
    uint32_t b0, uint32_t b1)
{
    asm volatile(
        "mma.sync.aligned.m16n8k16.row.col.f32.f16.f16.f32 "
        "{%0,%1,%2,%3}, {%4,%5,%6,%7}, {%8,%9}, {%0,%1,%2,%3};"
        : "+f"(c0), "+f"(c1), "+f"(c2), "+f"(c3)
        : "r"(a0), "r"(a1), "r"(a2), "r"(a3), "r"(b0), "r"(b1));
}

__device__ __forceinline__ void ldm_x4(uint32_t* r, uint32_t addr) {
    asm volatile("ldmatrix.sync.aligned.m8n8.x4.shared.b16 {%0,%1,%2,%3}, [%4];"
        : "=r"(r[0]), "=r"(r[1]), "=r"(r[2]), "=r"(r[3]) : "r"(addr));
}
__device__ __forceinline__ void ldm_x4_t(uint32_t* r, uint32_t addr) {
    asm volatile("ldmatrix.sync.aligned.m8n8.x4.trans.shared.b16 {%0,%1,%2,%3}, [%4];"
        : "=r"(r[0]), "=r"(r[1]), "=r"(r[2]), "=r"(r[3]) : "r"(addr));
}

#define MBARRIER_INIT(mbar, count) \
    asm volatile("mbarrier.init.shared.b64 [%0], %1;" \
        :: "r"((uint32_t)(mbar)), "r"((uint32_t)(count)) : "memory")

#define MBARRIER_EXPECT_TX(mbar, tx) \
    asm volatile("mbarrier.arrive.expect_tx.shared.b64 _, [%0], %1;" \
        :: "r"((uint32_t)(mbar)), "r"((uint32_t)(tx)) : "memory")

#define MBARRIER_WAIT_PARITY(mbar, parity) do { \
    uint32_t _mbar = (uint32_t)(mbar); \
    uint32_t _par  = (uint32_t)(parity); \
    uint32_t _done; \
    asm volatile( \
        "{\n\t.reg .pred p;\n\t" \
        "mbarrier.try_wait.parity.acquire.cta.shared::cta.b64 p, [%1], %2;\n\t" \
        "selp.b32 %0, 1, 0, p;\n\t}" \
        : "=r"(_done) : "r"(_mbar), "r"(_par) : "memory"); \
    if (!_done) { \
        asm volatile( \
            "{\n\t.reg .pred P1;\n\t" \
            "WAIT_LOOP_%=:\n\t" \
            "mbarrier.try_wait.parity.acquire.cta.shared::cta.b64 P1, [%0], %1, 0x989680;\n\t" \
            "@P1 bra.uni WAIT_DONE_%=;\n\t" \
            "bra.uni WAIT_LOOP_%=;\n\t" \
            "WAIT_DONE_%=:\n\t}" \
            :: "r"(_mbar), "r"(_par) : "memory"); \
    } \
} while (0)

__device__ __forceinline__ void bulk_g2s(uint32_t dst, const void* src,
                                         uint32_t bytes, uint32_t mbar) {
    asm volatile(
        "cp.async.bulk.shared::cluster.global.mbarrier::complete_tx::bytes "
        "[%0], [%1], %2, [%3];"
        :: "r"(dst), "l"(src), "r"(bytes), "r"(mbar) : "memory");
}

__device__ __forceinline__ void cp16(uint32_t dst, const void* src) {
    asm volatile("cp.async.cg.shared.global [%0], [%1], 16;"
                 :: "r"(dst), "l"(src));
}

// ---------------------------------------------------------------------------
// Round weights + memory to half into g_rw (tile format per region).
// ---------------------------------------------------------------------------
__global__ __launch_bounds__(256) void round_all_kernel(
    const float* __restrict__ wq, const float* __restrict__ wk,
    const float* __restrict__ wv, const float* __restrict__ wo,
    const float* __restrict__ inw, const float* __restrict__ outw,
    const float* __restrict__ w1, const float* __restrict__ w2,
    const float* __restrict__ mem, __half* __restrict__ dst)
{
    int i = blockIdx.x * 256 + threadIdx.x;   // float4 index, 0..5242879
    const float* src;
    int base, Kdim;
    if      (i < 262144)  { src = wq;   base = 0;       Kdim = 1024; }
    else if (i < 524288)  { src = wk;   base = 262144;  Kdim = 1024; }
    else if (i < 786432)  { src = wv;   base = 524288;  Kdim = 1024; }
    else if (i < 1048576) { src = wo;   base = 786432;  Kdim = 1024; }
    else if (i < 1835008) { src = inw;  base = 1048576; Kdim = 1024; }
    else if (i < 2097152) { src = outw; base = 1835008; Kdim = 1024; }
    else if (i < 3145728) { src = w1;   base = 2097152; Kdim = 1024; }
    else if (i < 4194304) { src = w2;   base = 3145728; Kdim = 4096; }
    else                  { src = mem;  base = 4194304; Kdim = 1024; }
    float4 v = ((const float4*)src)[i - base];
    int lin = (i - base) * 4;
    int row = lin / Kdim, col = lin % Kdim;
    size_t off = (size_t)(base << 2) + tile_off(row, col, Kdim);
    *(__half2*)(dst + off)     = __floats2half2_rn(v.x, v.y);
    *(__half2*)(dst + off + 2) = __floats2half2_rn(v.z, v.w);
}

// ---------------------------------------------------------------------------
// LayerNorm -> half tile format (K=1024)
// ---------------------------------------------------------------------------
__global__ __launch_bounds__(256) void ln_kernel(
    const float* __restrict__ x, const float* __restrict__ g,
    const float* __restrict__ be, __half* __restrict__ y)
{
    int row = blockIdx.x;
    const float* xr = x + (size_t)row * DMODEL;
    int c = threadIdx.x * 4;
    float4 v = *(const float4*)(xr + c);
    float s  = v.x + v.y + v.z + v.w;
    float ss = v.x*v.x + v.y*v.y + v.z*v.z + v.w*v.w;
    #pragma unroll
    for (int o = 16; o > 0; o >>= 1) {
        s  += __shfl_xor_sync(0xffffffffu, s,  o);
        ss += __shfl_xor_sync(0xffffffffu, ss, o);
    }
    __shared__ float sm[8], sm2[8];
    int w = threadIdx.x >> 5, lane = threadIdx.x & 31;
    if (lane == 0) { sm[w] = s; sm2[w] = ss; }
    __syncthreads();
    s = 0.f; ss = 0.f;
    #pragma unroll
    for (int i = 0; i < 8; i++) { s += sm[i]; ss += sm2[i]; }
    float mu   = s  * (1.0f / DMODEL);
    float var  = ss * (1.0f / DMODEL) - mu * mu;
    float rstd = rsqrtf(var + 1e-5f);
    float4 gv = *(const float4*)(g + c);
    float4 bv = *(const float4*)(be + c);
    size_t off = tile_off(row, c, 1024);
    *(__half2*)(y + off)     = __floats2half2_rn((v.x - mu) * rstd * gv.x + bv.x,
                                                 (v.y - mu) * rstd * gv.y + bv.y);
    *(__half2*)(y + off + 2) = __floats2half2_rn((v.z - mu) * rstd * gv.z + bv.z,
                                                 (v.w - mu) * rstd * gv.w + bv.w);
}

// ---------------------------------------------------------------------------
// fp16 GEMM (NT) on tile-format operands: C = A[M,K] @ B[N,K]^T
// cp.async.bulk stage loads; ldmatrix fragment loads.
// CTA 128x128x64, 256 thr, warp tile 64x32, 3 stages, 2 CTAs/SM.
// scatter=1: multi-section QKV epilogue (sec = (col>>10)+secbase).
// Section 0 (q) is additionally scaled by QSCALE (softmax prescale).
// ---------------------------------------------------------------------------
#define MBAR_OFF 98304
#define GEMM_SMEM (98304 + 64)

__global__ __launch_bounds__(256, 2) void gemm_f16_kernel(
    const __half* __restrict__ A, const __half* __restrict__ B,
    const float* __restrict__ bias, const float* __restrict__ res,
    void* __restrict__ C, __half* __restrict__ Ck, __half* __restrict__ Cv,
    float* __restrict__ Cfk, float* __restrict__ Cfv,
    int M, int N, int K, int relu, int scatter, int secbase,
    int halfOut, int outK)
{
    uint32_t sbase;
    asm("{ .reg .u64 t; cvta.to.shared.u64 t, %1; cvt.u32.u64 %0, t; }"
        : "=r"(sbase) : "l"((char*)dyn_smem));

    int tid  = threadIdx.x;
    int lane = tid & 31;
    int warp = tid >> 5;
    int g    = lane >> 2;
    int tig  = lane & 3;
    int wm   = warp >> 2;
    int wn   = warp & 3;
    int lrow = lane & 7;
    int lmat = lane >> 3;
    int bx = blockIdx.x, by = blockIdx.y;
    int m0 = by * 128, n0 = bx * 128;
    int TK = K >> 6;
    int NIT = TK;

    if (tid < 3) MBARRIER_INIT(sbase + MBAR_OFF + tid * 8, 1);
    __syncthreads();

    float c[4][4][4];
    #pragma unroll
    for (int i = 0; i < 4; i++)
        #pragma unroll
        for (int j = 0; j < 4; j++)
            #pragma unroll
            for (int f = 0; f < 4; f++) c[i][j][f] = 0.f;

    #define ISSUE_STAGE(s_) do { \
        if (tid == 0) { \
            int s__ = (s_); \
            uint32_t mb = sbase + MBAR_OFF + (s__ % 3) * 8; \
            MBARRIER_EXPECT_TX(mb, 32768u); \
            uint32_t d = sbase + (uint32_t)(s__ % 3) * 32768u; \
            const char* as_ = (const char*)A + ((size_t)(by * TK + s__) << 14); \
            const char* bs_ = (const char*)B + ((size_t)(bx * TK + s__) << 14); \
            bulk_g2s(d,           as_, 16384u, mb); \
            bulk_g2s(d + 16384u,  bs_, 16384u, mb); \
        } \
    } while (0)

    ISSUE_STAGE(0);
    ISSUE_STAGE(1);

    uint32_t key   = (uint32_t)lrow << 4;
    uint32_t rowA0 = (uint32_t)((wm*64 + (lmat & 1)*8 + lrow) * 128);
    uint32_t cbA   = (uint32_t)((lmat >> 1) * 16);
    uint32_t rowB0 = (uint32_t)((wn*32 + (lmat >> 1)*8 + lrow) * 128);
    uint32_t cbB   = (uint32_t)((lmat & 1) * 16);

    for (int i = 0; i < NIT; i++) {
        __syncthreads();
        if (i + 2 < NIT) ISSUE_STAGE(i + 2);
        MBARRIER_WAIT_PARITY(sbase + MBAR_OFF + (i % 3) * 8, (i / 3) & 1);

        uint32_t stg = sbase + (uint32_t)(i % 3) * 32768u;

        #pragma unroll
        for (int ks = 0; ks < 4; ks++) {
            uint32_t offA = (((uint32_t)(ks * 32)) | cbA) ^ key;
            uint32_t offB = (((uint32_t)(ks * 32)) | cbB) ^ key;
            uint32_t aaddr = stg + rowA0 + offA;
            uint32_t baddr = stg + 16384u + rowB0 + offB;

            uint32_t af[4][4], bf[2][4];
            #pragma unroll
            for (int mt = 0; mt < 4; mt++)
                ldm_x4(af[mt], aaddr + mt * 2048u);
            #pragma unroll
            for (int p = 0; p < 2; p++)
                ldm_x4(bf[p], baddr + p * 2048u);

            #pragma unroll
            for (int mt = 0; mt < 4; mt++) {
                #pragma unroll
                for (int p = 0; p < 2; p++) {
                    mma_f16(c[mt][2*p][0], c[mt][2*p][1], c[mt][2*p][2], c[mt][2*p][3],
                            af[mt][0], af[mt][1], af[mt][2], af[mt][3],
                            bf[p][0], bf[p][1]);
                    mma_f16(c[mt][2*p+1][0], c[mt][2*p+1][1], c[mt][2*p+1][2], c[mt][2*p+1][3],
                            af[mt][0], af[mt][1], af[mt][2], af[mt][3],
                            bf[p][2], bf[p][3]);
                }
            }
        }
    }
    #undef ISSUE_STAGE

    // epilogue
    __half* Ch = (__half*)C;
    float*  Cfl = (float*)C;
    #pragma unroll
    for (int mt = 0; mt < 4; mt++) {
        int row0 = m0 + wm * 64 + mt * 16 + g;
        int row1 = row0 + 8;
        #pragma unroll
        for (int nt = 0; nt < 4; nt++) {
            int col = n0 + wn * 32 + nt * 8 + tig * 2;
            float v00 = c[mt][nt][0], v01 = c[mt][nt][1];
            float v10 = c[mt][nt][2], v11 = c[mt][nt][3];
            if (bias) {
                float b0v = bias[col], b1v = bias[col + 1];
                v00 += b0v; v01 += b1v; v10 += b0v; v11 += b1v;
            }
            if (relu) {
                v00 = fmaxf(v00, 0.f); v01 = fmaxf(v01, 0.f);
                v10 = fmaxf(v10, 0.f); v11 = fmaxf(v11, 0.f);
            }
            if (res) {
                v00 += res[(size_t)row0 * N + col];
                v01 += res[(size_t)row0 * N + col + 1];
                v10 += res[(size_t)row1 * N + col];
                v11 += res[(size_t)row1 * N + col + 1];
            }
            if (scatter) {
                int sec = (col >> 10) + secbase;
                int cl = col & 1023;
                int h_ = cl >> 6, d_ = cl & 63;
                int b0_ = row0 >> 10, s0_ = row0 & 1023;
                int b1_ = row1 >> 10, s1_ = row1 & 1023;
                size_t o0 = (((size_t)(b0_ * 16 + h_) << 10) + s0_) * 64 + d_;
                size_t o1 = (((size_t)(b1_ * 16 + h_) << 10) + s1_) * 64 + d_;
                if (sec == 0) {
                    // q: fold softmax prescale (0.125 * log2e)
                    *(__half2*)(Ch + o0) =
                        __floats2half2_rn(v00 * QSCALE, v01 * QSCALE);
                    *(__half2*)(Ch + o1) =
                        __floats2half2_rn(v10 * QSCALE, v11 * QSCALE);
                } else if (sec == 1) {
                    *(__half2*)(Ck + o0) = __floats2half2_rn(v00, v01);
                    *(__half2*)(Ck + o1) = __floats2half2_rn(v10, v11);
                    if (Cfk) {
                        *(float2*)(Cfk + o0) = make_float2(v00, v01);
                        *(float2*)(Cfk + o1) = make_float2(v10, v11);
                    }
                } else {
                    *(__half2*)(Cv + o0) = __floats2half2_rn(v00, v01);
                    *(__half2*)(Cv + o1) = __floats2half2_rn(v10, v11);
                    if (Cfv) {
                        *(float2*)(Cfv + o0) = make_float2(v00, v01);
                        *(float2*)(Cfv + o1) = make_float2(v10, v11);
                    }
                }
            } else if (halfOut) {
                *(__half2*)(Ch + tile_off(row0, col, outK)) = __floats2half2_rn(v00, v01);
                *(__half2*)(Ch + tile_off(row1, col, outK)) = __floats2half2_rn(v10, v11);
            } else {
                *(float2*)(Cfl + (size_t)row0 * N + col) = make_float2(v00, v01);
                *(float2*)(Cfl + (size_t)row1 * N + col) = make_float2(v10, v11);
            }
        }
    }
}

// ---------------------------------------------------------------------------
// Flash attention, fp16 m16n8k16 + ldmatrix, register-resident P.
// Q prescaled by QSCALE -> scores are in log2 domain; softmax uses exp2f.
// Causal mask applied only on the diagonal tile.
// Smem: Q[0,9216), K0[9216), V0[18432), K1[27648), V1[36864,46080).
// ---------------------------------------------------------------------------
#define HP 72
#define ATTN_SMEM 46080
#define SOFF_K 9216
#define SOFF_V 18432

__global__ __launch_bounds__(128, 4) void attn_kernel(
    const __half* __restrict__ Q, const __half* __restrict__ K,
    const __half* __restrict__ V, __half* __restrict__ O, int causal)
{
    uint32_t sbase;
    asm("{ .reg .u64 t; cvta.to.shared.u64 t, %1; cvt.u32.u64 %0, t; }"
        : "=r"(sbase) : "l"((char*)dyn_smem));
    __half* Qs = (__half*)dyn_smem;

    int tid  = threadIdx.x;
    int lane = tid & 31;
    int w    = tid >> 5;
    int g    = lane >> 2;
    int tig  = lane & 3;
    int lrow = lane & 7;
    int lmat = lane >> 3;
    int q0 = blockIdx.x * 64;
    int bh = blockIdx.y;

    const __half* Qb = Q + ((size_t)bh * 1024 + q0) * 64;
    const __half* Kb = K + (size_t)bh * 1024 * 64;
    const __half* Vb = V + (size_t)bh * 1024 * 64;

    #pragma unroll
    for (int t = 0; t < 4; t++) {
        int chunk = tid + t * 128;
        int r = chunk >> 3, c8 = (chunk & 7) * 8;
        *(uint4*)&Qs[r*HP + c8] = *(const uint4*)(Qb + r * 64 + c8);
    }

    uint32_t qrow = (uint32_t)((w*16 + (lmat & 1)*8 + lrow) * 144 + (lmat >> 1) * 16);
    uint32_t krow[4], vrow[4];
    #pragma unroll
    for (int p = 0; p < 4; p++) {
        krow[p] = (uint32_t)((p*16 + (lmat >> 1)*8 + lrow) * 144 + (lmat & 1) * 16);
        vrow[p] = (uint32_t)(((lmat & 1)*8 + lrow) * 144 + (p*16 + (lmat >> 1)*8) * 2);
    }

    float o[8][4];
    float m0v = -1e30f, m1v = -1e30f, l0 = 0.f, l1 = 0.f;
    #pragma unroll
    for (int nt = 0; nt < 8; nt++)
        #pragma unroll
        for (int f = 0; f < 4; f++) o[nt][f] = 0.f;

    int rg0 = q0 + w*16 + g;
    int rg1 = rg0 + 8;
    int nfull  = causal ? blockIdx.x : 16;
    int ntiles = causal ? nfull + 1 : nfull;

    #define STAGE_KV(t_) do { \
        int k0_ = (t_) * 64; \
        uint32_t kb_ = sbase + SOFF_K + ((t_) & 1) * 18432u; \
        uint32_t vb_ = kb_ + 9216u; \
        _Pragma("unroll") \
        for (int u_ = 0; u_ < 4; u_++) { \
            int ch_ = tid + u_ * 128; \
            int r_ = ch_ >> 3, c16_ = (ch_ & 7) * 16; \
            cp16(kb_ + r_ * 144 + c16_, Kb + (size_t)(k0_ + r_) * 64 + (ch_ & 7) * 8); \
            cp16(vb_ + r_ * 144 + c16_, Vb + (size_t)(k0_ + r_) * 64 + (ch_ & 7) * 8); \
        } \
        asm volatile("cp.async.commit_group;"); \
    } while (0)

    STAGE_KV(0);

    for (int t = 0; t < ntiles; t++) {
        if (t + 1 < ntiles) {
            STAGE_KV(t + 1);
            asm volatile("cp.async.wait_group 1;");
        } else {
            asm volatile("cp.async.wait_group 0;");
        }
        __syncthreads();

        uint32_t kbase = sbase + SOFF_K + (t & 1) * 18432u;
        uint32_t vbase = kbase + 9216u;
        int k0 = t * 64;

        // S = Q @ K^T  (scores already in log2 domain)
        float s[8][4];
        #pragma unroll
        for (int nt = 0; nt < 8; nt++)
            #pragma unroll
            for (int f = 0; f < 4; f++) s[nt][f] = 0.f;

        #pragma unroll
        for (int kc = 0; kc < 4; kc++) {
            uint32_t a[4];
            ldm_x4(a, sbase + qrow + kc * 32);
            #pragma unroll
            for (int p = 0; p < 4; p++) {
                uint32_t bq[4];
                ldm_x4(bq, kbase + krow[p] + kc * 32);
                mma_f16(s[2*p][0], s[2*p][1], s[2*p][2], s[2*p][3],
                        a[0], a[1], a[2], a[3], bq[0], bq[1]);
                mma_f16(s[2*p+1][0], s[2*p+1][1], s[2*p+1][2], s[2*p+1][3],
                        a[0], a[1], a[2], a[3], bq[2], bq[3]);
            }
        }

        // causal mask only on the diagonal tile
        if (causal && t == nfull) {
            #pragma unroll
            for (int nt = 0; nt < 8; nt++) {
                int cg = k0 + nt*8 + tig*2;
                if (cg     > rg0) s[nt][0] = -1e30f;
                if (cg + 1 > rg0) s[nt][1] = -1e30f;
                if (cg     > rg1) s[nt][2] = -1e30f;
                if (cg + 1 > rg1) s[nt][3] = -1e30f;
            }
        }

        // online softmax (exp2 domain)
        float mx0 = -1e30f, mx1 = -1e30f;
        #pragma unroll
        for (int nt = 0; nt < 8; nt++) {
            mx0 = fmaxf(mx0, fmaxf(s[nt][0], s[nt][1]));
            mx1 = fmaxf(mx1, fmaxf(s[nt][2], s[nt][3]));
        }
        mx0 = fmaxf(mx0, __shfl_xor_sync(0xffffffffu, mx0, 1));
        mx0 = fmaxf(mx0, __shfl_xor_sync(0xffffffffu, mx0, 2));
        mx1 = fmaxf(mx1, __shfl_xor_sync(0xffffffffu, mx1, 1));
        mx1 = fmaxf(mx1, __shfl_xor_sync(0xffffffffu, mx1, 2));

        float mn0 = fmaxf(m0v, mx0), mn1 = fmaxf(m1v, mx1);
        float sc0 = exp2f(m0v - mn0), sc1 = exp2f(m1v - mn1);
        float ls0 = 0.f, ls1 = 0.f;

        // P stays in registers as mma A-fragments (half2 pairs)
        uint32_t pah[8], pal[8];
        #pragma unroll
        for (int nt = 0; nt < 8; nt++) {
            float p0 = exp2f(s[nt][0] - mn0);
            float p1 = exp2f(s[nt][1] - mn0);
            float p2 = exp2f(s[nt][2] - mn1);
            float p3 = exp2f(s[nt][3] - mn1);
            __half2 h01 = __floats2half2_rn(p0, p1);
            __half2 h23 = __floats2half2_rn(p2, p3);
            pah[nt] = *(uint32_t*)&h01;
            pal[nt] = *(uint32_t*)&h23;
            float2 f01 = __half22float2(h01);
            float2 f23 = __half22float2(h23);
            ls0 += f01.x + f01.y;
            ls1 += f23.x + f23.y;
        }
        ls0 += __shfl_xor_sync(0xffffffffu, ls0, 1);
        ls0 += __shfl_xor_sync(0xffffffffu, ls0, 2);
        ls1 += __shfl_xor_sync(0xffffffffu, ls1, 1);
        ls1 += __shfl_xor_sync(0xffffffffu, ls1, 2);
        l0 = l0 * sc0 + ls0; m0v = mn0;
        l1 = l1 * sc1 + ls1; m1v = mn1;
        #pragma unroll
        for (int nt = 0; nt < 8; nt++) {
            o[nt][0] *= sc0; o[nt][1] *= sc0;
            o[nt][2] *= sc1; o[nt][3] *= sc1;
        }

        // O += P @ V  (A = register P fragments, B via ldmatrix.trans)
        #pragma unroll
        for (int kc = 0; kc < 4; kc++) {
            uint32_t a0 = pah[2*kc],   a1 = pal[2*kc];
            uint32_t a2 = pah[2*kc+1], a3 = pal[2*kc+1];
            #pragma unroll
            for (int p = 0; p < 4; p++) {
                uint32_t bv[4];
                ldm_x4_t(bv, vbase + vrow[p] + kc * 2304u);
                mma_f16(o[2*p][0], o[2*p][1], o[2*p][2], o[2*p][3],
                        a0, a1, a2, a3, bv[0], bv[1]);
                mma_f16(o[2*p+1][0], o[2*p+1][1], o[2*p+1][2], o[2*p+1][3],
                        a0, a1, a2, a3, bv[2], bv[3]);
            }
        }
        __syncthreads();   // protect K/V buffers before next stage write
    }
    #undef STAGE_KV

    // output in tile format: row = b*1024 + seq, col = h*64 + d, K=1024
    float inv0 = 1.0f / l0, inv1 = 1.0f / l1;
    int b_ = bh >> 4, h_ = bh & 15;
    int row0 = b_ * 1024 + rg0;
    int row1 = b_ * 1024 + rg1;
    #pragma unroll
    for (int nt = 0; nt < 8; nt++) {
        int col = h_ * 64 + nt*8 + tig*2;
        *(__half2*)(O + tile_off(row0, col, 1024)) =
            __floats2half2_rn(o[nt][0]*inv0, o[nt][1]*inv0);
        *(__half2*)(O + tile_off(row1, col, 1024)) =
            __floats2half2_rn(o[nt][2]*inv1, o[nt][3]*inv1);
    }
}

// ---------------------------------------------------------------------------
// Host launch
// ---------------------------------------------------------------------------
extern "C" void kernel_launch(void* const* d_in, const int* in_sizes, int n_in,
                              void* d_out, int out_size)
{
    (void)in_sizes; (void)n_in; (void)out_size;
    const float* tgt       = (const float*)d_in[0];
    const float* memory    = (const float*)d_in[1];
    const float* Wq        = (const float*)d_in[2];
    const float* Wk        = (const float*)d_in[3];
    const float* Wv        = (const float*)d_in[4];
    const float* Wo        = (const float*)d_in[5];
    const float* mha_in_w  = (const float*)d_in[6];
    const float* mha_in_b  = (const float*)d_in[7];
    const float* mha_out_w = (const float*)d_in[8];
    const float* mha_out_b = (const float*)d_in[9];
    const float* W1        = (const float*)d_in[10];
    const float* b1        = (const float*)d_in[11];
    const float* W2        = (const float*)d_in[12];
    const float* b2        = (const float*)d_in[13];
    const float* g1        = (const float*)d_in[14];
    const float* be1       = (const float*)d_in[15];
    const float* g2        = (const float*)d_in[16];
    const float* be2       = (const float*)d_in[17];
    const float* g3        = (const float*)d_in[18];
    const float* be3       = (const float*)d_in[19];

    float* xout = (float*)d_out;
    float* kout = xout + (size_t)NELEM;
    float* vout = kout + (size_t)NELEM;

    void *lnp, *qp, *k2p, *v2p, *op, *x1p, *x2p, *h1p, *rwp;
    cudaGetSymbolAddress(&lnp, g_ln);
    cudaGetSymbolAddress(&qp,  g_q);
    cudaGetSymbolAddress(&k2p, g_k2);
    cudaGetSymbolAddress(&v2p, g_v2);
    cudaGetSymbolAddress(&op,  g_o);
    cudaGetSymbolAddress(&x1p, g_x1);
    cudaGetSymbolAddress(&x2p, g_x2);
    cudaGetSymbolAddress(&h1p, g_h1);
    cudaGetSymbolAddress(&rwp, g_rw);

    __half* lnh = (__half*)lnp;
    __half* qh  = (__half*)qp;
    __half* k2h = (__half*)k2p;
    __half* v2h = (__half*)v2p;
    __half* oh  = (__half*)op;
    float*  x1  = (float*)x1p;
    float*  x2  = (float*)x2p;
    __half* h1h = (__half*)h1p;
    __half* rwh = (__half*)rwp;

    cudaFuncSetAttribute(attn_kernel,
        cudaFuncAttributeMaxDynamicSharedMemorySize, ATTN_SMEM);
    cudaFuncSetAttribute(gemm_f16_kernel,
        cudaFuncAttributeMaxDynamicSharedMemorySize, GEMM_SMEM);

    dim3 gQKV (3*DMODEL/128, TOK/128);    // (24, 32)
    dim3 gKV  (2*DMODEL/128, TOK/128);    // (16, 32)
    dim3 gProj(DMODEL/128, TOK/128);      // (8, 32)
    dim3 gFF1 (DFF_/128,  TOK/128);       // (32, 32)
    dim3 gAttn(16, 64);

    round_all_kernel<<<20480, 256>>>(Wq, Wk, Wv, Wo, mha_in_w, mha_out_w,
                                     W1, W2, memory, rwh);

    // ---- self-attention (fused QKV) ----
    ln_kernel<<<TOK, 256>>>(tgt, g1, be1, lnh);
    gemm_f16_kernel<<<gQKV, 256, GEMM_SMEM>>>(
        lnh, rwh+RW_WQ, nullptr, nullptr,
        qh, k2h, v2h, kout, vout,
        TOK, 3*DMODEL, DMODEL, 0, 1, 0, 0, 0);
    attn_kernel<<<gAttn, 128, ATTN_SMEM>>>(qh, k2h, v2h, oh, 1);
    gemm_f16_kernel<<<gProj, 256, GEMM_SMEM>>>(
        oh, rwh+RW_WO, nullptr, tgt,
        x1, nullptr, nullptr, nullptr, nullptr,
        TOK, DMODEL, DMODEL, 0, 0, 0, 0, 0);

    // ---- cross-attention (q alone, fused KV) ----
    ln_kernel<<<TOK, 256>>>(x1, g2, be2, lnh);
    gemm_f16_kernel<<<gProj, 256, GEMM_SMEM>>>(
        lnh, rwh+RW_INW, mha_in_b, nullptr,
        qh, nullptr, nullptr, nullptr, nullptr,
        TOK, DMODEL, DMODEL, 0, 1, 0, 0, 0);
    gemm_f16_kernel<<<gKV, 256, GEMM_SMEM>>>(
        rwh+RW_MEM, rwh+RW_INW+1048576, mha_in_b + 1024, nullptr,
        nullptr, k2h, v2h, nullptr, nullptr,
        TOK, 2*DMODEL, DMODEL, 0, 1, 1, 0, 0);
    attn_kernel<<<gAttn, 128, ATTN_SMEM>>>(qh, k2h, v2h, oh, 0);
    gemm_f16_kernel<<<gProj, 256, GEMM_SMEM>>>(
        oh, rwh+RW_OUTW, mha_out_b, x1,
        x2, nullptr, nullptr, nullptr, nullptr,
        TOK, DMODEL, DMODEL, 0, 0, 0, 0, 0);

    // ---- FFN ----
    ln_kernel<<<TOK, 256>>>(x2, g3, be3, lnh);
    gemm_f16_kernel<<<gFF1, 256, GEMM_SMEM>>>(
        lnh, rwh+RW_W1, b1, nullptr,
        h1h, nullptr, nullptr, nullptr, nullptr,
        TOK, DFF_, DMODEL, 1, 0, 0, 1, 4096);
    gemm_f16_kernel<<<gProj, 256, GEMM_SMEM>>>(
        h1h, rwh+RW_W2, b2, x2,
        xout, nullptr, nullptr, nullptr, nullptr,
        TOK, DMODEL, DFF_, 0, 0, 0, 0, 0);
}